// round 1
// baseline (speedup 1.0000x reference)
#include <cuda_runtime.h>
#include <math.h>

#define NBATCH 4
#define SEQ    1024
#define EMBED  2048
#define EBS    512
#define NB     4
#define HEADS  8
#define HD     64
#define TTOK   (NBATCH * SEQ)        /* 4096 tokens */
#define NG     (NBATCH * NB * HEADS) /* 128 (n,b,h) heads */

/* ------------------------------------------------------------------ */
/* Device scratch (static __device__ arrays: the sanctioned scratch). */
/* ------------------------------------------------------------------ */
__device__ float g_Q[(size_t)NG * SEQ * HD];   /* 32 MB, head-major */
__device__ float g_K[(size_t)NG * SEQ * HD];   /* 32 MB */
__device__ float g_V[(size_t)NG * SEQ * HD];   /* 32 MB */
__device__ float g_S[(size_t)NG * SEQ * SEQ];  /* 512 MB energy scratch */
__device__ float g_M[NG * SEQ];                /* per-column max      */
__device__ float g_Zi[NG * SEQ];               /* per-column 1/sumexp */
__device__ float g_AO[(size_t)TTOK * EMBED];   /* 32 MB attn output   */

/* ------------------------------------------------------------------ */
/* Block-diagonal projection GEMM.                                     */
/* X: [4096, 2048] row-major; block b uses cols [b*512, b*512+512).    */
/* W: [NB, 512, 512] (in, out) row-major. bias: [NB, 512].             */
/* HEADMAJOR=1: write Out as Q/K/V head-major [g][s][d].               */
/* HEADMAJOR=0: write Out as [t, 2048] at col b*512+o (final output).  */
/* 64x64 tile, BK=16, 256 threads, 4x4 micro-tile.                     */
/* ------------------------------------------------------------------ */
template <int HEADMAJOR>
__global__ __launch_bounds__(256) void proj_kernel(
    const float* __restrict__ X, const float* __restrict__ W,
    const float* __restrict__ bias, float* __restrict__ Out)
{
    __shared__ float As[16][65];  /* transposed: As[k][m] */
    __shared__ float Bs[16][65];

    const int b   = blockIdx.z;
    const int m0  = blockIdx.y * 64;
    const int n0  = blockIdx.x * 64;
    const int tid = threadIdx.x;
    const int tx  = tid & 15, ty = tid >> 4;

    const float* Xb = X + b * EBS;
    const float* Wb = W + (size_t)b * EBS * EBS;

    float acc[4][4];
#pragma unroll
    for (int i = 0; i < 4; i++)
#pragma unroll
        for (int j = 0; j < 4; j++) acc[i][j] = 0.f;

    const int arow = tid >> 2;         /* 0..63 */
    const int akq  = (tid & 3) << 2;   /* 0,4,8,12 */
    const int bkk  = tid >> 4;         /* 0..15 */
    const int bcq  = (tid & 15) << 2;  /* 0..60 */

    for (int k0 = 0; k0 < EBS; k0 += 16) {
        float4 av = *(const float4*)(Xb + (size_t)(m0 + arow) * EMBED + k0 + akq);
        float4 bv = *(const float4*)(Wb + (size_t)(k0 + bkk) * EBS + n0 + bcq);
        As[akq + 0][arow] = av.x;
        As[akq + 1][arow] = av.y;
        As[akq + 2][arow] = av.z;
        As[akq + 3][arow] = av.w;
        Bs[bkk][bcq + 0] = bv.x;
        Bs[bkk][bcq + 1] = bv.y;
        Bs[bkk][bcq + 2] = bv.z;
        Bs[bkk][bcq + 3] = bv.w;
        __syncthreads();
#pragma unroll
        for (int k = 0; k < 16; k++) {
            float a[4], bb[4];
#pragma unroll
            for (int i = 0; i < 4; i++) a[i] = As[k][ty * 4 + i];
#pragma unroll
            for (int j = 0; j < 4; j++) bb[j] = Bs[k][tx * 4 + j];
#pragma unroll
            for (int i = 0; i < 4; i++)
#pragma unroll
                for (int j = 0; j < 4; j++) acc[i][j] += a[i] * bb[j];
        }
        __syncthreads();
    }

#pragma unroll
    for (int i = 0; i < 4; i++) {
        const int t = m0 + ty * 4 + i;
        const int n = t >> 10, s = t & (SEQ - 1);
#pragma unroll
        for (int j = 0; j < 4; j++) {
            const int o = n0 + tx * 4 + j;
            const float v = acc[i][j] + bias[b * EBS + o];
            if (HEADMAJOR) {
                const int h = o >> 6, d = o & 63;
                const size_t g = (size_t)((n * NB + b) * HEADS + h);
                Out[(g * SEQ + s) * HD + d] = v;
            } else {
                Out[(size_t)t * EMBED + b * EBS + o] = v;
            }
        }
    }
}

/* ------------------------------------------------------------------ */
/* Energy: S[g,q,l] = (sum_d Q[g,q,d]*K[g,l,d]) * 0.125, with mask.    */
/* One CTA = 64x64 tile, K=64 staged once.                             */
/* ------------------------------------------------------------------ */
__global__ __launch_bounds__(256) void energy_kernel(const int* __restrict__ mask)
{
    __shared__ float Qs[64][65];
    __shared__ float Ks[64][65];

    const int g   = blockIdx.z;
    const int q0  = blockIdx.y * 64;
    const int l0  = blockIdx.x * 64;
    const int tid = threadIdx.x;
    const int tx  = tid & 15, ty = tid >> 4;

    const float* Qg = g_Q + (size_t)g * SEQ * HD;
    const float* Kg = g_K + (size_t)g * SEQ * HD;

#pragma unroll
    for (int it = 0; it < 4; it++) {
        const int idx = tid + it * 256;      /* 0..1023 */
        const int row = idx >> 4;            /* 0..63   */
        const int c   = (idx & 15) << 2;     /* 0..60   */
        float4 qv = *(const float4*)(Qg + (size_t)(q0 + row) * HD + c);
        float4 kv = *(const float4*)(Kg + (size_t)(l0 + row) * HD + c);
        Qs[row][c + 0] = qv.x; Qs[row][c + 1] = qv.y;
        Qs[row][c + 2] = qv.z; Qs[row][c + 3] = qv.w;
        Ks[row][c + 0] = kv.x; Ks[row][c + 1] = kv.y;
        Ks[row][c + 2] = kv.z; Ks[row][c + 3] = kv.w;
    }
    __syncthreads();

    float acc[4][4];
#pragma unroll
    for (int i = 0; i < 4; i++)
#pragma unroll
        for (int j = 0; j < 4; j++) acc[i][j] = 0.f;

#pragma unroll
    for (int d = 0; d < 64; d++) {
        float a[4], bb[4];
#pragma unroll
        for (int i = 0; i < 4; i++) a[i] = Qs[ty * 4 + i][d];
#pragma unroll
        for (int j = 0; j < 4; j++) bb[j] = Ks[tx * 4 + j][d];
#pragma unroll
        for (int i = 0; i < 4; i++)
#pragma unroll
            for (int j = 0; j < 4; j++) acc[i][j] += a[i] * bb[j];
    }

    const int n = g >> 5;  /* g = ((n*NB+b)*HEADS+h), NB*HEADS = 32 */
    float* Sg = g_S + (size_t)g * SEQ * SEQ;
    const int* Mn = mask + (size_t)n * SEQ * SEQ;

#pragma unroll
    for (int i = 0; i < 4; i++) {
        const int q = q0 + ty * 4 + i;
#pragma unroll
        for (int j = 0; j < 4; j++) {
            const int l = l0 + tx * 4 + j;
            float e = acc[i][j];
            if (Mn[(size_t)q * SEQ + l] == 0) e = -1e20f;
            Sg[(size_t)q * SEQ + l] = e * 0.125f;
        }
    }
}

/* ------------------------------------------------------------------ */
/* Column softmax stats: softmax is over the QUERY axis (axis=3 of     */
/* nbhqk) -> per (g, l): m_l = max_q S, Zi_l = 1/sum_q exp(S - m_l).   */
/* One thread per column; rows walked together -> coalesced.           */
/* ------------------------------------------------------------------ */
__global__ __launch_bounds__(256) void colstat_kernel()
{
    const int g = blockIdx.y;
    const int l = blockIdx.x * 256 + threadIdx.x;
    const float* Sg = g_S + (size_t)g * SEQ * SEQ;

    float m = -3.4e38f;
#pragma unroll 8
    for (int q = 0; q < SEQ; q++)
        m = fmaxf(m, Sg[(size_t)q * SEQ + l]);

    float z = 0.f;
#pragma unroll 8
    for (int q = 0; q < SEQ; q++)
        z += __expf(Sg[(size_t)q * SEQ + l] - m);

    g_M[g * SEQ + l]  = m;
    g_Zi[g * SEQ + l] = 1.f / z;
}

/* ------------------------------------------------------------------ */
/* O[g,q,d] = sum_l A[g,q,l] * V[g,l,d], A = exp(S - m_l) * Zi_l       */
/* (exp/normalize folded into the S-tile load).                        */
/* CTA: 64 q-rows x 64 d-cols (full HD), BK=32.                        */
/* Writes directly into the [t, 2048] layout needed by out-proj.       */
/* ------------------------------------------------------------------ */
__global__ __launch_bounds__(256) void av_kernel()
{
    __shared__ float Es[64][33];
    __shared__ float Vs[32][65];

    const int g   = blockIdx.y;
    const int q0  = blockIdx.x * 64;
    const int tid = threadIdx.x;
    const int tx  = tid & 15, ty = tid >> 4;

    const float* Sg = g_S + (size_t)g * SEQ * SEQ;
    const float* Vg = g_V + (size_t)g * SEQ * HD;
    const float* Mg = g_M + g * SEQ;
    const float* Zg = g_Zi + g * SEQ;

    float acc[4][4];
#pragma unroll
    for (int i = 0; i < 4; i++)
#pragma unroll
        for (int j = 0; j < 4; j++) acc[i][j] = 0.f;

    for (int l0 = 0; l0 < SEQ; l0 += 32) {
#pragma unroll
        for (int it = 0; it < 2; it++) {
            const int idx = tid + it * 256;   /* 0..511 */
            /* E tile: 64 rows x 32 cols */
            {
                const int row = idx >> 3;           /* 0..63 */
                const int c   = (idx & 7) << 2;     /* 0..28 */
                float4 ev = *(const float4*)(Sg + (size_t)(q0 + row) * SEQ + l0 + c);
                Es[row][c + 0] = __expf(ev.x - Mg[l0 + c + 0]) * Zg[l0 + c + 0];
                Es[row][c + 1] = __expf(ev.y - Mg[l0 + c + 1]) * Zg[l0 + c + 1];
                Es[row][c + 2] = __expf(ev.z - Mg[l0 + c + 2]) * Zg[l0 + c + 2];
                Es[row][c + 3] = __expf(ev.w - Mg[l0 + c + 3]) * Zg[l0 + c + 3];
            }
            /* V tile: 32 rows x 64 cols */
            {
                const int row = idx >> 4;           /* 0..31 */
                const int c   = (idx & 15) << 2;    /* 0..60 */
                float4 vv = *(const float4*)(Vg + (size_t)(l0 + row) * HD + c);
                Vs[row][c + 0] = vv.x; Vs[row][c + 1] = vv.y;
                Vs[row][c + 2] = vv.z; Vs[row][c + 3] = vv.w;
            }
        }
        __syncthreads();
#pragma unroll
        for (int l = 0; l < 32; l++) {
            float a[4], bb[4];
#pragma unroll
            for (int i = 0; i < 4; i++) a[i] = Es[ty * 4 + i][l];
#pragma unroll
            for (int j = 0; j < 4; j++) bb[j] = Vs[l][tx * 4 + j];
#pragma unroll
            for (int i = 0; i < 4; i++)
#pragma unroll
                for (int j = 0; j < 4; j++) acc[i][j] += a[i] * bb[j];
        }
        __syncthreads();
    }

    const int n = g >> 5, b = (g >> 3) & 3, h = g & 7;
#pragma unroll
    for (int i = 0; i < 4; i++) {
        const int q = q0 + ty * 4 + i;
        const size_t t = (size_t)(n * SEQ + q);
#pragma unroll
        for (int j = 0; j < 4; j++) {
            const int d = tx * 4 + j;
            g_AO[t * EMBED + b * EBS + h * HD + d] = acc[i][j];
        }
    }
}

/* ------------------------------------------------------------------ */
extern "C" void kernel_launch(void* const* d_in, const int* in_sizes, int n_in,
                              void* d_out, int out_size)
{
    const float* values = (const float*)d_in[0];
    const float* keys   = (const float*)d_in[1];
    const float* query  = (const float*)d_in[2];
    const int*   mask   = (const int*)d_in[3];
    const float* Wv = (const float*)d_in[4];
    const float* bv = (const float*)d_in[5];
    const float* Wk = (const float*)d_in[6];
    const float* bk = (const float*)d_in[7];
    const float* Wq = (const float*)d_in[8];
    const float* bq = (const float*)d_in[9];
    const float* Wo = (const float*)d_in[10];
    const float* bo = (const float*)d_in[11];
    float* out = (float*)d_out;

    float *pQ, *pK, *pV, *pAO;
    cudaGetSymbolAddress((void**)&pQ,  g_Q);
    cudaGetSymbolAddress((void**)&pK,  g_K);
    cudaGetSymbolAddress((void**)&pV,  g_V);
    cudaGetSymbolAddress((void**)&pAO, g_AO);

    dim3 gp(EBS / 64, TTOK / 64, NB);
    proj_kernel<1><<<gp, 256>>>(values, Wv, bv, pV);
    proj_kernel<1><<<gp, 256>>>(keys,   Wk, bk, pK);
    proj_kernel<1><<<gp, 256>>>(query,  Wq, bq, pQ);

    dim3 ge(SEQ / 64, SEQ / 64, NG);
    energy_kernel<<<ge, 256>>>(mask);

    dim3 gc(SEQ / 256, NG);
    colstat_kernel<<<gc, 256>>>();

    dim3 ga(SEQ / 64, NG);
    av_kernel<<<ga, 256>>>();

    dim3 go(EBS / 64, TTOK / 64, NB);
    proj_kernel<0><<<go, 256>>>(pAO, Wo, bo, out);
}

// round 2
// speedup vs baseline: 1.2418x; 1.2418x over previous
#include <cuda_runtime.h>
#include <math.h>

#define NBATCH 4
#define SEQ    1024
#define EMBED  2048
#define EBS    512
#define NB     4
#define HEADS  8
#define HD     64
#define TTOK   (NBATCH * SEQ)        /* 4096 tokens */
#define NG     (NBATCH * NB * HEADS) /* 128 (n,b,h) heads */

/* ------------------------------------------------------------------ */
/* Device scratch                                                      */
/* ------------------------------------------------------------------ */
__device__ float g_Q[(size_t)NG * SEQ * HD];   /* 32 MB, head-major */
__device__ float g_K[(size_t)NG * SEQ * HD];   /* 32 MB */
__device__ float g_V[(size_t)NG * SEQ * HD];   /* 32 MB */
__device__ float g_S[(size_t)NG * SEQ * SEQ];  /* 512 MB energy scratch */
__device__ float g_M[NG * SEQ];                /* per-column max      */
__device__ float g_Zi[NG * SEQ];               /* per-column 1/sumexp */
__device__ float g_AO[(size_t)TTOK * EMBED];   /* 32 MB attn output   */

struct QKVArgs {
    const float* X[3];
    const float* W[3];
    const float* B[3];
    float*       O[3];
};

/* ================================================================== */
/* Fused Q/K/V block-diagonal projection.                              */
/* 128x128 CTA tile, BK=8, 256 threads, 8x8 micro-tile.                */
/* grid: (EBS/128, TTOK/128, 3*NB)                                     */
/* ================================================================== */
__global__ __launch_bounds__(256) void qkv_proj_kernel(QKVArgs args)
{
    __shared__ float As[8][132];
    __shared__ float Bs[8][132];

    const int p  = blockIdx.z >> 2;      /* 0=V,1=K,2=Q */
    const int b  = blockIdx.z & 3;
    const int m0 = blockIdx.y * 128;
    const int n0 = blockIdx.x * 128;
    const int tid = threadIdx.x;

    const float* Xb = args.X[p] + b * EBS;
    const float* Wb = args.W[p] + (size_t)b * EBS * EBS;
    const float* bias = args.B[p] + b * EBS;
    float* Out = args.O[p];

    const int ty = tid >> 4, tx = tid & 15;
    const int rowbase = ty * 8, colbase = tx * 8;

    /* loader indices */
    const int arow = tid >> 1;          /* 0..127 */
    const int akq  = (tid & 1) * 4;     /* 0 or 4 */
    const int bkrow = tid >> 5;         /* 0..7   */
    const int bcol  = (tid & 31) * 4;   /* 0..124 */

    float acc[8][8];
#pragma unroll
    for (int i = 0; i < 8; i++)
#pragma unroll
        for (int j = 0; j < 8; j++) acc[i][j] = 0.f;

    for (int k0 = 0; k0 < EBS; k0 += 8) {
        float4 av = *(const float4*)(Xb + (size_t)(m0 + arow) * EMBED + k0 + akq);
        float4 bv = *(const float4*)(Wb + (size_t)(k0 + bkrow) * EBS + n0 + bcol);
        As[akq + 0][arow] = av.x;
        As[akq + 1][arow] = av.y;
        As[akq + 2][arow] = av.z;
        As[akq + 3][arow] = av.w;
        *(float4*)&Bs[bkrow][bcol] = bv;
        __syncthreads();
#pragma unroll
        for (int k = 0; k < 8; k++) {
            float4 a0 = *(const float4*)&As[k][rowbase];
            float4 a1 = *(const float4*)&As[k][rowbase + 4];
            float4 b0 = *(const float4*)&Bs[k][colbase];
            float4 b1 = *(const float4*)&Bs[k][colbase + 4];
            const float a[8] = {a0.x,a0.y,a0.z,a0.w,a1.x,a1.y,a1.z,a1.w};
            const float bb[8] = {b0.x,b0.y,b0.z,b0.w,b1.x,b1.y,b1.z,b1.w};
#pragma unroll
            for (int i = 0; i < 8; i++)
#pragma unroll
                for (int j = 0; j < 8; j++) acc[i][j] += a[i] * bb[j];
        }
        __syncthreads();
    }

#pragma unroll
    for (int i = 0; i < 8; i++) {
        const int t = m0 + rowbase + i;
        const int n = t >> 10, s = t & (SEQ - 1);
#pragma unroll
        for (int j = 0; j < 8; j++) {
            const int o = n0 + colbase + j;
            const float v = acc[i][j] + bias[o];
            const int h = o >> 6, d = o & 63;
            const size_t g = (size_t)((n * NB + b) * HEADS + h);
            Out[(g * SEQ + s) * HD + d] = v;
        }
    }
}

/* ================================================================== */
/* Output projection: X = g_AO [4096,2048] -> out [4096,2048].         */
/* ================================================================== */
__global__ __launch_bounds__(256) void oproj_kernel(
    const float* __restrict__ X, const float* __restrict__ W,
    const float* __restrict__ bias, float* __restrict__ Out)
{
    __shared__ float As[8][132];
    __shared__ float Bs[8][132];

    const int b  = blockIdx.z;
    const int m0 = blockIdx.y * 128;
    const int n0 = blockIdx.x * 128;
    const int tid = threadIdx.x;

    const float* Xb = X + b * EBS;
    const float* Wb = W + (size_t)b * EBS * EBS;

    const int ty = tid >> 4, tx = tid & 15;
    const int rowbase = ty * 8, colbase = tx * 8;
    const int arow = tid >> 1, akq = (tid & 1) * 4;
    const int bkrow = tid >> 5, bcol = (tid & 31) * 4;

    float acc[8][8];
#pragma unroll
    for (int i = 0; i < 8; i++)
#pragma unroll
        for (int j = 0; j < 8; j++) acc[i][j] = 0.f;

    for (int k0 = 0; k0 < EBS; k0 += 8) {
        float4 av = *(const float4*)(Xb + (size_t)(m0 + arow) * EMBED + k0 + akq);
        float4 bv = *(const float4*)(Wb + (size_t)(k0 + bkrow) * EBS + n0 + bcol);
        As[akq + 0][arow] = av.x;
        As[akq + 1][arow] = av.y;
        As[akq + 2][arow] = av.z;
        As[akq + 3][arow] = av.w;
        *(float4*)&Bs[bkrow][bcol] = bv;
        __syncthreads();
#pragma unroll
        for (int k = 0; k < 8; k++) {
            float4 a0 = *(const float4*)&As[k][rowbase];
            float4 a1 = *(const float4*)&As[k][rowbase + 4];
            float4 b0 = *(const float4*)&Bs[k][colbase];
            float4 b1 = *(const float4*)&Bs[k][colbase + 4];
            const float a[8] = {a0.x,a0.y,a0.z,a0.w,a1.x,a1.y,a1.z,a1.w};
            const float bb[8] = {b0.x,b0.y,b0.z,b0.w,b1.x,b1.y,b1.z,b1.w};
#pragma unroll
            for (int i = 0; i < 8; i++)
#pragma unroll
                for (int j = 0; j < 8; j++) acc[i][j] += a[i] * bb[j];
        }
        __syncthreads();
    }

#pragma unroll
    for (int i = 0; i < 8; i++) {
        const size_t t = (size_t)(m0 + rowbase + i);
#pragma unroll
        for (int j = 0; j < 8; j++) {
            const int o = n0 + colbase + j;
            Out[t * EMBED + b * EBS + o] = acc[i][j] + bias[b * EBS + o];
        }
    }
}

/* ================================================================== */
/* Energy: S[g,q,l] = (sum_d Q[g,q,d]*K[g,l,d]) masked, * 0.125.       */
/* 128x128 tile, K=64 (8 x BK=8), 8x8 micro.                           */
/* grid: (SEQ/128, SEQ/128, NG)                                        */
/* ================================================================== */
__global__ __launch_bounds__(256) void energy_kernel(const int* __restrict__ mask)
{
    __shared__ float Qs[8][132];
    __shared__ float Ks[8][132];

    const int g  = blockIdx.z;
    const int q0 = blockIdx.y * 128;
    const int l0 = blockIdx.x * 128;
    const int tid = threadIdx.x;

    const float* Qg = g_Q + (size_t)g * SEQ * HD;
    const float* Kg = g_K + (size_t)g * SEQ * HD;

    const int ty = tid >> 4, tx = tid & 15;
    const int rowbase = ty * 8, colbase = tx * 8;
    const int arow = tid >> 1, akq = (tid & 1) * 4;

    float acc[8][8];
#pragma unroll
    for (int i = 0; i < 8; i++)
#pragma unroll
        for (int j = 0; j < 8; j++) acc[i][j] = 0.f;

    for (int k0 = 0; k0 < HD; k0 += 8) {
        float4 qv = *(const float4*)(Qg + (size_t)(q0 + arow) * HD + k0 + akq);
        float4 kv = *(const float4*)(Kg + (size_t)(l0 + arow) * HD + k0 + akq);
        Qs[akq + 0][arow] = qv.x;
        Qs[akq + 1][arow] = qv.y;
        Qs[akq + 2][arow] = qv.z;
        Qs[akq + 3][arow] = qv.w;
        Ks[akq + 0][arow] = kv.x;
        Ks[akq + 1][arow] = kv.y;
        Ks[akq + 2][arow] = kv.z;
        Ks[akq + 3][arow] = kv.w;
        __syncthreads();
#pragma unroll
        for (int k = 0; k < 8; k++) {
            float4 a0 = *(const float4*)&Qs[k][rowbase];
            float4 a1 = *(const float4*)&Qs[k][rowbase + 4];
            float4 b0 = *(const float4*)&Ks[k][colbase];
            float4 b1 = *(const float4*)&Ks[k][colbase + 4];
            const float a[8] = {a0.x,a0.y,a0.z,a0.w,a1.x,a1.y,a1.z,a1.w};
            const float bb[8] = {b0.x,b0.y,b0.z,b0.w,b1.x,b1.y,b1.z,b1.w};
#pragma unroll
            for (int i = 0; i < 8; i++)
#pragma unroll
                for (int j = 0; j < 8; j++) acc[i][j] += a[i] * bb[j];
        }
        __syncthreads();
    }

    const int n = g >> 5;
    float* Sg = g_S + (size_t)g * SEQ * SEQ;
    const int* Mn = mask + (size_t)n * SEQ * SEQ;

#pragma unroll
    for (int i = 0; i < 8; i++) {
        const int q = q0 + rowbase + i;
        const int* mrow = Mn + (size_t)q * SEQ + l0 + colbase;
        int4 mm0 = *(const int4*)(mrow);
        int4 mm1 = *(const int4*)(mrow + 4);
        const int mv[8] = {mm0.x,mm0.y,mm0.z,mm0.w,mm1.x,mm1.y,mm1.z,mm1.w};
        float4 r0, r1;
        float rr[8];
#pragma unroll
        for (int j = 0; j < 8; j++) {
            float e = (mv[j] == 0) ? -1e20f : acc[i][j];
            rr[j] = e * 0.125f;
        }
        r0.x = rr[0]; r0.y = rr[1]; r0.z = rr[2]; r0.w = rr[3];
        r1.x = rr[4]; r1.y = rr[5]; r1.z = rr[6]; r1.w = rr[7];
        float* srow = Sg + (size_t)q * SEQ + l0 + colbase;
        *(float4*)(srow)     = r0;
        *(float4*)(srow + 4) = r1;
    }
}

/* ================================================================== */
/* Column softmax stats (softmax over the QUERY axis): one online pass */
/* per (g,l): m = max_q S, Zi = 1/sum_q exp(S-m). 512MB read total.    */
/* ================================================================== */
__global__ __launch_bounds__(256) void colstat_kernel()
{
    const int g = blockIdx.y;
    const int l = blockIdx.x * 256 + threadIdx.x;
    const float* Sg = g_S + (size_t)g * SEQ * SEQ + l;

    float m = -3.4e38f, z = 0.f;
    for (int q = 0; q < SEQ; q += 4) {
        float x0 = Sg[(size_t)(q + 0) * SEQ];
        float x1 = Sg[(size_t)(q + 1) * SEQ];
        float x2 = Sg[(size_t)(q + 2) * SEQ];
        float x3 = Sg[(size_t)(q + 3) * SEQ];
#pragma unroll
        for (int u = 0; u < 4; u++) {
            float x = (u == 0) ? x0 : (u == 1) ? x1 : (u == 2) ? x2 : x3;
            if (x > m) { z = z * __expf(m - x) + 1.f; m = x; }
            else       { z += __expf(x - m); }
        }
    }
    g_M[g * SEQ + l]  = m;
    g_Zi[g * SEQ + l] = 1.f / z;
}

/* ================================================================== */
/* AV: O[g,q,d] = sum_l exp(S-m_l)*Zi_l * V[g,l,d].                    */
/* 256x64 tile, BK=32, 256 threads, 8x8 micro.                         */
/* grid: (SEQ/256, NG)                                                 */
/* ================================================================== */
__global__ __launch_bounds__(256) void av_kernel()
{
    __shared__ float Es[32][264];  /* [l][q] transposed */
    __shared__ float Vs[32][68];   /* [l][d]            */

    const int g  = blockIdx.y;
    const int q0 = blockIdx.x * 256;
    const int tid = threadIdx.x;

    const float* Sg = g_S + (size_t)g * SEQ * SEQ;
    const float* Vg = g_V + (size_t)g * SEQ * HD;
    const float* Mg = g_M + g * SEQ;
    const float* Zg = g_Zi + g * SEQ;

    const int ty = tid >> 3, tx = tid & 7;     /* 32 x 8 */
    const int rowbase = ty * 8, colbase = tx * 8;

    float acc[8][8];
#pragma unroll
    for (int i = 0; i < 8; i++)
#pragma unroll
        for (int j = 0; j < 8; j++) acc[i][j] = 0.f;

    for (int l0 = 0; l0 < SEQ; l0 += 32) {
        /* V tile: 32 x 64 */
#pragma unroll
        for (int it = 0; it < 2; it++) {
            const int idx = tid + it * 256;    /* 0..511 */
            const int row = idx >> 4;          /* 0..31  */
            const int c   = (idx & 15) * 4;    /* 0..60  */
            *(float4*)&Vs[row][c] = *(const float4*)(Vg + (size_t)(l0 + row) * HD + c);
        }
        /* E tile: 256 q-rows x 32 l-cols, transposed into Es[l][q] */
        {
            const int row = tid;               /* q offset 0..255 */
            const float* srow = Sg + (size_t)(q0 + row) * SEQ + l0;
#pragma unroll
            for (int cb = 0; cb < 32; cb += 4) {
                float4 sv = *(const float4*)(srow + cb);
                float4 mv = *(const float4*)(Mg + l0 + cb);
                float4 zv = *(const float4*)(Zg + l0 + cb);
                Es[cb + 0][row] = __expf(sv.x - mv.x) * zv.x;
                Es[cb + 1][row] = __expf(sv.y - mv.y) * zv.y;
                Es[cb + 2][row] = __expf(sv.z - mv.z) * zv.z;
                Es[cb + 3][row] = __expf(sv.w - mv.w) * zv.w;
            }
        }
        __syncthreads();
#pragma unroll
        for (int k = 0; k < 32; k++) {
            float4 a0 = *(const float4*)&Es[k][rowbase];
            float4 a1 = *(const float4*)&Es[k][rowbase + 4];
            float4 b0 = *(const float4*)&Vs[k][colbase];
            float4 b1 = *(const float4*)&Vs[k][colbase + 4];
            const float a[8] = {a0.x,a0.y,a0.z,a0.w,a1.x,a1.y,a1.z,a1.w};
            const float bb[8] = {b0.x,b0.y,b0.z,b0.w,b1.x,b1.y,b1.z,b1.w};
#pragma unroll
            for (int i = 0; i < 8; i++)
#pragma unroll
                for (int j = 0; j < 8; j++) acc[i][j] += a[i] * bb[j];
        }
        __syncthreads();
    }

    const int n = g >> 5, b = (g >> 3) & 3, h = g & 7;
#pragma unroll
    for (int i = 0; i < 8; i++) {
        const int q = q0 + rowbase + i;
        const size_t t = (size_t)(n * SEQ + q);
        float* orow = g_AO + t * EMBED + b * EBS + h * HD;
        float4 r0, r1;
        r0.x = acc[i][0]; r0.y = acc[i][1]; r0.z = acc[i][2]; r0.w = acc[i][3];
        r1.x = acc[i][4]; r1.y = acc[i][5]; r1.z = acc[i][6]; r1.w = acc[i][7];
        *(float4*)(orow + colbase)     = r0;
        *(float4*)(orow + colbase + 4) = r1;
    }
}

/* ------------------------------------------------------------------ */
extern "C" void kernel_launch(void* const* d_in, const int* in_sizes, int n_in,
                              void* d_out, int out_size)
{
    const float* values = (const float*)d_in[0];
    const float* keys   = (const float*)d_in[1];
    const float* query  = (const float*)d_in[2];
    const int*   mask   = (const int*)d_in[3];
    const float* Wv = (const float*)d_in[4];
    const float* bv = (const float*)d_in[5];
    const float* Wk = (const float*)d_in[6];
    const float* bk = (const float*)d_in[7];
    const float* Wq = (const float*)d_in[8];
    const float* bq = (const float*)d_in[9];
    const float* Wo = (const float*)d_in[10];
    const float* bo = (const float*)d_in[11];
    float* out = (float*)d_out;

    float *pQ, *pK, *pV, *pAO;
    cudaGetSymbolAddress((void**)&pQ,  g_Q);
    cudaGetSymbolAddress((void**)&pK,  g_K);
    cudaGetSymbolAddress((void**)&pV,  g_V);
    cudaGetSymbolAddress((void**)&pAO, g_AO);

    QKVArgs qa;
    qa.X[0] = values; qa.X[1] = keys; qa.X[2] = query;
    qa.W[0] = Wv;     qa.W[1] = Wk;   qa.W[2] = Wq;
    qa.B[0] = bv;     qa.B[1] = bk;   qa.B[2] = bq;
    qa.O[0] = pV;     qa.O[1] = pK;   qa.O[2] = pQ;

    dim3 gqkv(EBS / 128, TTOK / 128, 3 * NB);
    qkv_proj_kernel<<<gqkv, 256>>>(qa);

    dim3 ge(SEQ / 128, SEQ / 128, NG);
    energy_kernel<<<ge, 256>>>(mask);

    dim3 gc(SEQ / 256, NG);
    colstat_kernel<<<gc, 256>>>();

    dim3 ga(SEQ / 256, NG);
    av_kernel<<<ga, 256>>>();

    dim3 go(EBS / 128, TTOK / 128, NB);
    oproj_kernel<<<go, 256>>>(pAO, Wo, bo, out);
}

// round 3
// speedup vs baseline: 1.2451x; 1.0027x over previous
#include <cuda_runtime.h>
#include <math.h>

#define NBATCH 4
#define SEQ    1024
#define EMBED  2048
#define EBS    512
#define NB     4
#define HEADS  8
#define HD     64
#define TTOK   (NBATCH * SEQ)        /* 4096 tokens */
#define NG     (NBATCH * NB * HEADS) /* 128 (n,b,h) heads */

typedef unsigned long long u64;

/* ------------------------------------------------------------------ */
/* Packed fp32x2 helpers (Blackwell-only PTX; not emitted by ptxas).   */
/* ------------------------------------------------------------------ */
__device__ __forceinline__ u64 dup2(float x) {
    u64 r;
    asm("mov.b64 %0, {%1, %1};" : "=l"(r) : "f"(x));
    return r;
}
__device__ __forceinline__ u64 ffma2(u64 a, u64 b, u64 c) {
    u64 d;
    asm("fma.rn.f32x2 %0, %1, %2, %3;" : "=l"(d) : "l"(a), "l"(b), "l"(c));
    return d;
}
__device__ __forceinline__ float2 unpack2(u64 v) {
    float2 f;
    asm("mov.b64 {%0, %1}, %2;" : "=f"(f.x), "=f"(f.y) : "l"(v));
    return f;
}

/* ------------------------------------------------------------------ */
/* Device scratch                                                      */
/* ------------------------------------------------------------------ */
__device__ float g_Q[(size_t)NG * SEQ * HD];   /* 32 MB, head-major */
__device__ float g_K[(size_t)NG * SEQ * HD];   /* 32 MB */
__device__ float g_V[(size_t)NG * SEQ * HD];   /* 32 MB */
__device__ float g_S[(size_t)NG * SEQ * SEQ];  /* 512 MB energy scratch */
__device__ float g_M[NG * SEQ];                /* per-column max      */
__device__ float g_Zi[NG * SEQ];               /* per-column 1/sumexp */
__device__ float g_AO[(size_t)TTOK * EMBED];   /* 32 MB attn output   */

struct QKVArgs {
    const float* X[3];
    const float* W[3];
    const float* B[3];
    float*       O[3];
};

/* 8x8 micro-tile inner product step on packed f32x2 accumulators.     */
/* acc[i][p] holds columns (2p, 2p+1) of row i.                        */
#define MICRO_FFMA2(As_, Bs_, k_, rowbase_, colbase_, acc_)                   \
    do {                                                                      \
        float4 a0_ = *(const float4*)&As_[k_][rowbase_];                      \
        float4 a1_ = *(const float4*)&As_[k_][rowbase_ + 4];                  \
        ulonglong2 bb0_ = *(const ulonglong2*)&Bs_[k_][colbase_];             \
        ulonglong2 bb1_ = *(const ulonglong2*)&Bs_[k_][colbase_ + 4];         \
        const u64 bp_[4] = {bb0_.x, bb0_.y, bb1_.x, bb1_.y};                  \
        const float af_[8] = {a0_.x, a0_.y, a0_.z, a0_.w,                     \
                              a1_.x, a1_.y, a1_.z, a1_.w};                    \
        _Pragma("unroll")                                                     \
        for (int i_ = 0; i_ < 8; i_++) {                                      \
            const u64 ad_ = dup2(af_[i_]);                                    \
            _Pragma("unroll")                                                 \
            for (int p_ = 0; p_ < 4; p_++)                                    \
                acc_[i_][p_] = ffma2(ad_, bp_[p_], acc_[i_][p_]);             \
        }                                                                     \
    } while (0)

/* ================================================================== */
/* Fused Q/K/V block-diagonal projection.                              */
/* 128x128 CTA tile, BK=8, 256 threads, 8x8 micro-tile.                */
/* grid: (EBS/128, TTOK/128, 3*NB)                                     */
/* ================================================================== */
__global__ __launch_bounds__(256) void qkv_proj_kernel(QKVArgs args)
{
    __shared__ float As[8][132];
    __shared__ float Bs[8][132];

    const int p  = blockIdx.z >> 2;      /* 0=V,1=K,2=Q */
    const int b  = blockIdx.z & 3;
    const int m0 = blockIdx.y * 128;
    const int n0 = blockIdx.x * 128;
    const int tid = threadIdx.x;

    const float* Xb = args.X[p] + b * EBS;
    const float* Wb = args.W[p] + (size_t)b * EBS * EBS;
    const float* bias = args.B[p] + b * EBS;
    float* Out = args.O[p];

    const int ty = tid >> 4, tx = tid & 15;
    const int rowbase = ty * 8, colbase = tx * 8;

    const int arow = tid >> 1;          /* 0..127 */
    const int akq  = (tid & 1) * 4;     /* 0 or 4 */
    const int bkrow = tid >> 5;         /* 0..7   */
    const int bcol  = (tid & 31) * 4;   /* 0..124 */

    u64 acc[8][4];
#pragma unroll
    for (int i = 0; i < 8; i++)
#pragma unroll
        for (int j = 0; j < 4; j++) acc[i][j] = 0ull;

    for (int k0 = 0; k0 < EBS; k0 += 8) {
        float4 av = *(const float4*)(Xb + (size_t)(m0 + arow) * EMBED + k0 + akq);
        float4 bv = *(const float4*)(Wb + (size_t)(k0 + bkrow) * EBS + n0 + bcol);
        As[akq + 0][arow] = av.x;
        As[akq + 1][arow] = av.y;
        As[akq + 2][arow] = av.z;
        As[akq + 3][arow] = av.w;
        *(float4*)&Bs[bkrow][bcol] = bv;
        __syncthreads();
#pragma unroll
        for (int k = 0; k < 8; k++)
            MICRO_FFMA2(As, Bs, k, rowbase, colbase, acc);
        __syncthreads();
    }

#pragma unroll
    for (int i = 0; i < 8; i++) {
        const int t = m0 + rowbase + i;
        const int n = t >> 10, s = t & (SEQ - 1);
        float r[8];
#pragma unroll
        for (int pp = 0; pp < 4; pp++) {
            float2 f = unpack2(acc[i][pp]);
            r[2 * pp] = f.x; r[2 * pp + 1] = f.y;
        }
#pragma unroll
        for (int j = 0; j < 8; j++) {
            const int o = n0 + colbase + j;
            const float v = r[j] + bias[o];
            const int h = o >> 6, d = o & 63;
            const size_t g = (size_t)((n * NB + b) * HEADS + h);
            Out[(g * SEQ + s) * HD + d] = v;
        }
    }
}

/* ================================================================== */
/* Output projection: X = g_AO [4096,2048] -> out [4096,2048].         */
/* ================================================================== */
__global__ __launch_bounds__(256) void oproj_kernel(
    const float* __restrict__ X, const float* __restrict__ W,
    const float* __restrict__ bias, float* __restrict__ Out)
{
    __shared__ float As[8][132];
    __shared__ float Bs[8][132];

    const int b  = blockIdx.z;
    const int m0 = blockIdx.y * 128;
    const int n0 = blockIdx.x * 128;
    const int tid = threadIdx.x;

    const float* Xb = X + b * EBS;
    const float* Wb = W + (size_t)b * EBS * EBS;

    const int ty = tid >> 4, tx = tid & 15;
    const int rowbase = ty * 8, colbase = tx * 8;
    const int arow = tid >> 1, akq = (tid & 1) * 4;
    const int bkrow = tid >> 5, bcol = (tid & 31) * 4;

    u64 acc[8][4];
#pragma unroll
    for (int i = 0; i < 8; i++)
#pragma unroll
        for (int j = 0; j < 4; j++) acc[i][j] = 0ull;

    for (int k0 = 0; k0 < EBS; k0 += 8) {
        float4 av = *(const float4*)(Xb + (size_t)(m0 + arow) * EMBED + k0 + akq);
        float4 bv = *(const float4*)(Wb + (size_t)(k0 + bkrow) * EBS + n0 + bcol);
        As[akq + 0][arow] = av.x;
        As[akq + 1][arow] = av.y;
        As[akq + 2][arow] = av.z;
        As[akq + 3][arow] = av.w;
        *(float4*)&Bs[bkrow][bcol] = bv;
        __syncthreads();
#pragma unroll
        for (int k = 0; k < 8; k++)
            MICRO_FFMA2(As, Bs, k, rowbase, colbase, acc);
        __syncthreads();
    }

#pragma unroll
    for (int i = 0; i < 8; i++) {
        const size_t t = (size_t)(m0 + rowbase + i);
        float r[8];
#pragma unroll
        for (int pp = 0; pp < 4; pp++) {
            float2 f = unpack2(acc[i][pp]);
            r[2 * pp] = f.x; r[2 * pp + 1] = f.y;
        }
#pragma unroll
        for (int j = 0; j < 8; j++) {
            const int o = n0 + colbase + j;
            Out[t * EMBED + b * EBS + o] = r[j] + bias[b * EBS + o];
        }
    }
}

/* ================================================================== */
/* Energy: S[g,q,l] = (sum_d Q[g,q,d]*K[g,l,d]) masked, * 0.125.       */
/* 128x128 tile, K=64 (8 x BK=8), 8x8 micro.                           */
/* ================================================================== */
__global__ __launch_bounds__(256) void energy_kernel(const int* __restrict__ mask)
{
    __shared__ float Qs[8][132];
    __shared__ float Ks[8][132];

    const int g  = blockIdx.z;
    const int q0 = blockIdx.y * 128;
    const int l0 = blockIdx.x * 128;
    const int tid = threadIdx.x;

    const float* Qg = g_Q + (size_t)g * SEQ * HD;
    const float* Kg = g_K + (size_t)g * SEQ * HD;

    const int ty = tid >> 4, tx = tid & 15;
    const int rowbase = ty * 8, colbase = tx * 8;
    const int arow = tid >> 1, akq = (tid & 1) * 4;

    u64 acc[8][4];
#pragma unroll
    for (int i = 0; i < 8; i++)
#pragma unroll
        for (int j = 0; j < 4; j++) acc[i][j] = 0ull;

    for (int k0 = 0; k0 < HD; k0 += 8) {
        float4 qv = *(const float4*)(Qg + (size_t)(q0 + arow) * HD + k0 + akq);
        float4 kv = *(const float4*)(Kg + (size_t)(l0 + arow) * HD + k0 + akq);
        Qs[akq + 0][arow] = qv.x;
        Qs[akq + 1][arow] = qv.y;
        Qs[akq + 2][arow] = qv.z;
        Qs[akq + 3][arow] = qv.w;
        Ks[akq + 0][arow] = kv.x;
        Ks[akq + 1][arow] = kv.y;
        Ks[akq + 2][arow] = kv.z;
        Ks[akq + 3][arow] = kv.w;
        __syncthreads();
#pragma unroll
        for (int k = 0; k < 8; k++)
            MICRO_FFMA2(Qs, Ks, k, rowbase, colbase, acc);
        __syncthreads();
    }

    const int n = g >> 5;
    float* Sg = g_S + (size_t)g * SEQ * SEQ;
    const int* Mn = mask + (size_t)n * SEQ * SEQ;

#pragma unroll
    for (int i = 0; i < 8; i++) {
        const int q = q0 + rowbase + i;
        const int* mrow = Mn + (size_t)q * SEQ + l0 + colbase;
        int4 mm0 = *(const int4*)(mrow);
        int4 mm1 = *(const int4*)(mrow + 4);
        const int mv[8] = {mm0.x,mm0.y,mm0.z,mm0.w,mm1.x,mm1.y,mm1.z,mm1.w};
        float r[8];
#pragma unroll
        for (int pp = 0; pp < 4; pp++) {
            float2 f = unpack2(acc[i][pp]);
            r[2 * pp] = f.x; r[2 * pp + 1] = f.y;
        }
        float rr[8];
#pragma unroll
        for (int j = 0; j < 8; j++) {
            float e = (mv[j] == 0) ? -1e20f : r[j];
            rr[j] = e * 0.125f;
        }
        float4 r0, r1;
        r0.x = rr[0]; r0.y = rr[1]; r0.z = rr[2]; r0.w = rr[3];
        r1.x = rr[4]; r1.y = rr[5]; r1.z = rr[6]; r1.w = rr[7];
        float* srow = Sg + (size_t)q * SEQ + l0 + colbase;
        *(float4*)(srow)     = r0;
        *(float4*)(srow + 4) = r1;
    }
}

/* ================================================================== */
/* Column softmax stats (softmax over the QUERY axis), one online pass */
/* ================================================================== */
__global__ __launch_bounds__(256) void colstat_kernel()
{
    const int g = blockIdx.y;
    const int l = blockIdx.x * 256 + threadIdx.x;
    const float* Sg = g_S + (size_t)g * SEQ * SEQ + l;

    float m = -3.4e38f, z = 0.f;
    for (int q = 0; q < SEQ; q += 4) {
        float x0 = Sg[(size_t)(q + 0) * SEQ];
        float x1 = Sg[(size_t)(q + 1) * SEQ];
        float x2 = Sg[(size_t)(q + 2) * SEQ];
        float x3 = Sg[(size_t)(q + 3) * SEQ];
#pragma unroll
        for (int u = 0; u < 4; u++) {
            float x = (u == 0) ? x0 : (u == 1) ? x1 : (u == 2) ? x2 : x3;
            if (x > m) { z = z * __expf(m - x) + 1.f; m = x; }
            else       { z += __expf(x - m); }
        }
    }
    g_M[g * SEQ + l]  = m;
    g_Zi[g * SEQ + l] = 1.f / z;
}

/* ================================================================== */
/* AV: O[g,q,d] = sum_l exp(S-m_l)*Zi_l * V[g,l,d].                    */
/* 256x64 tile, BK=32, 256 threads, 8x8 micro.                         */
/* ================================================================== */
__global__ __launch_bounds__(256) void av_kernel()
{
    __shared__ float Es[32][264];  /* [l][q] transposed */
    __shared__ float Vs[32][68];   /* [l][d]            */

    const int g  = blockIdx.y;
    const int q0 = blockIdx.x * 256;
    const int tid = threadIdx.x;

    const float* Sg = g_S + (size_t)g * SEQ * SEQ;
    const float* Vg = g_V + (size_t)g * SEQ * HD;
    const float* Mg = g_M + g * SEQ;
    const float* Zg = g_Zi + g * SEQ;

    const int ty = tid >> 3, tx = tid & 7;     /* 32 x 8 */
    const int rowbase = ty * 8, colbase = tx * 8;

    u64 acc[8][4];
#pragma unroll
    for (int i = 0; i < 8; i++)
#pragma unroll
        for (int j = 0; j < 4; j++) acc[i][j] = 0ull;

    for (int l0 = 0; l0 < SEQ; l0 += 32) {
        /* V tile: 32 x 64 */
#pragma unroll
        for (int it = 0; it < 2; it++) {
            const int idx = tid + it * 256;    /* 0..511 */
            const int row = idx >> 4;          /* 0..31  */
            const int c   = (idx & 15) * 4;    /* 0..60  */
            *(float4*)&Vs[row][c] = *(const float4*)(Vg + (size_t)(l0 + row) * HD + c);
        }
        /* E tile: 256 q-rows x 32 l-cols, transposed into Es[l][q] */
        {
            const int row = tid;               /* q offset 0..255 */
            const float* srow = Sg + (size_t)(q0 + row) * SEQ + l0;
#pragma unroll
            for (int cb = 0; cb < 32; cb += 4) {
                float4 sv = *(const float4*)(srow + cb);
                float4 mv = *(const float4*)(Mg + l0 + cb);
                float4 zv = *(const float4*)(Zg + l0 + cb);
                Es[cb + 0][row] = __expf(sv.x - mv.x) * zv.x;
                Es[cb + 1][row] = __expf(sv.y - mv.y) * zv.y;
                Es[cb + 2][row] = __expf(sv.z - mv.z) * zv.z;
                Es[cb + 3][row] = __expf(sv.w - mv.w) * zv.w;
            }
        }
        __syncthreads();
#pragma unroll
        for (int k = 0; k < 32; k++)
            MICRO_FFMA2(Es, Vs, k, rowbase, colbase, acc);
        __syncthreads();
    }

    const int n = g >> 5, b = (g >> 3) & 3, h = g & 7;
#pragma unroll
    for (int i = 0; i < 8; i++) {
        const int q = q0 + rowbase + i;
        const size_t t = (size_t)(n * SEQ + q);
        float* orow = g_AO + t * EMBED + b * EBS + h * HD;
        float r[8];
#pragma unroll
        for (int pp = 0; pp < 4; pp++) {
            float2 f = unpack2(acc[i][pp]);
            r[2 * pp] = f.x; r[2 * pp + 1] = f.y;
        }
        float4 r0, r1;
        r0.x = r[0]; r0.y = r[1]; r0.z = r[2]; r0.w = r[3];
        r1.x = r[4]; r1.y = r[5]; r1.z = r[6]; r1.w = r[7];
        *(float4*)(orow + colbase)     = r0;
        *(float4*)(orow + colbase + 4) = r1;
    }
}

/* ------------------------------------------------------------------ */
extern "C" void kernel_launch(void* const* d_in, const int* in_sizes, int n_in,
                              void* d_out, int out_size)
{
    const float* values = (const float*)d_in[0];
    const float* keys   = (const float*)d_in[1];
    const float* query  = (const float*)d_in[2];
    const int*   mask   = (const int*)d_in[3];
    const float* Wv = (const float*)d_in[4];
    const float* bv = (const float*)d_in[5];
    const float* Wk = (const float*)d_in[6];
    const float* bk = (const float*)d_in[7];
    const float* Wq = (const float*)d_in[8];
    const float* bq = (const float*)d_in[9];
    const float* Wo = (const float*)d_in[10];
    const float* bo = (const float*)d_in[11];
    float* out = (float*)d_out;

    float *pQ, *pK, *pV, *pAO;
    cudaGetSymbolAddress((void**)&pQ,  g_Q);
    cudaGetSymbolAddress((void**)&pK,  g_K);
    cudaGetSymbolAddress((void**)&pV,  g_V);
    cudaGetSymbolAddress((void**)&pAO, g_AO);

    QKVArgs qa;
    qa.X[0] = values; qa.X[1] = keys; qa.X[2] = query;
    qa.W[0] = Wv;     qa.W[1] = Wk;   qa.W[2] = Wq;
    qa.B[0] = bv;     qa.B[1] = bk;   qa.B[2] = bq;
    qa.O[0] = pV;     qa.O[1] = pK;   qa.O[2] = pQ;

    dim3 gqkv(EBS / 128, TTOK / 128, 3 * NB);
    qkv_proj_kernel<<<gqkv, 256>>>(qa);

    dim3 ge(SEQ / 128, SEQ / 128, NG);
    energy_kernel<<<ge, 256>>>(mask);

    dim3 gc(SEQ / 256, NG);
    colstat_kernel<<<gc, 256>>>();

    dim3 ga(SEQ / 256, NG);
    av_kernel<<<ga, 256>>>();

    dim3 go(EBS / 128, TTOK / 128, NB);
    oproj_kernel<<<go, 256>>>(pAO, Wo, bo, out);
}

// round 7
// speedup vs baseline: 1.6071x; 1.2908x over previous
#include <cuda_runtime.h>
#include <cuda_bf16.h>
#include <math.h>
#include <stdint.h>

#define NBATCH 4
#define SEQ    1024
#define EMBED  2048
#define EBS    512
#define NB     4
#define HEADS  8
#define HD     64
#define TTOK   (NBATCH * SEQ)        /* 4096 tokens */
#define NG     (NBATCH * NB * HEADS) /* 128 (n,b,h) heads */

typedef unsigned long long u64;

#define SMEM_SWIZZLE_128B(off) ((off) ^ (((off) >> 3) & 0x70))

/* ================================================================== */
/* sm_80-path tensor helpers (non-arch-specific: work on sm_103 base)  */
/* ================================================================== */
__device__ __forceinline__ uint32_t smem_to_u32(const void* p) {
    uint32_t a;
    asm("{ .reg .u64 t; cvta.to.shared.u64 t, %1; cvt.u32.u64 %0, t; }"
        : "=r"(a) : "l"(p));
    return a;
}
__device__ __forceinline__ void ldsm4(uint32_t* r, uint32_t addr) {
    asm volatile("ldmatrix.sync.aligned.m8n8.x4.shared.b16 {%0,%1,%2,%3}, [%4];"
                 : "=r"(r[0]), "=r"(r[1]), "=r"(r[2]), "=r"(r[3]) : "r"(addr));
}
__device__ __forceinline__ void mma16816(float* d, const uint32_t* a,
                                         const uint32_t* b) {
    asm volatile(
        "mma.sync.aligned.m16n8k16.row.col.f32.bf16.bf16.f32 "
        "{%0,%1,%2,%3}, {%4,%5,%6,%7}, {%8,%9}, {%0,%1,%2,%3};"
        : "+f"(d[0]), "+f"(d[1]), "+f"(d[2]), "+f"(d[3])
        : "r"(a[0]), "r"(a[1]), "r"(a[2]), "r"(a[3]), "r"(b[0]), "r"(b[1]));
}

/* packed fp32x2 helpers (attention kernels) */
__device__ __forceinline__ u64 dup2(float x) {
    u64 r; asm("mov.b64 %0, {%1, %1};" : "=l"(r) : "f"(x)); return r;
}
__device__ __forceinline__ u64 ffma2(u64 a, u64 b, u64 c) {
    u64 d; asm("fma.rn.f32x2 %0, %1, %2, %3;" : "=l"(d) : "l"(a), "l"(b), "l"(c)); return d;
}
__device__ __forceinline__ float2 unpack2(u64 v) {
    float2 f; asm("mov.b64 {%0, %1}, %2;" : "=f"(f.x), "=f"(f.y) : "l"(v)); return f;
}
__device__ __forceinline__ uint32_t packbf2(float a, float b) {
    __nv_bfloat162 p = __floats2bfloat162_rn(a, b);
    return *(uint32_t*)&p;
}

/* ================================================================== */
/* Device scratch                                                      */
/* ================================================================== */
__device__ __align__(256) float g_Q[(size_t)NG * SEQ * HD];
__device__ __align__(256) float g_K[(size_t)NG * SEQ * HD];
__device__ __align__(256) float g_V[(size_t)NG * SEQ * HD];
__device__ __align__(256) float g_S[(size_t)NG * SEQ * SEQ];
__device__ float g_M[NG * SEQ];
__device__ float g_Zi[NG * SEQ];
__device__ __align__(256) __nv_bfloat16 g_Xh[(size_t)3 * TTOK * EMBED];
__device__ __align__(256) __nv_bfloat16 g_Xl[(size_t)3 * TTOK * EMBED];
__device__ __align__(256) __nv_bfloat16 g_AOh[(size_t)TTOK * EMBED];
__device__ __align__(256) __nv_bfloat16 g_AOl[(size_t)TTOK * EMBED];
__device__ __align__(256) __nv_bfloat16 g_Wh[(size_t)4 * NB * EBS * EBS]; /* [wi][b][o][i] */
__device__ __align__(256) __nv_bfloat16 g_Wl[(size_t)4 * NB * EBS * EBS];

/* ================================================================== */
/* Converters                                                          */
/* ================================================================== */
__global__ __launch_bounds__(256) void convx_kernel(
    const float* __restrict__ V, const float* __restrict__ K,
    const float* __restrict__ Q)
{
    const int p = blockIdx.y;
    const float* src = (p == 0) ? V : (p == 1) ? K : Q;
    __nv_bfloat16* dh = g_Xh + (size_t)p * TTOK * EMBED;
    __nv_bfloat16* dl = g_Xl + (size_t)p * TTOK * EMBED;
    const size_t i = ((size_t)blockIdx.x * 256 + threadIdx.x) * 4;
    float4 v = *(const float4*)(src + i);
    float f[4] = {v.x, v.y, v.z, v.w};
    __nv_bfloat16 h[4], l[4];
#pragma unroll
    for (int j = 0; j < 4; j++) {
        h[j] = __float2bfloat16_rn(f[j]);
        l[j] = __float2bfloat16_rn(f[j] - __bfloat162float(h[j]));
    }
    uint2 hv, lv;
    hv.x = packbf2(__bfloat162float(h[0]), __bfloat162float(h[1]));
    hv.y = packbf2(__bfloat162float(h[2]), __bfloat162float(h[3]));
    lv.x = packbf2(__bfloat162float(l[0]), __bfloat162float(l[1]));
    lv.y = packbf2(__bfloat162float(l[2]), __bfloat162float(l[3]));
    *(uint2*)(dh + i) = hv;
    *(uint2*)(dl + i) = lv;
}

/* transpose + split weights: W[wi][b][i][o] -> g_Wh/l [wi][b][o][i] */
__global__ __launch_bounds__(256) void convw_kernel(
    const float* __restrict__ Wv, const float* __restrict__ Wk,
    const float* __restrict__ Wq, const float* __restrict__ Wo)
{
    __shared__ float st[32][33];
    const int z = blockIdx.z;
    const int wi = z >> 2, b = z & 3;
    const float* W = ((wi == 0) ? Wv : (wi == 1) ? Wk : (wi == 2) ? Wq : Wo)
                     + (size_t)b * EBS * EBS;
    const int i0 = blockIdx.y * 32, o0 = blockIdx.x * 32;
    const int tx = threadIdx.x, ty = threadIdx.y;
#pragma unroll
    for (int kk = 0; kk < 4; kk++)
        st[ty + 8 * kk][tx] = W[(size_t)(i0 + ty + 8 * kk) * EBS + o0 + tx];
    __syncthreads();
    __nv_bfloat16* oh = g_Wh + (size_t)(wi * NB + b) * EBS * EBS;
    __nv_bfloat16* ol = g_Wl + (size_t)(wi * NB + b) * EBS * EBS;
#pragma unroll
    for (int kk = 0; kk < 4; kk++) {
        const float v = st[tx][ty + 8 * kk];
        const __nv_bfloat16 h = __float2bfloat16_rn(v);
        const __nv_bfloat16 l = __float2bfloat16_rn(v - __bfloat162float(h));
        const size_t off = (size_t)(o0 + ty + 8 * kk) * EBS + i0 + tx;
        oh[off] = h;
        ol[off] = l;
    }
}

/* ================================================================== */
/* mma.sync bf16 3-split GEMM. 128x128 CTA tile, K=512 in 8 chunks of  */
/* 64. 8 warps as 2(m)x4(n); warp tile 64x32; frags via ldmatrix on    */
/* SW128-swizzled smem tiles.                                          */
/* MODE 0: qkv (z = p*4+b, A = g_Xh[p], out head-major g_V/K/Q).       */
/* MODE 1: oproj (z = b, A = g_AOh, out = d_out).                      */
/* ================================================================== */
#define KCHUNK 64
#define NCHUNKS 8
#define TILE_BYTES 16384                  /* 128 rows x 128B */
#define SS 132                            /* staging stride (floats) */
#define SMEM_GEMM_TOTAL (128 * SS * 4)    /* 67584B >= 4*TILE_BYTES  */

template <int MODE>
__global__ __launch_bounds__(256) void mm_kernel(
    const float* __restrict__ bias0, const float* __restrict__ bias1,
    const float* __restrict__ bias2, float* __restrict__ oout)
{
    extern __shared__ char smem[];
    const uint32_t smem_base = smem_to_u32(smem);
    const int tid = threadIdx.x;
    const int wid = tid >> 5, lane = tid & 31;
    const int wm = wid & 1, wn = wid >> 1;   /* warp tile: (wm*64, wn*32) */

    int p, b;
    const __nv_bfloat16 *Ah, *Al;
    const float* bias;
    if (MODE == 0) {
        p = blockIdx.z >> 2; b = blockIdx.z & 3;
        Ah = g_Xh + (size_t)p * TTOK * EMBED;
        Al = g_Xl + (size_t)p * TTOK * EMBED;
        bias = (p == 0) ? bias0 : (p == 1) ? bias1 : bias2;
    } else {
        p = 3; b = blockIdx.z;
        Ah = g_AOh; Al = g_AOl;
        bias = bias0;
    }
    const __nv_bfloat16* Bh = g_Wh + (size_t)(p * NB + b) * EBS * EBS;
    const __nv_bfloat16* Bl = g_Wl + (size_t)(p * NB + b) * EBS * EBS;
    const int m0 = blockIdx.y * 128, n0 = blockIdx.x * 128;

    const uint32_t tAh = smem_base;
    const uint32_t tAl = smem_base + TILE_BYTES;
    const uint32_t tBh = smem_base + 2 * TILE_BYTES;
    const uint32_t tBl = smem_base + 3 * TILE_BYTES;

    /* gmem loader indices (64B per thread per tile) */
    const int lrow = tid >> 1;
    const int lhalf = (tid & 1) * 32;
    const __nv_bfloat16* Arow_h = Ah + (size_t)(m0 + lrow) * EMBED + b * EBS + lhalf;
    const __nv_bfloat16* Arow_l = Al + (size_t)(m0 + lrow) * EMBED + b * EBS + lhalf;
    const __nv_bfloat16* Brow_h = Bh + (size_t)(n0 + lrow) * EBS + lhalf;
    const __nv_bfloat16* Brow_l = Bl + (size_t)(n0 + lrow) * EBS + lhalf;
    uint32_t sw[4];
#pragma unroll
    for (int gix = 0; gix < 4; gix++)
        sw[gix] = SMEM_SWIZZLE_128B((uint32_t)(lrow * 128 + (lhalf + gix * 8) * 2));

    /* ldmatrix per-lane address components */
    const int a_row = (lane & 15);            /* within 16-row frag */
    const int a_c16 = (lane >> 4) * 16;       /* k-halves           */
    const int b_row = (lane & 7) + ((lane >> 4) << 3);
    const int b_c16 = ((lane >> 3) & 1) * 16;

    float acc[4][4][4];
#pragma unroll
    for (int mf = 0; mf < 4; mf++)
#pragma unroll
        for (int nf = 0; nf < 4; nf++)
#pragma unroll
            for (int r = 0; r < 4; r++) acc[mf][nf][r] = 0.f;

    for (int c = 0; c < NCHUNKS; c++) {
        const int coff = c * KCHUNK;
#pragma unroll
        for (int gix = 0; gix < 4; gix++) {
            uint4 vah = *(const uint4*)(Arow_h + coff + gix * 8);
            uint4 val = *(const uint4*)(Arow_l + coff + gix * 8);
            uint4 vbh = *(const uint4*)(Brow_h + coff + gix * 8);
            uint4 vbl = *(const uint4*)(Brow_l + coff + gix * 8);
            *(uint4*)(smem + (tAh - smem_base) + sw[gix]) = vah;
            *(uint4*)(smem + (tAl - smem_base) + sw[gix]) = val;
            *(uint4*)(smem + (tBh - smem_base) + sw[gix]) = vbh;
            *(uint4*)(smem + (tBl - smem_base) + sw[gix]) = vbl;
        }
        __syncthreads();

#pragma unroll
        for (int ks = 0; ks < 4; ks++) {
            uint32_t ah[4][4], al[4][4];
#pragma unroll
            for (int mf = 0; mf < 4; mf++) {
                const uint32_t off = (uint32_t)((wm * 64 + mf * 16 + a_row) * 128
                                                + ks * 32 + a_c16);
                const uint32_t swo = SMEM_SWIZZLE_128B(off);
                ldsm4(ah[mf], tAh + swo);
                ldsm4(al[mf], tAl + swo);
            }
            uint32_t bh[8];
#pragma unroll
            for (int np = 0; np < 2; np++) {
                const uint32_t off = (uint32_t)((wn * 32 + np * 16 + b_row) * 128
                                                + ks * 32 + b_c16);
                ldsm4(&bh[np * 4], tBh + SMEM_SWIZZLE_128B(off));
            }
#pragma unroll
            for (int mf = 0; mf < 4; mf++)
#pragma unroll
                for (int nf = 0; nf < 4; nf++)
                    mma16816(acc[mf][nf], ah[mf], &bh[nf * 2]);
#pragma unroll
            for (int mf = 0; mf < 4; mf++)
#pragma unroll
                for (int nf = 0; nf < 4; nf++)
                    mma16816(acc[mf][nf], al[mf], &bh[nf * 2]);
            uint32_t bl[8];
#pragma unroll
            for (int np = 0; np < 2; np++) {
                const uint32_t off = (uint32_t)((wn * 32 + np * 16 + b_row) * 128
                                                + ks * 32 + b_c16);
                ldsm4(&bl[np * 4], tBl + SMEM_SWIZZLE_128B(off));
            }
#pragma unroll
            for (int mf = 0; mf < 4; mf++)
#pragma unroll
                for (int nf = 0; nf < 4; nf++)
                    mma16816(acc[mf][nf], ah[mf], &bl[nf * 2]);
        }
        __syncthreads();
    }

    /* stage accumulators to smem (overwrites tiles) */
    float* stg = (float*)smem;  /* [128][SS] */
    const int gr = lane >> 2, c2 = (lane & 3) * 2;
#pragma unroll
    for (int mf = 0; mf < 4; mf++) {
        const int row0 = wm * 64 + mf * 16 + gr;
#pragma unroll
        for (int nf = 0; nf < 4; nf++) {
            const int col = wn * 32 + nf * 8 + c2;
            *(float2*)&stg[row0 * SS + col]       = make_float2(acc[mf][nf][0], acc[mf][nf][1]);
            *(float2*)&stg[(row0 + 8) * SS + col] = make_float2(acc[mf][nf][2], acc[mf][nf][3]);
        }
    }
    __syncthreads();

    if (MODE == 0) {
        const int n = m0 >> 10, s0 = m0 & (SEQ - 1);
        const int h0 = n0 >> 6;
        float* outp = (p == 0) ? g_V : (p == 1) ? g_K : g_Q;
#pragma unroll
        for (int it = 0; it < 16; it++) {
            const int flat = tid + it * 256;
            const int srow = flat >> 5;
            const int rem = flat & 31;
            const int hh = rem >> 4, dq = (rem & 15) * 4;
            const int ocol = hh * 64 + dq;
            float4 v;
            v.x = stg[srow * SS + ocol + 0] + bias[b * EBS + n0 + ocol + 0];
            v.y = stg[srow * SS + ocol + 1] + bias[b * EBS + n0 + ocol + 1];
            v.z = stg[srow * SS + ocol + 2] + bias[b * EBS + n0 + ocol + 2];
            v.w = stg[srow * SS + ocol + 3] + bias[b * EBS + n0 + ocol + 3];
            const size_t gidx = (size_t)((n * NB + b) * HEADS + h0 + hh);
            *(float4*)(outp + (gidx * SEQ + s0 + srow) * HD + dq) = v;
        }
    } else {
#pragma unroll
        for (int it = 0; it < 16; it++) {
            const int flat = tid + it * 256;
            const int srow = flat >> 5;
            const int oq = (flat & 31) * 4;
            float4 v;
            v.x = stg[srow * SS + oq + 0] + bias[b * EBS + n0 + oq + 0];
            v.y = stg[srow * SS + oq + 1] + bias[b * EBS + n0 + oq + 1];
            v.z = stg[srow * SS + oq + 2] + bias[b * EBS + n0 + oq + 2];
            v.w = stg[srow * SS + oq + 3] + bias[b * EBS + n0 + oq + 3];
            *(float4*)(oout + (size_t)(m0 + srow) * EMBED + b * EBS + n0 + oq) = v;
        }
    }
}

/* ================================================================== */
/* Energy: S[g,q,l] = (sum_d Q*K) masked * 0.125. 128x128, 8x8 micro.  */
/* ================================================================== */
#define MICRO_FFMA2(As_, Bs_, k_, rowbase_, colbase_, acc_)                   \
    do {                                                                      \
        float4 a0_ = *(const float4*)&As_[k_][rowbase_];                      \
        float4 a1_ = *(const float4*)&As_[k_][rowbase_ + 4];                  \
        ulonglong2 bb0_ = *(const ulonglong2*)&Bs_[k_][colbase_];             \
        ulonglong2 bb1_ = *(const ulonglong2*)&Bs_[k_][colbase_ + 4];         \
        const u64 bp_[4] = {bb0_.x, bb0_.y, bb1_.x, bb1_.y};                  \
        const float af_[8] = {a0_.x, a0_.y, a0_.z, a0_.w,                     \
                              a1_.x, a1_.y, a1_.z, a1_.w};                    \
        _Pragma("unroll")                                                     \
        for (int i_ = 0; i_ < 8; i_++) {                                      \
            const u64 ad_ = dup2(af_[i_]);                                    \
            _Pragma("unroll")                                                 \
            for (int p_ = 0; p_ < 4; p_++)                                    \
                acc_[i_][p_] = ffma2(ad_, bp_[p_], acc_[i_][p_]);             \
        }                                                                     \
    } while (0)

__global__ __launch_bounds__(256) void energy_kernel(const int* __restrict__ mask)
{
    __shared__ float Qs[8][132];
    __shared__ float Ks[8][132];

    const int g  = blockIdx.z;
    const int q0 = blockIdx.y * 128;
    const int l0 = blockIdx.x * 128;
    const int tid = threadIdx.x;

    const float* Qg = g_Q + (size_t)g * SEQ * HD;
    const float* Kg = g_K + (size_t)g * SEQ * HD;

    const int ty = tid >> 4, tx = tid & 15;
    const int rowbase = ty * 8, colbase = tx * 8;
    const int arow = tid >> 1, akq = (tid & 1) * 4;

    u64 acc[8][4];
#pragma unroll
    for (int i = 0; i < 8; i++)
#pragma unroll
        for (int j = 0; j < 4; j++) acc[i][j] = 0ull;

    for (int k0 = 0; k0 < HD; k0 += 8) {
        float4 qv = *(const float4*)(Qg + (size_t)(q0 + arow) * HD + k0 + akq);
        float4 kv = *(const float4*)(Kg + (size_t)(l0 + arow) * HD + k0 + akq);
        Qs[akq + 0][arow] = qv.x; Qs[akq + 1][arow] = qv.y;
        Qs[akq + 2][arow] = qv.z; Qs[akq + 3][arow] = qv.w;
        Ks[akq + 0][arow] = kv.x; Ks[akq + 1][arow] = kv.y;
        Ks[akq + 2][arow] = kv.z; Ks[akq + 3][arow] = kv.w;
        __syncthreads();
#pragma unroll
        for (int k = 0; k < 8; k++)
            MICRO_FFMA2(Qs, Ks, k, rowbase, colbase, acc);
        __syncthreads();
    }

    const int n = g >> 5;
    float* Sg = g_S + (size_t)g * SEQ * SEQ;
    const int* Mn = mask + (size_t)n * SEQ * SEQ;

#pragma unroll
    for (int i = 0; i < 8; i++) {
        const int q = q0 + rowbase + i;
        const int* mrow = Mn + (size_t)q * SEQ + l0 + colbase;
        int4 mm0 = *(const int4*)(mrow);
        int4 mm1 = *(const int4*)(mrow + 4);
        const int mv[8] = {mm0.x,mm0.y,mm0.z,mm0.w,mm1.x,mm1.y,mm1.z,mm1.w};
        float r[8];
#pragma unroll
        for (int pp = 0; pp < 4; pp++) {
            float2 f = unpack2(acc[i][pp]);
            r[2 * pp] = f.x; r[2 * pp + 1] = f.y;
        }
        float rr[8];
#pragma unroll
        for (int j = 0; j < 8; j++) {
            float e = (mv[j] == 0) ? -1e20f : r[j];
            rr[j] = e * 0.125f;
        }
        float4 r0, r1;
        r0.x = rr[0]; r0.y = rr[1]; r0.z = rr[2]; r0.w = rr[3];
        r1.x = rr[4]; r1.y = rr[5]; r1.z = rr[6]; r1.w = rr[7];
        float* srow = Sg + (size_t)q * SEQ + l0 + colbase;
        *(float4*)(srow)     = r0;
        *(float4*)(srow + 4) = r1;
    }
}

/* ================================================================== */
/* Column softmax stats over the QUERY axis (one online pass)          */
/* ================================================================== */
__global__ __launch_bounds__(256) void colstat_kernel()
{
    const int g = blockIdx.y;
    const int l = blockIdx.x * 256 + threadIdx.x;
    const float* Sg = g_S + (size_t)g * SEQ * SEQ + l;

    float m = -3.4e38f, z = 0.f;
    for (int q = 0; q < SEQ; q += 4) {
        float x0 = Sg[(size_t)(q + 0) * SEQ];
        float x1 = Sg[(size_t)(q + 1) * SEQ];
        float x2 = Sg[(size_t)(q + 2) * SEQ];
        float x3 = Sg[(size_t)(q + 3) * SEQ];
#pragma unroll
        for (int u = 0; u < 4; u++) {
            float x = (u == 0) ? x0 : (u == 1) ? x1 : (u == 2) ? x2 : x3;
            if (x > m) { z = z * __expf(m - x) + 1.f; m = x; }
            else       { z += __expf(x - m); }
        }
    }
    g_M[g * SEQ + l]  = m;
    g_Zi[g * SEQ + l] = 1.f / z;
}

/* ================================================================== */
/* AV: O = A·V, writes bf16 hi/lo pairs directly (oproj input).        */
/* ================================================================== */
__global__ __launch_bounds__(256) void av_kernel()
{
    __shared__ float Es[32][264];
    __shared__ float Vs[32][68];

    const int g  = blockIdx.y;
    const int q0 = blockIdx.x * 256;
    const int tid = threadIdx.x;

    const float* Sg = g_S + (size_t)g * SEQ * SEQ;
    const float* Vg = g_V + (size_t)g * SEQ * HD;
    const float* Mg = g_M + g * SEQ;
    const float* Zg = g_Zi + g * SEQ;

    const int ty = tid >> 3, tx = tid & 7;
    const int rowbase = ty * 8, colbase = tx * 8;

    u64 acc[8][4];
#pragma unroll
    for (int i = 0; i < 8; i++)
#pragma unroll
        for (int j = 0; j < 4; j++) acc[i][j] = 0ull;

    for (int l0 = 0; l0 < SEQ; l0 += 32) {
#pragma unroll
        for (int it = 0; it < 2; it++) {
            const int idx = tid + it * 256;
            const int row = idx >> 4;
            const int c   = (idx & 15) * 4;
            *(float4*)&Vs[row][c] = *(const float4*)(Vg + (size_t)(l0 + row) * HD + c);
        }
        {
            const int row = tid;
            const float* srow = Sg + (size_t)(q0 + row) * SEQ + l0;
#pragma unroll
            for (int cb = 0; cb < 32; cb += 4) {
                float4 sv = *(const float4*)(srow + cb);
                float4 mv = *(const float4*)(Mg + l0 + cb);
                float4 zv = *(const float4*)(Zg + l0 + cb);
                Es[cb + 0][row] = __expf(sv.x - mv.x) * zv.x;
                Es[cb + 1][row] = __expf(sv.y - mv.y) * zv.y;
                Es[cb + 2][row] = __expf(sv.z - mv.z) * zv.z;
                Es[cb + 3][row] = __expf(sv.w - mv.w) * zv.w;
            }
        }
        __syncthreads();
#pragma unroll
        for (int k = 0; k < 32; k++)
            MICRO_FFMA2(Es, Vs, k, rowbase, colbase, acc);
        __syncthreads();
    }

    const int n = g >> 5, b = (g >> 3) & 3, hd = g & 7;
#pragma unroll
    for (int i = 0; i < 8; i++) {
        const int q = q0 + rowbase + i;
        const size_t t = (size_t)(n * SEQ + q);
        const size_t off = t * EMBED + b * EBS + hd * HD + colbase;
        float r[8];
#pragma unroll
        for (int pp = 0; pp < 4; pp++) {
            float2 f = unpack2(acc[i][pp]);
            r[2 * pp] = f.x; r[2 * pp + 1] = f.y;
        }
        float hi[8], lo[8];
#pragma unroll
        for (int j = 0; j < 8; j++) {
            __nv_bfloat16 hb = __float2bfloat16_rn(r[j]);
            hi[j] = __bfloat162float(hb);
            lo[j] = r[j] - hi[j];
        }
        uint4 hv, lv;
        hv.x = packbf2(hi[0], hi[1]); hv.y = packbf2(hi[2], hi[3]);
        hv.z = packbf2(hi[4], hi[5]); hv.w = packbf2(hi[6], hi[7]);
        lv.x = packbf2(lo[0], lo[1]); lv.y = packbf2(lo[2], lo[3]);
        lv.z = packbf2(lo[4], lo[5]); lv.w = packbf2(lo[6], lo[7]);
        *(uint4*)(g_AOh + off) = hv;
        *(uint4*)(g_AOl + off) = lv;
    }
}

/* ------------------------------------------------------------------ */
extern "C" void kernel_launch(void* const* d_in, const int* in_sizes, int n_in,
                              void* d_out, int out_size)
{
    const float* values = (const float*)d_in[0];
    const float* keys   = (const float*)d_in[1];
    const float* query  = (const float*)d_in[2];
    const int*   mask   = (const int*)d_in[3];
    const float* Wv = (const float*)d_in[4];
    const float* bv = (const float*)d_in[5];
    const float* Wk = (const float*)d_in[6];
    const float* bk = (const float*)d_in[7];
    const float* Wq = (const float*)d_in[8];
    const float* bq = (const float*)d_in[9];
    const float* Wo = (const float*)d_in[10];
    const float* bo = (const float*)d_in[11];
    float* out = (float*)d_out;

    cudaFuncSetAttribute(mm_kernel<0>, cudaFuncAttributeMaxDynamicSharedMemorySize,
                         SMEM_GEMM_TOTAL);
    cudaFuncSetAttribute(mm_kernel<1>, cudaFuncAttributeMaxDynamicSharedMemorySize,
                         SMEM_GEMM_TOTAL);

    /* converts */
    dim3 gx((TTOK * EMBED) / (256 * 4), 3);
    convx_kernel<<<gx, 256>>>(values, keys, query);
    dim3 gw(EBS / 32, EBS / 32, 16);
    convw_kernel<<<gw, dim3(32, 8)>>>(Wv, Wk, Wq, Wo);

    /* fused qkv projections on mma.sync bf16 */
    dim3 gqkv(EBS / 128, TTOK / 128, 12);
    mm_kernel<0><<<gqkv, 256, SMEM_GEMM_TOTAL>>>(bv, bk, bq, nullptr);

    dim3 ge(SEQ / 128, SEQ / 128, NG);
    energy_kernel<<<ge, 256>>>(mask);

    dim3 gc(SEQ / 256, NG);
    colstat_kernel<<<gc, 256>>>();

    dim3 ga(SEQ / 256, NG);
    av_kernel<<<ga, 256>>>();

    /* output projection on mma.sync bf16 */
    dim3 go(EBS / 128, TTOK / 128, NB);
    mm_kernel<1><<<go, 256, SMEM_GEMM_TOTAL>>>(bo, nullptr, nullptr, out);
}

// round 9
// speedup vs baseline: 2.1557x; 1.3413x over previous
#include <cuda_runtime.h>
#include <cuda_bf16.h>
#include <math.h>
#include <stdint.h>

#define NBATCH 4
#define SEQ    1024
#define EMBED  2048
#define EBS    512
#define NB     4
#define HEADS  8
#define HD     64
#define TTOK   (NBATCH * SEQ)        /* 4096 tokens */
#define NG     (NBATCH * NB * HEADS) /* 128 (n,b,h) heads */

typedef unsigned long long u64;

#define SMEM_SWIZZLE_128B(off) ((off) ^ (((off) >> 3) & 0x70))

/* ================================================================== */
/* Tensor helpers (sm_80 path: legal on base sm_103 target)            */
/* ================================================================== */
__device__ __forceinline__ uint32_t smem_to_u32(const void* p) {
    uint32_t a;
    asm("{ .reg .u64 t; cvta.to.shared.u64 t, %1; cvt.u32.u64 %0, t; }"
        : "=r"(a) : "l"(p));
    return a;
}
__device__ __forceinline__ void ldsm4(uint32_t* r, uint32_t addr) {
    asm volatile("ldmatrix.sync.aligned.m8n8.x4.shared.b16 {%0,%1,%2,%3}, [%4];"
                 : "=r"(r[0]), "=r"(r[1]), "=r"(r[2]), "=r"(r[3]) : "r"(addr));
}
__device__ __forceinline__ void mma16816(float* d, const uint32_t* a,
                                         const uint32_t* b) {
    asm volatile(
        "mma.sync.aligned.m16n8k16.row.col.f32.bf16.bf16.f32 "
        "{%0,%1,%2,%3}, {%4,%5,%6,%7}, {%8,%9}, {%0,%1,%2,%3};"
        : "+f"(d[0]), "+f"(d[1]), "+f"(d[2]), "+f"(d[3])
        : "r"(a[0]), "r"(a[1]), "r"(a[2]), "r"(a[3]), "r"(b[0]), "r"(b[1]));
}
__device__ __forceinline__ uint32_t packbf2(float a, float b) {
    __nv_bfloat162 p = __floats2bfloat162_rn(a, b);
    return *(uint32_t*)&p;
}
__device__ __forceinline__ void splitf(float v, float& hi, float& lo) {
    __nv_bfloat16 hb = __float2bfloat16_rn(v);
    hi = __bfloat162float(hb);
    lo = v - hi;
}

/* ================================================================== */
/* Device scratch                                                      */
/* ================================================================== */
__device__ __align__(256) float g_S[(size_t)NG * SEQ * SEQ];  /* 512 MB */
__device__ float g_M[NG * SEQ];
__device__ float g_Zi[NG * SEQ];
__device__ __align__(256) __nv_bfloat16 g_Xh[(size_t)3 * TTOK * EMBED];
__device__ __align__(256) __nv_bfloat16 g_Xl[(size_t)3 * TTOK * EMBED];
__device__ __align__(256) __nv_bfloat16 g_AOh[(size_t)TTOK * EMBED];
__device__ __align__(256) __nv_bfloat16 g_AOl[(size_t)TTOK * EMBED];
__device__ __align__(256) __nv_bfloat16 g_Wh[(size_t)4 * NB * EBS * EBS]; /* [wi][b][o][i] */
__device__ __align__(256) __nv_bfloat16 g_Wl[(size_t)4 * NB * EBS * EBS];
__device__ __align__(256) __nv_bfloat16 g_Qh[(size_t)NG * SEQ * HD]; /* [g][s][d] */
__device__ __align__(256) __nv_bfloat16 g_Ql[(size_t)NG * SEQ * HD];
__device__ __align__(256) __nv_bfloat16 g_Kh[(size_t)NG * SEQ * HD];
__device__ __align__(256) __nv_bfloat16 g_Kl[(size_t)NG * SEQ * HD];
__device__ __align__(256) __nv_bfloat16 g_Vth[(size_t)NG * HD * SEQ]; /* [g][d][s] */
__device__ __align__(256) __nv_bfloat16 g_Vtl[(size_t)NG * HD * SEQ];

/* ================================================================== */
/* Converters                                                          */
/* ================================================================== */
__global__ __launch_bounds__(256) void convx_kernel(
    const float* __restrict__ V, const float* __restrict__ K,
    const float* __restrict__ Q)
{
    const int p = blockIdx.y;
    const float* src = (p == 0) ? V : (p == 1) ? K : Q;
    __nv_bfloat16* dh = g_Xh + (size_t)p * TTOK * EMBED;
    __nv_bfloat16* dl = g_Xl + (size_t)p * TTOK * EMBED;
    const size_t i = ((size_t)blockIdx.x * 256 + threadIdx.x) * 4;
    float4 v = *(const float4*)(src + i);
    float f[4] = {v.x, v.y, v.z, v.w};
    float hi[4], lo[4];
#pragma unroll
    for (int j = 0; j < 4; j++) splitf(f[j], hi[j], lo[j]);
    uint2 hv, lv;
    hv.x = packbf2(hi[0], hi[1]); hv.y = packbf2(hi[2], hi[3]);
    lv.x = packbf2(lo[0], lo[1]); lv.y = packbf2(lo[2], lo[3]);
    *(uint2*)(dh + i) = hv;
    *(uint2*)(dl + i) = lv;
}

/* transpose + split weights: W[wi][b][i][o] -> g_Wh/l [wi][b][o][i] */
__global__ __launch_bounds__(256) void convw_kernel(
    const float* __restrict__ Wv, const float* __restrict__ Wk,
    const float* __restrict__ Wq, const float* __restrict__ Wo)
{
    __shared__ float st[32][33];
    const int z = blockIdx.z;
    const int wi = z >> 2, b = z & 3;
    const float* W = ((wi == 0) ? Wv : (wi == 1) ? Wk : (wi == 2) ? Wq : Wo)
                     + (size_t)b * EBS * EBS;
    const int i0 = blockIdx.y * 32, o0 = blockIdx.x * 32;
    const int tx = threadIdx.x, ty = threadIdx.y;
#pragma unroll
    for (int kk = 0; kk < 4; kk++)
        st[ty + 8 * kk][tx] = W[(size_t)(i0 + ty + 8 * kk) * EBS + o0 + tx];
    __syncthreads();
    __nv_bfloat16* oh = g_Wh + (size_t)(wi * NB + b) * EBS * EBS;
    __nv_bfloat16* ol = g_Wl + (size_t)(wi * NB + b) * EBS * EBS;
#pragma unroll
    for (int kk = 0; kk < 4; kk++) {
        const float v = st[tx][ty + 8 * kk];
        float h, l;
        splitf(v, h, l);
        const size_t off = (size_t)(o0 + ty + 8 * kk) * EBS + i0 + tx;
        oh[off] = __float2bfloat16_rn(h);
        ol[off] = __float2bfloat16_rn(l);
    }
}

/* ================================================================== */
/* mma.sync bf16 3-split projection GEMM. 128x128 CTA tile, K=512 in   */
/* 8 chunks of 64. Warps 2(m)x4(n); warp tile 64x32.                   */
/* MODE 0: qkv. Q/K out: bf16 hi/lo head-major. V out: bf16 hi/lo      */
/*         transposed [g][d][s].                                       */
/* MODE 1: oproj (A = g_AOh/l, out = d_out fp32).                      */
/* ================================================================== */
#define KCHUNK 64
#define NCHUNKS 8
#define TILE_BYTES 16384                  /* 128 rows x 128B */
#define SS 132                            /* staging stride (floats) */
#define SMEM_GEMM_TOTAL (128 * SS * 4)    /* 67584B >= 4*TILE_BYTES  */

template <int MODE>
__global__ __launch_bounds__(256) void mm_kernel(
    const float* __restrict__ bias0, const float* __restrict__ bias1,
    const float* __restrict__ bias2, float* __restrict__ oout)
{
    extern __shared__ char smem[];
    const uint32_t smem_base = smem_to_u32(smem);
    const int tid = threadIdx.x;
    const int wid = tid >> 5, lane = tid & 31;
    const int wm = wid & 1, wn = wid >> 1;

    int p, b;
    const __nv_bfloat16 *Ah, *Al;
    const float* bias;
    if (MODE == 0) {
        p = blockIdx.z >> 2; b = blockIdx.z & 3;
        Ah = g_Xh + (size_t)p * TTOK * EMBED;
        Al = g_Xl + (size_t)p * TTOK * EMBED;
        bias = (p == 0) ? bias0 : (p == 1) ? bias1 : bias2;
    } else {
        p = 3; b = blockIdx.z;
        Ah = g_AOh; Al = g_AOl;
        bias = bias0;
    }
    const __nv_bfloat16* Bh = g_Wh + (size_t)(p * NB + b) * EBS * EBS;
    const __nv_bfloat16* Bl = g_Wl + (size_t)(p * NB + b) * EBS * EBS;
    const int m0 = blockIdx.y * 128, n0 = blockIdx.x * 128;

    const uint32_t tAh = smem_base;
    const uint32_t tAl = smem_base + TILE_BYTES;
    const uint32_t tBh = smem_base + 2 * TILE_BYTES;
    const uint32_t tBl = smem_base + 3 * TILE_BYTES;

    const int lrow = tid >> 1;
    const int lhalf = (tid & 1) * 32;
    const __nv_bfloat16* Arow_h = Ah + (size_t)(m0 + lrow) * EMBED + b * EBS + lhalf;
    const __nv_bfloat16* Arow_l = Al + (size_t)(m0 + lrow) * EMBED + b * EBS + lhalf;
    const __nv_bfloat16* Brow_h = Bh + (size_t)(n0 + lrow) * EBS + lhalf;
    const __nv_bfloat16* Brow_l = Bl + (size_t)(n0 + lrow) * EBS + lhalf;
    uint32_t sw[4];
#pragma unroll
    for (int gix = 0; gix < 4; gix++)
        sw[gix] = SMEM_SWIZZLE_128B((uint32_t)(lrow * 128 + (lhalf + gix * 8) * 2));

    const int a_row = (lane & 15);
    const int a_c16 = (lane >> 4) * 16;
    const int b_row = (lane & 7) + ((lane >> 4) << 3);
    const int b_c16 = ((lane >> 3) & 1) * 16;

    float acc[4][4][4];
#pragma unroll
    for (int mf = 0; mf < 4; mf++)
#pragma unroll
        for (int nf = 0; nf < 4; nf++)
#pragma unroll
            for (int r = 0; r < 4; r++) acc[mf][nf][r] = 0.f;

    for (int c = 0; c < NCHUNKS; c++) {
        const int coff = c * KCHUNK;
#pragma unroll
        for (int gix = 0; gix < 4; gix++) {
            uint4 vah = *(const uint4*)(Arow_h + coff + gix * 8);
            uint4 val = *(const uint4*)(Arow_l + coff + gix * 8);
            uint4 vbh = *(const uint4*)(Brow_h + coff + gix * 8);
            uint4 vbl = *(const uint4*)(Brow_l + coff + gix * 8);
            *(uint4*)(smem + 0 * TILE_BYTES + sw[gix]) = vah;
            *(uint4*)(smem + 1 * TILE_BYTES + sw[gix]) = val;
            *(uint4*)(smem + 2 * TILE_BYTES + sw[gix]) = vbh;
            *(uint4*)(smem + 3 * TILE_BYTES + sw[gix]) = vbl;
        }
        __syncthreads();

#pragma unroll
        for (int ks = 0; ks < 4; ks++) {
            uint32_t ah[4][4], al[4][4];
#pragma unroll
            for (int mf = 0; mf < 4; mf++) {
                const uint32_t off = (uint32_t)((wm * 64 + mf * 16 + a_row) * 128
                                                + ks * 32 + a_c16);
                const uint32_t swo = SMEM_SWIZZLE_128B(off);
                ldsm4(ah[mf], tAh + swo);
                ldsm4(al[mf], tAl + swo);
            }
            uint32_t bh[8];
#pragma unroll
            for (int np = 0; np < 2; np++) {
                const uint32_t off = (uint32_t)((wn * 32 + np * 16 + b_row) * 128
                                                + ks * 32 + b_c16);
                ldsm4(&bh[np * 4], tBh + SMEM_SWIZZLE_128B(off));
            }
#pragma unroll
            for (int mf = 0; mf < 4; mf++)
#pragma unroll
                for (int nf = 0; nf < 4; nf++)
                    mma16816(acc[mf][nf], ah[mf], &bh[nf * 2]);
#pragma unroll
            for (int mf = 0; mf < 4; mf++)
#pragma unroll
                for (int nf = 0; nf < 4; nf++)
                    mma16816(acc[mf][nf], al[mf], &bh[nf * 2]);
            uint32_t bl[8];
#pragma unroll
            for (int np = 0; np < 2; np++) {
                const uint32_t off = (uint32_t)((wn * 32 + np * 16 + b_row) * 128
                                                + ks * 32 + b_c16);
                ldsm4(&bl[np * 4], tBl + SMEM_SWIZZLE_128B(off));
            }
#pragma unroll
            for (int mf = 0; mf < 4; mf++)
#pragma unroll
                for (int nf = 0; nf < 4; nf++)
                    mma16816(acc[mf][nf], ah[mf], &bl[nf * 2]);
        }
        __syncthreads();
    }

    /* stage accumulators to smem */
    float* stg = (float*)smem;  /* [128][SS] */
    const int gr = lane >> 2, c2 = (lane & 3) * 2;
#pragma unroll
    for (int mf = 0; mf < 4; mf++) {
        const int row0 = wm * 64 + mf * 16 + gr;
#pragma unroll
        for (int nf = 0; nf < 4; nf++) {
            const int col = wn * 32 + nf * 8 + c2;
            *(float2*)&stg[row0 * SS + col]       = make_float2(acc[mf][nf][0], acc[mf][nf][1]);
            *(float2*)&stg[(row0 + 8) * SS + col] = make_float2(acc[mf][nf][2], acc[mf][nf][3]);
        }
    }
    __syncthreads();

    if (MODE == 0) {
        const int n = m0 >> 10, s0 = m0 & (SEQ - 1);
        const int h0 = n0 >> 6;
        if (p >= 1) {
            /* Q or K: bf16 hi/lo head-major [g][s][d] */
            __nv_bfloat16* oh = (p == 1) ? g_Kh : g_Qh;
            __nv_bfloat16* ol = (p == 1) ? g_Kl : g_Ql;
#pragma unroll
            for (int it = 0; it < 16; it++) {
                const int flat = tid + it * 256;
                const int srow = flat >> 5;
                const int rem = flat & 31;
                const int hh = rem >> 4, dq = (rem & 15) * 4;
                const int ocol = hh * 64 + dq;
                float hi[4], lo[4];
#pragma unroll
                for (int j = 0; j < 4; j++) {
                    const float v = stg[srow * SS + ocol + j]
                                    + bias[b * EBS + n0 + ocol + j];
                    splitf(v, hi[j], lo[j]);
                }
                uint2 hv, lv;
                hv.x = packbf2(hi[0], hi[1]); hv.y = packbf2(hi[2], hi[3]);
                lv.x = packbf2(lo[0], lo[1]); lv.y = packbf2(lo[2], lo[3]);
                const size_t gidx = (size_t)((n * NB + b) * HEADS + h0 + hh);
                const size_t off = (gidx * SEQ + s0 + srow) * HD + dq;
                *(uint2*)(oh + off) = hv;
                *(uint2*)(ol + off) = lv;
            }
        } else {
            /* V: bf16 hi/lo transposed [g][d][s] */
            const int dcol = tid >> 1;
            const int shalf = (tid & 1) * 64;
            const int hh = dcol >> 6, dl = dcol & 63;
            const size_t gidx = (size_t)((n * NB + b) * HEADS + h0 + hh);
            const float bb = bias[b * EBS + n0 + dcol];
            __nv_bfloat16* oh = g_Vth + (gidx * HD + dl) * SEQ + s0 + shalf;
            __nv_bfloat16* ol = g_Vtl + (gidx * HD + dl) * SEQ + s0 + shalf;
#pragma unroll
            for (int blk = 0; blk < 16; blk++) {
                float hi[4], lo[4];
#pragma unroll
                for (int j = 0; j < 4; j++) {
                    const float v = stg[(shalf + blk * 4 + j) * SS + dcol] + bb;
                    splitf(v, hi[j], lo[j]);
                }
                uint2 hv, lv;
                hv.x = packbf2(hi[0], hi[1]); hv.y = packbf2(hi[2], hi[3]);
                lv.x = packbf2(lo[0], lo[1]); lv.y = packbf2(lo[2], lo[3]);
                *(uint2*)(oh + blk * 4) = hv;
                *(uint2*)(ol + blk * 4) = lv;
            }
        }
    } else {
#pragma unroll
        for (int it = 0; it < 16; it++) {
            const int flat = tid + it * 256;
            const int srow = flat >> 5;
            const int oq = (flat & 31) * 4;
            float4 v;
            v.x = stg[srow * SS + oq + 0] + bias[b * EBS + n0 + oq + 0];
            v.y = stg[srow * SS + oq + 1] + bias[b * EBS + n0 + oq + 1];
            v.z = stg[srow * SS + oq + 2] + bias[b * EBS + n0 + oq + 2];
            v.w = stg[srow * SS + oq + 3] + bias[b * EBS + n0 + oq + 3];
            *(float4*)(oout + (size_t)(m0 + srow) * EMBED + b * EBS + n0 + oq) = v;
        }
    }
}

/* ================================================================== */
/* Energy via mma: S[g,q,l] = (Q·K^T) masked * 0.125. 128x128 tile,    */
/* single K=64 pass, bf16 3-split.                                     */
/* ================================================================== */
#define SMEM_ENERGY (4 * TILE_BYTES)

__global__ __launch_bounds__(256) void energy_mma_kernel(const int* __restrict__ mask)
{
    extern __shared__ char smem[];
    const uint32_t smem_base = smem_to_u32(smem);
    const int tid = threadIdx.x;
    const int wid = tid >> 5, lane = tid & 31;
    const int wm = wid & 1, wn = wid >> 1;

    const int g  = blockIdx.z;
    const int q0 = blockIdx.y * 128;
    const int l0 = blockIdx.x * 128;

    const uint32_t tQh = smem_base;
    const uint32_t tQl = smem_base + TILE_BYTES;
    const uint32_t tKh = smem_base + 2 * TILE_BYTES;
    const uint32_t tKl = smem_base + 3 * TILE_BYTES;

    const int lrow = tid >> 1;
    const int lhalf = (tid & 1) * 32;
    const __nv_bfloat16* qh = g_Qh + ((size_t)g * SEQ + q0 + lrow) * HD + lhalf;
    const __nv_bfloat16* ql = g_Ql + ((size_t)g * SEQ + q0 + lrow) * HD + lhalf;
    const __nv_bfloat16* kh = g_Kh + ((size_t)g * SEQ + l0 + lrow) * HD + lhalf;
    const __nv_bfloat16* kl = g_Kl + ((size_t)g * SEQ + l0 + lrow) * HD + lhalf;
#pragma unroll
    for (int gix = 0; gix < 4; gix++) {
        const uint32_t sw = SMEM_SWIZZLE_128B((uint32_t)(lrow * 128 + (lhalf + gix * 8) * 2));
        *(uint4*)(smem + 0 * TILE_BYTES + sw) = *(const uint4*)(qh + gix * 8);
        *(uint4*)(smem + 1 * TILE_BYTES + sw) = *(const uint4*)(ql + gix * 8);
        *(uint4*)(smem + 2 * TILE_BYTES + sw) = *(const uint4*)(kh + gix * 8);
        *(uint4*)(smem + 3 * TILE_BYTES + sw) = *(const uint4*)(kl + gix * 8);
    }
    __syncthreads();

    const int a_row = (lane & 15);
    const int a_c16 = (lane >> 4) * 16;
    const int b_row = (lane & 7) + ((lane >> 4) << 3);
    const int b_c16 = ((lane >> 3) & 1) * 16;

    float acc[4][4][4];
#pragma unroll
    for (int mf = 0; mf < 4; mf++)
#pragma unroll
        for (int nf = 0; nf < 4; nf++)
#pragma unroll
            for (int r = 0; r < 4; r++) acc[mf][nf][r] = 0.f;

#pragma unroll
    for (int ks = 0; ks < 4; ks++) {
        uint32_t ah[4][4], al[4][4];
#pragma unroll
        for (int mf = 0; mf < 4; mf++) {
            const uint32_t off = (uint32_t)((wm * 64 + mf * 16 + a_row) * 128
                                            + ks * 32 + a_c16);
            const uint32_t swo = SMEM_SWIZZLE_128B(off);
            ldsm4(ah[mf], tQh + swo);
            ldsm4(al[mf], tQl + swo);
        }
        uint32_t bh[8];
#pragma unroll
        for (int np = 0; np < 2; np++) {
            const uint32_t off = (uint32_t)((wn * 32 + np * 16 + b_row) * 128
                                            + ks * 32 + b_c16);
            ldsm4(&bh[np * 4], tKh + SMEM_SWIZZLE_128B(off));
        }
#pragma unroll
        for (int mf = 0; mf < 4; mf++)
#pragma unroll
            for (int nf = 0; nf < 4; nf++)
                mma16816(acc[mf][nf], ah[mf], &bh[nf * 2]);
#pragma unroll
        for (int mf = 0; mf < 4; mf++)
#pragma unroll
            for (int nf = 0; nf < 4; nf++)
                mma16816(acc[mf][nf], al[mf], &bh[nf * 2]);
        uint32_t bl[8];
#pragma unroll
        for (int np = 0; np < 2; np++) {
            const uint32_t off = (uint32_t)((wn * 32 + np * 16 + b_row) * 128
                                            + ks * 32 + b_c16);
            ldsm4(&bl[np * 4], tKl + SMEM_SWIZZLE_128B(off));
        }
#pragma unroll
        for (int mf = 0; mf < 4; mf++)
#pragma unroll
            for (int nf = 0; nf < 4; nf++)
                mma16816(acc[mf][nf], ah[mf], &bl[nf * 2]);
    }

    /* epilogue: mask + *0.125, store fp32 S directly from fragments */
    const int n = g >> 5;
    float* Sg = g_S + (size_t)g * SEQ * SEQ;
    const int* Mn = mask + (size_t)n * SEQ * SEQ;
    const int gr = lane >> 2, c2 = (lane & 3) * 2;
#pragma unroll
    for (int mf = 0; mf < 4; mf++) {
#pragma unroll
        for (int nf = 0; nf < 4; nf++) {
            const int col = l0 + wn * 32 + nf * 8 + c2;
#pragma unroll
            for (int half = 0; half < 2; half++) {
                const int q = q0 + wm * 64 + mf * 16 + gr + half * 8;
                const int2 mm = *(const int2*)(Mn + (size_t)q * SEQ + col);
                float2 r;
                r.x = ((mm.x == 0) ? -1e20f : acc[mf][nf][half * 2 + 0]) * 0.125f;
                r.y = ((mm.y == 0) ? -1e20f : acc[mf][nf][half * 2 + 1]) * 0.125f;
                *(float2*)(Sg + (size_t)q * SEQ + col) = r;
            }
        }
    }
}

/* ================================================================== */
/* Column softmax stats over the QUERY axis (one online pass)          */
/* ================================================================== */
__global__ __launch_bounds__(256) void colstat_kernel()
{
    const int g = blockIdx.y;
    const int l = blockIdx.x * 256 + threadIdx.x;
    const float* Sg = g_S + (size_t)g * SEQ * SEQ + l;

    float m = -3.4e38f, z = 0.f;
    for (int q = 0; q < SEQ; q += 4) {
        float x0 = Sg[(size_t)(q + 0) * SEQ];
        float x1 = Sg[(size_t)(q + 1) * SEQ];
        float x2 = Sg[(size_t)(q + 2) * SEQ];
        float x3 = Sg[(size_t)(q + 3) * SEQ];
#pragma unroll
        for (int u = 0; u < 4; u++) {
            float x = (u == 0) ? x0 : (u == 1) ? x1 : (u == 2) ? x2 : x3;
            if (x > m) { z = z * __expf(m - x) + 1.f; m = x; }
            else       { z += __expf(x - m); }
        }
    }
    g_M[g * SEQ + l]  = m;
    g_Zi[g * SEQ + l] = 1.f / z;
}

/* ================================================================== */
/* AV via mma: O[q][d] = E[q][l] V[l][d]; E = exp(S-m_l)*Zi_l split to */
/* bf16 hi/lo; V from transposed bf16 hi/lo tiles. 128q x 64d per CTA, */
/* 16 l-chunks of 64. Warps 4(m)x2(n), warp tile 32x32.                */
/* ================================================================== */
#define AV_E_BYTES 16384                 /* 128 x 128B */
#define AV_V_BYTES 8192                  /* 64 x 128B  */
#define SMEM_AV (2 * AV_E_BYTES + 2 * AV_V_BYTES)

__global__ __launch_bounds__(256) void av_mma_kernel()
{
    extern __shared__ char smem[];
    const uint32_t smem_base = smem_to_u32(smem);
    const int tid = threadIdx.x;
    const int wid = tid >> 5, lane = tid & 31;
    const int wm = wid >> 1, wn = wid & 1;

    const int g  = blockIdx.y;
    const int q0 = blockIdx.x * 128;

    const uint32_t tEh = smem_base;
    const uint32_t tEl = smem_base + AV_E_BYTES;
    const uint32_t tVh = smem_base + 2 * AV_E_BYTES;
    const uint32_t tVl = smem_base + 2 * AV_E_BYTES + AV_V_BYTES;

    const float* Sg = g_S + (size_t)g * SEQ * SEQ;
    const float* Mg = g_M + g * SEQ;
    const float* Zg = g_Zi + g * SEQ;

    /* E loader: thread covers (q = tid>>1, 32 l-values) */
    const int erow = tid >> 1;
    const int elhalf = (tid & 1) * 32;
    /* V loader: thread covers (d = tid>>2, 16 l-values) */
    const int vrow = tid >> 2;
    const int vq = (tid & 3) * 16;
    const __nv_bfloat16* vsrc_h = g_Vth + ((size_t)g * HD + vrow) * SEQ + vq;
    const __nv_bfloat16* vsrc_l = g_Vtl + ((size_t)g * HD + vrow) * SEQ + vq;

    const int a_row = (lane & 15);
    const int a_c16 = (lane >> 4) * 16;
    const int b_row = (lane & 7) + ((lane >> 4) << 3);
    const int b_c16 = ((lane >> 3) & 1) * 16;

    float acc[2][4][4];
#pragma unroll
    for (int mf = 0; mf < 2; mf++)
#pragma unroll
        for (int nf = 0; nf < 4; nf++)
#pragma unroll
            for (int r = 0; r < 4; r++) acc[mf][nf][r] = 0.f;

    for (int c = 0; c < 16; c++) {
        const int l0 = c * 64;
        /* E: load S, fold exp/normalize, split hi/lo */
        {
            const float* srow = Sg + (size_t)(q0 + erow) * SEQ + l0 + elhalf;
#pragma unroll
            for (int gix = 0; gix < 4; gix++) {
                float4 s0 = *(const float4*)(srow + gix * 8);
                float4 s1 = *(const float4*)(srow + gix * 8 + 4);
                float4 m0 = *(const float4*)(Mg + l0 + elhalf + gix * 8);
                float4 m1 = *(const float4*)(Mg + l0 + elhalf + gix * 8 + 4);
                float4 z0 = *(const float4*)(Zg + l0 + elhalf + gix * 8);
                float4 z1 = *(const float4*)(Zg + l0 + elhalf + gix * 8 + 4);
                float e[8];
                e[0] = __expf(s0.x - m0.x) * z0.x;
                e[1] = __expf(s0.y - m0.y) * z0.y;
                e[2] = __expf(s0.z - m0.z) * z0.z;
                e[3] = __expf(s0.w - m0.w) * z0.w;
                e[4] = __expf(s1.x - m1.x) * z1.x;
                e[5] = __expf(s1.y - m1.y) * z1.y;
                e[6] = __expf(s1.z - m1.z) * z1.z;
                e[7] = __expf(s1.w - m1.w) * z1.w;
                float hi[8], lo[8];
#pragma unroll
                for (int j = 0; j < 8; j++) splitf(e[j], hi[j], lo[j]);
                uint4 hv, lv;
                hv.x = packbf2(hi[0], hi[1]); hv.y = packbf2(hi[2], hi[3]);
                hv.z = packbf2(hi[4], hi[5]); hv.w = packbf2(hi[6], hi[7]);
                lv.x = packbf2(lo[0], lo[1]); lv.y = packbf2(lo[2], lo[3]);
                lv.z = packbf2(lo[4], lo[5]); lv.w = packbf2(lo[6], lo[7]);
                const uint32_t sw = SMEM_SWIZZLE_128B(
                    (uint32_t)(erow * 128 + (elhalf + gix * 8) * 2));
                *(uint4*)(smem + sw) = hv;                 /* tEh */
                *(uint4*)(smem + AV_E_BYTES + sw) = lv;    /* tEl */
            }
        }
        /* V tiles */
#pragma unroll
        for (int j = 0; j < 2; j++) {
            const uint32_t sw = SMEM_SWIZZLE_128B(
                (uint32_t)(vrow * 128 + (vq + j * 8) * 2));
            *(uint4*)(smem + 2 * AV_E_BYTES + sw) = *(const uint4*)(vsrc_h + l0 + j * 8);
            *(uint4*)(smem + 2 * AV_E_BYTES + AV_V_BYTES + sw) = *(const uint4*)(vsrc_l + l0 + j * 8);
        }
        __syncthreads();

#pragma unroll
        for (int ks = 0; ks < 4; ks++) {
            uint32_t ah[2][4], al[2][4];
#pragma unroll
            for (int mf = 0; mf < 2; mf++) {
                const uint32_t off = (uint32_t)((wm * 32 + mf * 16 + a_row) * 128
                                                + ks * 32 + a_c16);
                const uint32_t swo = SMEM_SWIZZLE_128B(off);
                ldsm4(ah[mf], tEh + swo);
                ldsm4(al[mf], tEl + swo);
            }
            uint32_t bh[8];
#pragma unroll
            for (int np = 0; np < 2; np++) {
                const uint32_t off = (uint32_t)((wn * 32 + np * 16 + b_row) * 128
                                                + ks * 32 + b_c16);
                ldsm4(&bh[np * 4], tVh + SMEM_SWIZZLE_128B(off));
            }
#pragma unroll
            for (int mf = 0; mf < 2; mf++)
#pragma unroll
                for (int nf = 0; nf < 4; nf++)
                    mma16816(acc[mf][nf], ah[mf], &bh[nf * 2]);
#pragma unroll
            for (int mf = 0; mf < 2; mf++)
#pragma unroll
                for (int nf = 0; nf < 4; nf++)
                    mma16816(acc[mf][nf], al[mf], &bh[nf * 2]);
            uint32_t bl[8];
#pragma unroll
            for (int np = 0; np < 2; np++) {
                const uint32_t off = (uint32_t)((wn * 32 + np * 16 + b_row) * 128
                                                + ks * 32 + b_c16);
                ldsm4(&bl[np * 4], tVl + SMEM_SWIZZLE_128B(off));
            }
#pragma unroll
            for (int mf = 0; mf < 2; mf++)
#pragma unroll
                for (int nf = 0; nf < 4; nf++)
                    mma16816(acc[mf][nf], ah[mf], &bl[nf * 2]);
        }
        __syncthreads();
    }

    /* epilogue: split O to bf16 hi/lo -> g_AOh/g_AOl */
    const int n = g >> 5, b = (g >> 3) & 3, hd = g & 7;
    const int gr = lane >> 2, c2 = (lane & 3) * 2;
#pragma unroll
    for (int mf = 0; mf < 2; mf++) {
#pragma unroll
        for (int nf = 0; nf < 4; nf++) {
            const int d = wn * 32 + nf * 8 + c2;
#pragma unroll
            for (int half = 0; half < 2; half++) {
                const int q = q0 + wm * 32 + mf * 16 + gr + half * 8;
                const size_t t = (size_t)(n * SEQ + q);
                const size_t off = t * EMBED + b * EBS + hd * HD + d;
                float h0, l0f, h1, l1;
                splitf(acc[mf][nf][half * 2 + 0], h0, l0f);
                splitf(acc[mf][nf][half * 2 + 1], h1, l1);
                *(uint32_t*)(g_AOh + off) = packbf2(h0, h1);
                *(uint32_t*)(g_AOl + off) = packbf2(l0f, l1);
            }
        }
    }
}

/* ------------------------------------------------------------------ */
extern "C" void kernel_launch(void* const* d_in, const int* in_sizes, int n_in,
                              void* d_out, int out_size)
{
    const float* values = (const float*)d_in[0];
    const float* keys   = (const float*)d_in[1];
    const float* query  = (const float*)d_in[2];
    const int*   mask   = (const int*)d_in[3];
    const float* Wv = (const float*)d_in[4];
    const float* bv = (const float*)d_in[5];
    const float* Wk = (const float*)d_in[6];
    const float* bk = (const float*)d_in[7];
    const float* Wq = (const float*)d_in[8];
    const float* bq = (const float*)d_in[9];
    const float* Wo = (const float*)d_in[10];
    const float* bo = (const float*)d_in[11];
    float* out = (float*)d_out;

    cudaFuncSetAttribute(mm_kernel<0>, cudaFuncAttributeMaxDynamicSharedMemorySize,
                         SMEM_GEMM_TOTAL);
    cudaFuncSetAttribute(mm_kernel<1>, cudaFuncAttributeMaxDynamicSharedMemorySize,
                         SMEM_GEMM_TOTAL);
    cudaFuncSetAttribute(energy_mma_kernel, cudaFuncAttributeMaxDynamicSharedMemorySize,
                         SMEM_ENERGY);
    cudaFuncSetAttribute(av_mma_kernel, cudaFuncAttributeMaxDynamicSharedMemorySize,
                         SMEM_AV);

    /* converts */
    dim3 gx((TTOK * EMBED) / (256 * 4), 3);
    convx_kernel<<<gx, 256>>>(values, keys, query);
    dim3 gw(EBS / 32, EBS / 32, 16);
    convw_kernel<<<gw, dim3(32, 8)>>>(Wv, Wk, Wq, Wo);

    /* fused qkv projections (tensor) */
    dim3 gqkv(EBS / 128, TTOK / 128, 12);
    mm_kernel<0><<<gqkv, 256, SMEM_GEMM_TOTAL>>>(bv, bk, bq, nullptr);

    /* energy (tensor) */
    dim3 ge(SEQ / 128, SEQ / 128, NG);
    energy_mma_kernel<<<ge, 256, SMEM_ENERGY>>>(mask);

    dim3 gc(SEQ / 256, NG);
    colstat_kernel<<<gc, 256>>>();

    /* AV (tensor) */
    dim3 ga(SEQ / 128, NG);
    av_mma_kernel<<<ga, 256, SMEM_AV>>>();

    /* output projection (tensor) */
    dim3 go(EBS / 128, TTOK / 128, NB);
    mm_kernel<1><<<go, 256, SMEM_GEMM_TOTAL>>>(bo, nullptr, nullptr, out);
}

// round 10
// speedup vs baseline: 2.5264x; 1.1720x over previous
#include <cuda_runtime.h>
#include <cuda_bf16.h>
#include <math.h>
#include <stdint.h>

#define NBATCH 4
#define SEQ    1024
#define EMBED  2048
#define EBS    512
#define NB     4
#define HEADS  8
#define HD     64
#define TTOK   (NBATCH * SEQ)        /* 4096 tokens */
#define NG     (NBATCH * NB * HEADS) /* 128 (n,b,h) heads */

typedef unsigned long long u64;

#define SMEM_SWIZZLE_128B(off) ((off) ^ (((off) >> 3) & 0x70))

/* ================================================================== */
/* Tensor helpers (sm_80 path: legal on base sm_103 target)            */
/* ================================================================== */
__device__ __forceinline__ uint32_t smem_to_u32(const void* p) {
    uint32_t a;
    asm("{ .reg .u64 t; cvta.to.shared.u64 t, %1; cvt.u32.u64 %0, t; }"
        : "=r"(a) : "l"(p));
    return a;
}
__device__ __forceinline__ void ldsm4(uint32_t* r, uint32_t addr) {
    asm volatile("ldmatrix.sync.aligned.m8n8.x4.shared.b16 {%0,%1,%2,%3}, [%4];"
                 : "=r"(r[0]), "=r"(r[1]), "=r"(r[2]), "=r"(r[3]) : "r"(addr));
}
__device__ __forceinline__ void mma16816(float* d, const uint32_t* a,
                                         const uint32_t* b) {
    asm volatile(
        "mma.sync.aligned.m16n8k16.row.col.f32.bf16.bf16.f32 "
        "{%0,%1,%2,%3}, {%4,%5,%6,%7}, {%8,%9}, {%0,%1,%2,%3};"
        : "+f"(d[0]), "+f"(d[1]), "+f"(d[2]), "+f"(d[3])
        : "r"(a[0]), "r"(a[1]), "r"(a[2]), "r"(a[3]), "r"(b[0]), "r"(b[1]));
}
__device__ __forceinline__ uint32_t packbf2(float a, float b) {
    __nv_bfloat162 p = __floats2bfloat162_rn(a, b);
    return *(uint32_t*)&p;
}
__device__ __forceinline__ void splitf(float v, float& hi, float& lo) {
    __nv_bfloat16 hb = __float2bfloat16_rn(v);
    hi = __bfloat162float(hb);
    lo = v - hi;
}

/* ================================================================== */
/* Device scratch                                                      */
/* ================================================================== */
__device__ __align__(256) float g_E[(size_t)NG * SEQ * SEQ];  /* 512 MB: exp(S) */
__device__ __align__(256) float g_Zp[16][NG * SEQ];           /* col-sum partials */
__device__ float g_Zi[NG * SEQ];                              /* 1/Z per column   */
__device__ __align__(256) __nv_bfloat16 g_Xh[(size_t)3 * TTOK * EMBED];
__device__ __align__(256) __nv_bfloat16 g_Xl[(size_t)3 * TTOK * EMBED];
__device__ __align__(256) __nv_bfloat16 g_AOh[(size_t)TTOK * EMBED];
__device__ __align__(256) __nv_bfloat16 g_AOl[(size_t)TTOK * EMBED];
__device__ __align__(256) __nv_bfloat16 g_Wh[(size_t)4 * NB * EBS * EBS]; /* [wi][b][o][i] */
__device__ __align__(256) __nv_bfloat16 g_Wl[(size_t)4 * NB * EBS * EBS];
__device__ __align__(256) __nv_bfloat16 g_Qh[(size_t)NG * SEQ * HD]; /* [g][s][d] */
__device__ __align__(256) __nv_bfloat16 g_Ql[(size_t)NG * SEQ * HD];
__device__ __align__(256) __nv_bfloat16 g_Kh[(size_t)NG * SEQ * HD];
__device__ __align__(256) __nv_bfloat16 g_Kl[(size_t)NG * SEQ * HD];
__device__ __align__(256) __nv_bfloat16 g_Vth[(size_t)NG * HD * SEQ]; /* [g][d][s] */
__device__ __align__(256) __nv_bfloat16 g_Vtl[(size_t)NG * HD * SEQ];

/* ================================================================== */
/* Converters                                                          */
/* ================================================================== */
__global__ __launch_bounds__(256) void convx_kernel(
    const float* __restrict__ V, const float* __restrict__ K,
    const float* __restrict__ Q)
{
    const int p = blockIdx.y;
    const float* src = (p == 0) ? V : (p == 1) ? K : Q;
    __nv_bfloat16* dh = g_Xh + (size_t)p * TTOK * EMBED;
    __nv_bfloat16* dl = g_Xl + (size_t)p * TTOK * EMBED;
    const size_t i = ((size_t)blockIdx.x * 256 + threadIdx.x) * 4;
    float4 v = *(const float4*)(src + i);
    float f[4] = {v.x, v.y, v.z, v.w};
    float hi[4], lo[4];
#pragma unroll
    for (int j = 0; j < 4; j++) splitf(f[j], hi[j], lo[j]);
    uint2 hv, lv;
    hv.x = packbf2(hi[0], hi[1]); hv.y = packbf2(hi[2], hi[3]);
    lv.x = packbf2(lo[0], lo[1]); lv.y = packbf2(lo[2], lo[3]);
    *(uint2*)(dh + i) = hv;
    *(uint2*)(dl + i) = lv;
}

/* transpose + split weights: W[wi][b][i][o] -> g_Wh/l [wi][b][o][i] */
__global__ __launch_bounds__(256) void convw_kernel(
    const float* __restrict__ Wv, const float* __restrict__ Wk,
    const float* __restrict__ Wq, const float* __restrict__ Wo)
{
    __shared__ float st[32][33];
    const int z = blockIdx.z;
    const int wi = z >> 2, b = z & 3;
    const float* W = ((wi == 0) ? Wv : (wi == 1) ? Wk : (wi == 2) ? Wq : Wo)
                     + (size_t)b * EBS * EBS;
    const int i0 = blockIdx.y * 32, o0 = blockIdx.x * 32;
    const int tx = threadIdx.x, ty = threadIdx.y;
#pragma unroll
    for (int kk = 0; kk < 4; kk++)
        st[ty + 8 * kk][tx] = W[(size_t)(i0 + ty + 8 * kk) * EBS + o0 + tx];
    __syncthreads();
    __nv_bfloat16* oh = g_Wh + (size_t)(wi * NB + b) * EBS * EBS;
    __nv_bfloat16* ol = g_Wl + (size_t)(wi * NB + b) * EBS * EBS;
#pragma unroll
    for (int kk = 0; kk < 4; kk++) {
        const float v = st[tx][ty + 8 * kk];
        float h, l;
        splitf(v, h, l);
        const size_t off = (size_t)(o0 + ty + 8 * kk) * EBS + i0 + tx;
        oh[off] = __float2bfloat16_rn(h);
        ol[off] = __float2bfloat16_rn(l);
    }
}

/* ================================================================== */
/* mma.sync bf16 3-split projection GEMM. 128x128 CTA tile, K=512 in   */
/* 8 chunks of 64. Warps 2(m)x4(n); warp tile 64x32.                   */
/* ================================================================== */
#define KCHUNK 64
#define NCHUNKS 8
#define TILE_BYTES 16384                  /* 128 rows x 128B */
#define SS 132                            /* staging stride (floats) */
#define SMEM_GEMM_TOTAL (128 * SS * 4)    /* 67584B >= 4*TILE_BYTES  */

template <int MODE>
__global__ __launch_bounds__(256) void mm_kernel(
    const float* __restrict__ bias0, const float* __restrict__ bias1,
    const float* __restrict__ bias2, float* __restrict__ oout)
{
    extern __shared__ char smem[];
    const uint32_t smem_base = smem_to_u32(smem);
    const int tid = threadIdx.x;
    const int wid = tid >> 5, lane = tid & 31;
    const int wm = wid & 1, wn = wid >> 1;

    int p, b;
    const __nv_bfloat16 *Ah, *Al;
    const float* bias;
    if (MODE == 0) {
        p = blockIdx.z >> 2; b = blockIdx.z & 3;
        Ah = g_Xh + (size_t)p * TTOK * EMBED;
        Al = g_Xl + (size_t)p * TTOK * EMBED;
        bias = (p == 0) ? bias0 : (p == 1) ? bias1 : bias2;
    } else {
        p = 3; b = blockIdx.z;
        Ah = g_AOh; Al = g_AOl;
        bias = bias0;
    }
    const __nv_bfloat16* Bh = g_Wh + (size_t)(p * NB + b) * EBS * EBS;
    const __nv_bfloat16* Bl = g_Wl + (size_t)(p * NB + b) * EBS * EBS;
    const int m0 = blockIdx.y * 128, n0 = blockIdx.x * 128;

    const uint32_t tAh = smem_base;
    const uint32_t tAl = smem_base + TILE_BYTES;
    const uint32_t tBh = smem_base + 2 * TILE_BYTES;
    const uint32_t tBl = smem_base + 3 * TILE_BYTES;

    const int lrow = tid >> 1;
    const int lhalf = (tid & 1) * 32;
    const __nv_bfloat16* Arow_h = Ah + (size_t)(m0 + lrow) * EMBED + b * EBS + lhalf;
    const __nv_bfloat16* Arow_l = Al + (size_t)(m0 + lrow) * EMBED + b * EBS + lhalf;
    const __nv_bfloat16* Brow_h = Bh + (size_t)(n0 + lrow) * EBS + lhalf;
    const __nv_bfloat16* Brow_l = Bl + (size_t)(n0 + lrow) * EBS + lhalf;
    uint32_t sw[4];
#pragma unroll
    for (int gix = 0; gix < 4; gix++)
        sw[gix] = SMEM_SWIZZLE_128B((uint32_t)(lrow * 128 + (lhalf + gix * 8) * 2));

    const int a_row = (lane & 15);
    const int a_c16 = (lane >> 4) * 16;
    const int b_row = (lane & 7) + ((lane >> 4) << 3);
    const int b_c16 = ((lane >> 3) & 1) * 16;

    float acc[4][4][4];
#pragma unroll
    for (int mf = 0; mf < 4; mf++)
#pragma unroll
        for (int nf = 0; nf < 4; nf++)
#pragma unroll
            for (int r = 0; r < 4; r++) acc[mf][nf][r] = 0.f;

    for (int c = 0; c < NCHUNKS; c++) {
        const int coff = c * KCHUNK;
#pragma unroll
        for (int gix = 0; gix < 4; gix++) {
            uint4 vah = *(const uint4*)(Arow_h + coff + gix * 8);
            uint4 val = *(const uint4*)(Arow_l + coff + gix * 8);
            uint4 vbh = *(const uint4*)(Brow_h + coff + gix * 8);
            uint4 vbl = *(const uint4*)(Brow_l + coff + gix * 8);
            *(uint4*)(smem + 0 * TILE_BYTES + sw[gix]) = vah;
            *(uint4*)(smem + 1 * TILE_BYTES + sw[gix]) = val;
            *(uint4*)(smem + 2 * TILE_BYTES + sw[gix]) = vbh;
            *(uint4*)(smem + 3 * TILE_BYTES + sw[gix]) = vbl;
        }
        __syncthreads();

#pragma unroll
        for (int ks = 0; ks < 4; ks++) {
            uint32_t ah[4][4], al[4][4];
#pragma unroll
            for (int mf = 0; mf < 4; mf++) {
                const uint32_t off = (uint32_t)((wm * 64 + mf * 16 + a_row) * 128
                                                + ks * 32 + a_c16);
                const uint32_t swo = SMEM_SWIZZLE_128B(off);
                ldsm4(ah[mf], tAh + swo);
                ldsm4(al[mf], tAl + swo);
            }
            uint32_t bh[8];
#pragma unroll
            for (int np = 0; np < 2; np++) {
                const uint32_t off = (uint32_t)((wn * 32 + np * 16 + b_row) * 128
                                                + ks * 32 + b_c16);
                ldsm4(&bh[np * 4], tBh + SMEM_SWIZZLE_128B(off));
            }
#pragma unroll
            for (int mf = 0; mf < 4; mf++)
#pragma unroll
                for (int nf = 0; nf < 4; nf++)
                    mma16816(acc[mf][nf], ah[mf], &bh[nf * 2]);
#pragma unroll
            for (int mf = 0; mf < 4; mf++)
#pragma unroll
                for (int nf = 0; nf < 4; nf++)
                    mma16816(acc[mf][nf], al[mf], &bh[nf * 2]);
            uint32_t bl[8];
#pragma unroll
            for (int np = 0; np < 2; np++) {
                const uint32_t off = (uint32_t)((wn * 32 + np * 16 + b_row) * 128
                                                + ks * 32 + b_c16);
                ldsm4(&bl[np * 4], tBl + SMEM_SWIZZLE_128B(off));
            }
#pragma unroll
            for (int mf = 0; mf < 4; mf++)
#pragma unroll
                for (int nf = 0; nf < 4; nf++)
                    mma16816(acc[mf][nf], ah[mf], &bl[nf * 2]);
        }
        __syncthreads();
    }

    /* stage accumulators to smem */
    float* stg = (float*)smem;  /* [128][SS] */
    const int gr = lane >> 2, c2 = (lane & 3) * 2;
#pragma unroll
    for (int mf = 0; mf < 4; mf++) {
        const int row0 = wm * 64 + mf * 16 + gr;
#pragma unroll
        for (int nf = 0; nf < 4; nf++) {
            const int col = wn * 32 + nf * 8 + c2;
            *(float2*)&stg[row0 * SS + col]       = make_float2(acc[mf][nf][0], acc[mf][nf][1]);
            *(float2*)&stg[(row0 + 8) * SS + col] = make_float2(acc[mf][nf][2], acc[mf][nf][3]);
        }
    }
    __syncthreads();

    if (MODE == 0) {
        const int n = m0 >> 10, s0 = m0 & (SEQ - 1);
        const int h0 = n0 >> 6;
        if (p >= 1) {
            /* Q or K: bf16 hi/lo head-major [g][s][d] */
            __nv_bfloat16* oh = (p == 1) ? g_Kh : g_Qh;
            __nv_bfloat16* ol = (p == 1) ? g_Kl : g_Ql;
#pragma unroll
            for (int it = 0; it < 16; it++) {
                const int flat = tid + it * 256;
                const int srow = flat >> 5;
                const int rem = flat & 31;
                const int hh = rem >> 4, dq = (rem & 15) * 4;
                const int ocol = hh * 64 + dq;
                float hi[4], lo[4];
#pragma unroll
                for (int j = 0; j < 4; j++) {
                    const float v = stg[srow * SS + ocol + j]
                                    + bias[b * EBS + n0 + ocol + j];
                    splitf(v, hi[j], lo[j]);
                }
                uint2 hv, lv;
                hv.x = packbf2(hi[0], hi[1]); hv.y = packbf2(hi[2], hi[3]);
                lv.x = packbf2(lo[0], lo[1]); lv.y = packbf2(lo[2], lo[3]);
                const size_t gidx = (size_t)((n * NB + b) * HEADS + h0 + hh);
                const size_t off = (gidx * SEQ + s0 + srow) * HD + dq;
                *(uint2*)(oh + off) = hv;
                *(uint2*)(ol + off) = lv;
            }
        } else {
            /* V: bf16 hi/lo transposed [g][d][s] */
            const int dcol = tid >> 1;
            const int shalf = (tid & 1) * 64;
            const int hh = dcol >> 6, dl = dcol & 63;
            const size_t gidx = (size_t)((n * NB + b) * HEADS + h0 + hh);
            const float bb = bias[b * EBS + n0 + dcol];
            __nv_bfloat16* oh = g_Vth + (gidx * HD + dl) * SEQ + s0 + shalf;
            __nv_bfloat16* ol = g_Vtl + (gidx * HD + dl) * SEQ + s0 + shalf;
#pragma unroll
            for (int blk = 0; blk < 16; blk++) {
                float hi[4], lo[4];
#pragma unroll
                for (int j = 0; j < 4; j++) {
                    const float v = stg[(shalf + blk * 4 + j) * SS + dcol] + bb;
                    splitf(v, hi[j], lo[j]);
                }
                uint2 hv, lv;
                hv.x = packbf2(hi[0], hi[1]); hv.y = packbf2(hi[2], hi[3]);
                lv.x = packbf2(lo[0], lo[1]); lv.y = packbf2(lo[2], lo[3]);
                *(uint2*)(oh + blk * 4) = hv;
                *(uint2*)(ol + blk * 4) = lv;
            }
        }
    } else {
#pragma unroll
        for (int it = 0; it < 16; it++) {
            const int flat = tid + it * 256;
            const int srow = flat >> 5;
            const int oq = (flat & 31) * 4;
            float4 v;
            v.x = stg[srow * SS + oq + 0] + bias[b * EBS + n0 + oq + 0];
            v.y = stg[srow * SS + oq + 1] + bias[b * EBS + n0 + oq + 1];
            v.z = stg[srow * SS + oq + 2] + bias[b * EBS + n0 + oq + 2];
            v.w = stg[srow * SS + oq + 3] + bias[b * EBS + n0 + oq + 3];
            *(float4*)(oout + (size_t)(m0 + srow) * EMBED + b * EBS + n0 + oq) = v;
        }
    }
}

/* ================================================================== */
/* Energy via mma + fused exp + column partial sums.                   */
/* E[g,q,l] = exp((Q·K^T masked) * 0.125); per-column partial sums     */
/* written to g_Zp[qtile*2+wm] (deterministic, no atomics).            */
/* ================================================================== */
#define SMEM_ENERGY (4 * TILE_BYTES)

__global__ __launch_bounds__(256, 2) void energy_mma_kernel(const int* __restrict__ mask)
{
    extern __shared__ char smem[];
    const uint32_t smem_base = smem_to_u32(smem);
    const int tid = threadIdx.x;
    const int wid = tid >> 5, lane = tid & 31;
    const int wm = wid & 1, wn = wid >> 1;

    const int g  = blockIdx.z;
    const int q0 = blockIdx.y * 128;
    const int l0 = blockIdx.x * 128;

    const uint32_t tQh = smem_base;
    const uint32_t tQl = smem_base + TILE_BYTES;
    const uint32_t tKh = smem_base + 2 * TILE_BYTES;
    const uint32_t tKl = smem_base + 3 * TILE_BYTES;

    const int lrow = tid >> 1;
    const int lhalf = (tid & 1) * 32;
    const __nv_bfloat16* qh = g_Qh + ((size_t)g * SEQ + q0 + lrow) * HD + lhalf;
    const __nv_bfloat16* ql = g_Ql + ((size_t)g * SEQ + q0 + lrow) * HD + lhalf;
    const __nv_bfloat16* kh = g_Kh + ((size_t)g * SEQ + l0 + lrow) * HD + lhalf;
    const __nv_bfloat16* kl = g_Kl + ((size_t)g * SEQ + l0 + lrow) * HD + lhalf;
#pragma unroll
    for (int gix = 0; gix < 4; gix++) {
        const uint32_t sw = SMEM_SWIZZLE_128B((uint32_t)(lrow * 128 + (lhalf + gix * 8) * 2));
        *(uint4*)(smem + 0 * TILE_BYTES + sw) = *(const uint4*)(qh + gix * 8);
        *(uint4*)(smem + 1 * TILE_BYTES + sw) = *(const uint4*)(ql + gix * 8);
        *(uint4*)(smem + 2 * TILE_BYTES + sw) = *(const uint4*)(kh + gix * 8);
        *(uint4*)(smem + 3 * TILE_BYTES + sw) = *(const uint4*)(kl + gix * 8);
    }
    __syncthreads();

    const int a_row = (lane & 15);
    const int a_c16 = (lane >> 4) * 16;
    const int b_row = (lane & 7) + ((lane >> 4) << 3);
    const int b_c16 = ((lane >> 3) & 1) * 16;

    float acc[4][4][4];
#pragma unroll
    for (int mf = 0; mf < 4; mf++)
#pragma unroll
        for (int nf = 0; nf < 4; nf++)
#pragma unroll
            for (int r = 0; r < 4; r++) acc[mf][nf][r] = 0.f;

#pragma unroll
    for (int ks = 0; ks < 4; ks++) {
        uint32_t ah[4][4], al[4][4];
#pragma unroll
        for (int mf = 0; mf < 4; mf++) {
            const uint32_t off = (uint32_t)((wm * 64 + mf * 16 + a_row) * 128
                                            + ks * 32 + a_c16);
            const uint32_t swo = SMEM_SWIZZLE_128B(off);
            ldsm4(ah[mf], tQh + swo);
            ldsm4(al[mf], tQl + swo);
        }
        uint32_t bh[8];
#pragma unroll
        for (int np = 0; np < 2; np++) {
            const uint32_t off = (uint32_t)((wn * 32 + np * 16 + b_row) * 128
                                            + ks * 32 + b_c16);
            ldsm4(&bh[np * 4], tKh + SMEM_SWIZZLE_128B(off));
        }
#pragma unroll
        for (int mf = 0; mf < 4; mf++)
#pragma unroll
            for (int nf = 0; nf < 4; nf++)
                mma16816(acc[mf][nf], ah[mf], &bh[nf * 2]);
#pragma unroll
        for (int mf = 0; mf < 4; mf++)
#pragma unroll
            for (int nf = 0; nf < 4; nf++)
                mma16816(acc[mf][nf], al[mf], &bh[nf * 2]);
        uint32_t bl[8];
#pragma unroll
        for (int np = 0; np < 2; np++) {
            const uint32_t off = (uint32_t)((wn * 32 + np * 16 + b_row) * 128
                                            + ks * 32 + b_c16);
            ldsm4(&bl[np * 4], tKl + SMEM_SWIZZLE_128B(off));
        }
#pragma unroll
        for (int mf = 0; mf < 4; mf++)
#pragma unroll
            for (int nf = 0; nf < 4; nf++)
                mma16816(acc[mf][nf], ah[mf], &bl[nf * 2]);
    }

    /* epilogue: E = exp(masked * 0.125); column partial sums */
    const int n = g >> 5;
    float* Eg = g_E + (size_t)g * SEQ * SEQ;
    const int* Mn = mask + (size_t)n * SEQ * SEQ;
    const int gr = lane >> 2, c2 = (lane & 3) * 2;

    float csum[4][2];
#pragma unroll
    for (int nf = 0; nf < 4; nf++) { csum[nf][0] = 0.f; csum[nf][1] = 0.f; }

#pragma unroll
    for (int mf = 0; mf < 4; mf++) {
#pragma unroll
        for (int nf = 0; nf < 4; nf++) {
            const int col = l0 + wn * 32 + nf * 8 + c2;
#pragma unroll
            for (int half = 0; half < 2; half++) {
                const int q = q0 + wm * 64 + mf * 16 + gr + half * 8;
                const int2 mm = *(const int2*)(Mn + (size_t)q * SEQ + col);
                float2 e;
                e.x = (mm.x == 0) ? 0.f : __expf(acc[mf][nf][half * 2 + 0] * 0.125f);
                e.y = (mm.y == 0) ? 0.f : __expf(acc[mf][nf][half * 2 + 1] * 0.125f);
                *(float2*)(Eg + (size_t)q * SEQ + col) = e;
                csum[nf][0] += e.x;
                csum[nf][1] += e.y;
            }
        }
    }
    /* reduce over the 8 gr-lanes (bits 2..4 of lane) */
    float* Zp = g_Zp[blockIdx.y * 2 + wm] + g * SEQ;
#pragma unroll
    for (int nf = 0; nf < 4; nf++) {
#pragma unroll
        for (int cc = 0; cc < 2; cc++) {
            float v = csum[nf][cc];
            v += __shfl_xor_sync(0xffffffffu, v, 4);
            v += __shfl_xor_sync(0xffffffffu, v, 8);
            v += __shfl_xor_sync(0xffffffffu, v, 16);
            if (gr == 0)
                Zp[l0 + wn * 32 + nf * 8 + c2 + cc] = v;
        }
    }
}

/* ================================================================== */
/* Reduce 16 column-sum partials -> Zi = 1/Z                           */
/* ================================================================== */
__global__ __launch_bounds__(256) void zred_kernel()
{
    const int i = blockIdx.x * 256 + threadIdx.x;
    float z = 0.f;
#pragma unroll
    for (int s = 0; s < 16; s++)
        z += g_Zp[s][i];
    g_Zi[i] = (z > 0.f) ? (1.f / z) : 0.f;
}

/* ================================================================== */
/* AV via mma: O[q][d] = (E * Zi)[q][l] V[l][d]; E already exp'd.      */
/* 128q x 64d per CTA, 16 l-chunks of 64. Warps 4(m)x2(n).             */
/* ================================================================== */
#define AV_E_BYTES 16384                 /* 128 x 128B */
#define AV_V_BYTES 8192                  /* 64 x 128B  */
#define SMEM_AV (2 * AV_E_BYTES + 2 * AV_V_BYTES)

__global__ __launch_bounds__(256, 2) void av_mma_kernel()
{
    extern __shared__ char smem[];
    const uint32_t smem_base = smem_to_u32(smem);
    const int tid = threadIdx.x;
    const int wid = tid >> 5, lane = tid & 31;
    const int wm = wid >> 1, wn = wid & 1;

    const int g  = blockIdx.y;
    const int q0 = blockIdx.x * 128;

    const uint32_t tEh = smem_base;
    const uint32_t tEl = smem_base + AV_E_BYTES;
    const uint32_t tVh = smem_base + 2 * AV_E_BYTES;
    const uint32_t tVl = smem_base + 2 * AV_E_BYTES + AV_V_BYTES;

    const float* Eg = g_E + (size_t)g * SEQ * SEQ;
    const float* Rg = g_Zi + g * SEQ;

    const int erow = tid >> 1;
    const int elhalf = (tid & 1) * 32;
    const int vrow = tid >> 2;
    const int vq = (tid & 3) * 16;
    const __nv_bfloat16* vsrc_h = g_Vth + ((size_t)g * HD + vrow) * SEQ + vq;
    const __nv_bfloat16* vsrc_l = g_Vtl + ((size_t)g * HD + vrow) * SEQ + vq;

    const int a_row = (lane & 15);
    const int a_c16 = (lane >> 4) * 16;
    const int b_row = (lane & 7) + ((lane >> 4) << 3);
    const int b_c16 = ((lane >> 3) & 1) * 16;

    float acc[2][4][4];
#pragma unroll
    for (int mf = 0; mf < 2; mf++)
#pragma unroll
        for (int nf = 0; nf < 4; nf++)
#pragma unroll
            for (int r = 0; r < 4; r++) acc[mf][nf][r] = 0.f;

    for (int c = 0; c < 16; c++) {
        const int l0 = c * 64;
        /* E: load exp'd values, scale by 1/Z, split hi/lo */
        {
            const float* srow = Eg + (size_t)(q0 + erow) * SEQ + l0 + elhalf;
#pragma unroll
            for (int gix = 0; gix < 4; gix++) {
                float4 s0 = *(const float4*)(srow + gix * 8);
                float4 s1 = *(const float4*)(srow + gix * 8 + 4);
                float4 r0 = *(const float4*)(Rg + l0 + elhalf + gix * 8);
                float4 r1 = *(const float4*)(Rg + l0 + elhalf + gix * 8 + 4);
                float e[8];
                e[0] = s0.x * r0.x; e[1] = s0.y * r0.y;
                e[2] = s0.z * r0.z; e[3] = s0.w * r0.w;
                e[4] = s1.x * r1.x; e[5] = s1.y * r1.y;
                e[6] = s1.z * r1.z; e[7] = s1.w * r1.w;
                float hi[8], lo[8];
#pragma unroll
                for (int j = 0; j < 8; j++) splitf(e[j], hi[j], lo[j]);
                uint4 hv, lv;
                hv.x = packbf2(hi[0], hi[1]); hv.y = packbf2(hi[2], hi[3]);
                hv.z = packbf2(hi[4], hi[5]); hv.w = packbf2(hi[6], hi[7]);
                lv.x = packbf2(lo[0], lo[1]); lv.y = packbf2(lo[2], lo[3]);
                lv.z = packbf2(lo[4], lo[5]); lv.w = packbf2(lo[6], lo[7]);
                const uint32_t sw = SMEM_SWIZZLE_128B(
                    (uint32_t)(erow * 128 + (elhalf + gix * 8) * 2));
                *(uint4*)(smem + sw) = hv;
                *(uint4*)(smem + AV_E_BYTES + sw) = lv;
            }
        }
#pragma unroll
        for (int j = 0; j < 2; j++) {
            const uint32_t sw = SMEM_SWIZZLE_128B(
                (uint32_t)(vrow * 128 + (vq + j * 8) * 2));
            *(uint4*)(smem + 2 * AV_E_BYTES + sw) = *(const uint4*)(vsrc_h + l0 + j * 8);
            *(uint4*)(smem + 2 * AV_E_BYTES + AV_V_BYTES + sw) = *(const uint4*)(vsrc_l + l0 + j * 8);
        }
        __syncthreads();

#pragma unroll
        for (int ks = 0; ks < 4; ks++) {
            uint32_t ah[2][4], al[2][4];
#pragma unroll
            for (int mf = 0; mf < 2; mf++) {
                const uint32_t off = (uint32_t)((wm * 32 + mf * 16 + a_row) * 128
                                                + ks * 32 + a_c16);
                const uint32_t swo = SMEM_SWIZZLE_128B(off);
                ldsm4(ah[mf], tEh + swo);
                ldsm4(al[mf], tEl + swo);
            }
            uint32_t bh[8];
#pragma unroll
            for (int np = 0; np < 2; np++) {
                const uint32_t off = (uint32_t)((wn * 32 + np * 16 + b_row) * 128
                                                + ks * 32 + b_c16);
                ldsm4(&bh[np * 4], tVh + SMEM_SWIZZLE_128B(off));
            }
#pragma unroll
            for (int mf = 0; mf < 2; mf++)
#pragma unroll
                for (int nf = 0; nf < 4; nf++)
                    mma16816(acc[mf][nf], ah[mf], &bh[nf * 2]);
#pragma unroll
            for (int mf = 0; mf < 2; mf++)
#pragma unroll
                for (int nf = 0; nf < 4; nf++)
                    mma16816(acc[mf][nf], al[mf], &bh[nf * 2]);
            uint32_t bl[8];
#pragma unroll
            for (int np = 0; np < 2; np++) {
                const uint32_t off = (uint32_t)((wn * 32 + np * 16 + b_row) * 128
                                                + ks * 32 + b_c16);
                ldsm4(&bl[np * 4], tVl + SMEM_SWIZZLE_128B(off));
            }
#pragma unroll
            for (int mf = 0; mf < 2; mf++)
#pragma unroll
                for (int nf = 0; nf < 4; nf++)
                    mma16816(acc[mf][nf], ah[mf], &bl[nf * 2]);
        }
        __syncthreads();
    }

    /* epilogue: split O to bf16 hi/lo -> g_AOh/g_AOl */
    const int n = g >> 5, b = (g >> 3) & 3, hd = g & 7;
    const int gr = lane >> 2, c2 = (lane & 3) * 2;
#pragma unroll
    for (int mf = 0; mf < 2; mf++) {
#pragma unroll
        for (int nf = 0; nf < 4; nf++) {
            const int d = wn * 32 + nf * 8 + c2;
#pragma unroll
            for (int half = 0; half < 2; half++) {
                const int q = q0 + wm * 32 + mf * 16 + gr + half * 8;
                const size_t t = (size_t)(n * SEQ + q);
                const size_t off = t * EMBED + b * EBS + hd * HD + d;
                float h0, l0f, h1, l1;
                splitf(acc[mf][nf][half * 2 + 0], h0, l0f);
                splitf(acc[mf][nf][half * 2 + 1], h1, l1);
                *(uint32_t*)(g_AOh + off) = packbf2(h0, h1);
                *(uint32_t*)(g_AOl + off) = packbf2(l0f, l1);
            }
        }
    }
}

/* ------------------------------------------------------------------ */
extern "C" void kernel_launch(void* const* d_in, const int* in_sizes, int n_in,
                              void* d_out, int out_size)
{
    const float* values = (const float*)d_in[0];
    const float* keys   = (const float*)d_in[1];
    const float* query  = (const float*)d_in[2];
    const int*   mask   = (const int*)d_in[3];
    const float* Wv = (const float*)d_in[4];
    const float* bv = (const float*)d_in[5];
    const float* Wk = (const float*)d_in[6];
    const float* bk = (const float*)d_in[7];
    const float* Wq = (const float*)d_in[8];
    const float* bq = (const float*)d_in[9];
    const float* Wo = (const float*)d_in[10];
    const float* bo = (const float*)d_in[11];
    float* out = (float*)d_out;

    cudaFuncSetAttribute(mm_kernel<0>, cudaFuncAttributeMaxDynamicSharedMemorySize,
                         SMEM_GEMM_TOTAL);
    cudaFuncSetAttribute(mm_kernel<1>, cudaFuncAttributeMaxDynamicSharedMemorySize,
                         SMEM_GEMM_TOTAL);
    cudaFuncSetAttribute(energy_mma_kernel, cudaFuncAttributeMaxDynamicSharedMemorySize,
                         SMEM_ENERGY);
    cudaFuncSetAttribute(av_mma_kernel, cudaFuncAttributeMaxDynamicSharedMemorySize,
                         SMEM_AV);

    /* converts */
    dim3 gx((TTOK * EMBED) / (256 * 4), 3);
    convx_kernel<<<gx, 256>>>(values, keys, query);
    dim3 gw(EBS / 32, EBS / 32, 16);
    convw_kernel<<<gw, dim3(32, 8)>>>(Wv, Wk, Wq, Wo);

    /* fused qkv projections (tensor) */
    dim3 gqkv(EBS / 128, TTOK / 128, 12);
    mm_kernel<0><<<gqkv, 256, SMEM_GEMM_TOTAL>>>(bv, bk, bq, nullptr);

    /* energy + exp + column partial sums (tensor) */
    dim3 ge(SEQ / 128, SEQ / 128, NG);
    energy_mma_kernel<<<ge, 256, SMEM_ENERGY>>>(mask);

    /* reduce partials -> 1/Z */
    zred_kernel<<<(NG * SEQ) / 256, 256>>>();

    /* AV (tensor) */
    dim3 ga(SEQ / 128, NG);
    av_mma_kernel<<<ga, 256, SMEM_AV>>>();

    /* output projection (tensor) */
    dim3 go(EBS / 128, TTOK / 128, NB);
    mm_kernel<1><<<go, 256, SMEM_GEMM_TOTAL>>>(bo, nullptr, nullptr, out);
}

// round 11
// speedup vs baseline: 2.7776x; 1.0994x over previous
#include <cuda_runtime.h>
#include <cuda_bf16.h>
#include <math.h>
#include <stdint.h>

#define NBATCH 4
#define SEQ    1024
#define EMBED  2048
#define EBS    512
#define NB     4
#define HEADS  8
#define HD     64
#define TTOK   (NBATCH * SEQ)        /* 4096 tokens */
#define NG     (NBATCH * NB * HEADS) /* 128 (n,b,h) heads */

typedef unsigned long long u64;

#define SMEM_SWIZZLE_128B(off) ((off) ^ (((off) >> 3) & 0x70))

/* ================================================================== */
/* Tensor / async helpers (sm_80 path: legal on base sm_103 target)    */
/* ================================================================== */
__device__ __forceinline__ uint32_t smem_to_u32(const void* p) {
    uint32_t a;
    asm("{ .reg .u64 t; cvta.to.shared.u64 t, %1; cvt.u32.u64 %0, t; }"
        : "=r"(a) : "l"(p));
    return a;
}
__device__ __forceinline__ void ldsm4(uint32_t* r, uint32_t addr) {
    asm volatile("ldmatrix.sync.aligned.m8n8.x4.shared.b16 {%0,%1,%2,%3}, [%4];"
                 : "=r"(r[0]), "=r"(r[1]), "=r"(r[2]), "=r"(r[3]) : "r"(addr));
}
__device__ __forceinline__ void mma16816(float* d, const uint32_t* a,
                                         const uint32_t* b) {
    asm volatile(
        "mma.sync.aligned.m16n8k16.row.col.f32.bf16.bf16.f32 "
        "{%0,%1,%2,%3}, {%4,%5,%6,%7}, {%8,%9}, {%0,%1,%2,%3};"
        : "+f"(d[0]), "+f"(d[1]), "+f"(d[2]), "+f"(d[3])
        : "r"(a[0]), "r"(a[1]), "r"(a[2]), "r"(a[3]), "r"(b[0]), "r"(b[1]));
}
__device__ __forceinline__ void cpa16(uint32_t dst, const void* src) {
    asm volatile("cp.async.cg.shared.global [%0], [%1], 16;"
                 :: "r"(dst), "l"(src) : "memory");
}
#define CP_COMMIT() asm volatile("cp.async.commit_group;" ::: "memory")
#define CP_WAIT1()  asm volatile("cp.async.wait_group 1;" ::: "memory")
__device__ __forceinline__ uint32_t packbf2(float a, float b) {
    __nv_bfloat162 p = __floats2bfloat162_rn(a, b);
    return *(uint32_t*)&p;
}
__device__ __forceinline__ void splitf(float v, float& hi, float& lo) {
    __nv_bfloat16 hb = __float2bfloat16_rn(v);
    hi = __bfloat162float(hb);
    lo = v - hi;
}
__device__ __forceinline__ float2 upk(uint32_t u) {
    __nv_bfloat162 b = *(__nv_bfloat162*)&u;
    return __bfloat1622float2(b);
}

/* ================================================================== */
/* Device scratch                                                      */
/* ================================================================== */
__device__ __align__(256) __nv_bfloat16 g_Eh[(size_t)NG * SEQ * SEQ]; /* 256 MB */
__device__ __align__(256) __nv_bfloat16 g_El[(size_t)NG * SEQ * SEQ]; /* 256 MB */
__device__ __align__(256) float g_Zp[16][NG * SEQ];
__device__ float g_Zi[NG * SEQ];
__device__ __align__(256) uint32_t g_Mb[NBATCH * SEQ * 32];           /* bit mask */
__device__ __align__(256) __nv_bfloat16 g_Xh[(size_t)3 * TTOK * EMBED];
__device__ __align__(256) __nv_bfloat16 g_Xl[(size_t)3 * TTOK * EMBED];
__device__ __align__(256) __nv_bfloat16 g_AOh[(size_t)TTOK * EMBED];
__device__ __align__(256) __nv_bfloat16 g_AOl[(size_t)TTOK * EMBED];
__device__ __align__(256) __nv_bfloat16 g_Wh[(size_t)4 * NB * EBS * EBS];
__device__ __align__(256) __nv_bfloat16 g_Wl[(size_t)4 * NB * EBS * EBS];
__device__ __align__(256) __nv_bfloat16 g_Qh[(size_t)NG * SEQ * HD];
__device__ __align__(256) __nv_bfloat16 g_Ql[(size_t)NG * SEQ * HD];
__device__ __align__(256) __nv_bfloat16 g_Kh[(size_t)NG * SEQ * HD];
__device__ __align__(256) __nv_bfloat16 g_Kl[(size_t)NG * SEQ * HD];
__device__ __align__(256) __nv_bfloat16 g_Vth[(size_t)NG * HD * SEQ]; /* [g][d][s] */
__device__ __align__(256) __nv_bfloat16 g_Vtl[(size_t)NG * HD * SEQ];

/* ================================================================== */
/* Converters                                                          */
/* ================================================================== */
__global__ __launch_bounds__(256) void convx_kernel(
    const float* __restrict__ V, const float* __restrict__ K,
    const float* __restrict__ Q)
{
    const int p = blockIdx.y;
    const float* src = (p == 0) ? V : (p == 1) ? K : Q;
    __nv_bfloat16* dh = g_Xh + (size_t)p * TTOK * EMBED;
    __nv_bfloat16* dl = g_Xl + (size_t)p * TTOK * EMBED;
    const size_t i = ((size_t)blockIdx.x * 256 + threadIdx.x) * 4;
    float4 v = *(const float4*)(src + i);
    float f[4] = {v.x, v.y, v.z, v.w};
    float hi[4], lo[4];
#pragma unroll
    for (int j = 0; j < 4; j++) splitf(f[j], hi[j], lo[j]);
    uint2 hv, lv;
    hv.x = packbf2(hi[0], hi[1]); hv.y = packbf2(hi[2], hi[3]);
    lv.x = packbf2(lo[0], lo[1]); lv.y = packbf2(lo[2], lo[3]);
    *(uint2*)(dh + i) = hv;
    *(uint2*)(dl + i) = lv;
}

__global__ __launch_bounds__(256) void convw_kernel(
    const float* __restrict__ Wv, const float* __restrict__ Wk,
    const float* __restrict__ Wq, const float* __restrict__ Wo)
{
    __shared__ float st[32][33];
    const int z = blockIdx.z;
    const int wi = z >> 2, b = z & 3;
    const float* W = ((wi == 0) ? Wv : (wi == 1) ? Wk : (wi == 2) ? Wq : Wo)
                     + (size_t)b * EBS * EBS;
    const int i0 = blockIdx.y * 32, o0 = blockIdx.x * 32;
    const int tx = threadIdx.x, ty = threadIdx.y;
#pragma unroll
    for (int kk = 0; kk < 4; kk++)
        st[ty + 8 * kk][tx] = W[(size_t)(i0 + ty + 8 * kk) * EBS + o0 + tx];
    __syncthreads();
    __nv_bfloat16* oh = g_Wh + (size_t)(wi * NB + b) * EBS * EBS;
    __nv_bfloat16* ol = g_Wl + (size_t)(wi * NB + b) * EBS * EBS;
#pragma unroll
    for (int kk = 0; kk < 4; kk++) {
        const float v = st[tx][ty + 8 * kk];
        float h, l;
        splitf(v, h, l);
        const size_t off = (size_t)(o0 + ty + 8 * kk) * EBS + i0 + tx;
        oh[off] = __float2bfloat16_rn(h);
        ol[off] = __float2bfloat16_rn(l);
    }
}

/* pack mask int32 -> bits (bit i of word w = mask[l = w*32+i] != 0) */
__global__ __launch_bounds__(256) void convm_kernel(const int* __restrict__ mask)
{
    const int wid = threadIdx.x >> 5, lane = threadIdx.x & 31;
    const int r = blockIdx.x * 8 + wid;  /* row in [0, NBATCH*SEQ) */
    const int* row = mask + (size_t)r * SEQ;
    uint32_t* orow = g_Mb + (size_t)r * 32;
    for (int w = 0; w < 32; w++) {
        const int m = row[w * 32 + lane];
        const uint32_t bits = __ballot_sync(0xffffffffu, m != 0);
        if (lane == 0) orow[w] = bits;
    }
}

/* ================================================================== */
/* mma.sync bf16 3-split projection GEMM (unchanged from R10).         */
/* ================================================================== */
#define KCHUNK 64
#define NCHUNKS 8
#define TILE_BYTES 16384
#define SS 132
#define SMEM_GEMM_TOTAL (128 * SS * 4)

template <int MODE>
__global__ __launch_bounds__(256) void mm_kernel(
    const float* __restrict__ bias0, const float* __restrict__ bias1,
    const float* __restrict__ bias2, float* __restrict__ oout)
{
    extern __shared__ char smem[];
    const uint32_t smem_base = smem_to_u32(smem);
    const int tid = threadIdx.x;
    const int wid = tid >> 5, lane = tid & 31;
    const int wm = wid & 1, wn = wid >> 1;

    int p, b;
    const __nv_bfloat16 *Ah, *Al;
    const float* bias;
    if (MODE == 0) {
        p = blockIdx.z >> 2; b = blockIdx.z & 3;
        Ah = g_Xh + (size_t)p * TTOK * EMBED;
        Al = g_Xl + (size_t)p * TTOK * EMBED;
        bias = (p == 0) ? bias0 : (p == 1) ? bias1 : bias2;
    } else {
        p = 3; b = blockIdx.z;
        Ah = g_AOh; Al = g_AOl;
        bias = bias0;
    }
    const __nv_bfloat16* Bh = g_Wh + (size_t)(p * NB + b) * EBS * EBS;
    const __nv_bfloat16* Bl = g_Wl + (size_t)(p * NB + b) * EBS * EBS;
    const int m0 = blockIdx.y * 128, n0 = blockIdx.x * 128;

    const uint32_t tAh = smem_base;
    const uint32_t tAl = smem_base + TILE_BYTES;
    const uint32_t tBh = smem_base + 2 * TILE_BYTES;
    const uint32_t tBl = smem_base + 3 * TILE_BYTES;

    const int lrow = tid >> 1;
    const int lhalf = (tid & 1) * 32;
    const __nv_bfloat16* Arow_h = Ah + (size_t)(m0 + lrow) * EMBED + b * EBS + lhalf;
    const __nv_bfloat16* Arow_l = Al + (size_t)(m0 + lrow) * EMBED + b * EBS + lhalf;
    const __nv_bfloat16* Brow_h = Bh + (size_t)(n0 + lrow) * EBS + lhalf;
    const __nv_bfloat16* Brow_l = Bl + (size_t)(n0 + lrow) * EBS + lhalf;
    uint32_t sw[4];
#pragma unroll
    for (int gix = 0; gix < 4; gix++)
        sw[gix] = SMEM_SWIZZLE_128B((uint32_t)(lrow * 128 + (lhalf + gix * 8) * 2));

    const int a_row = (lane & 15);
    const int a_c16 = (lane >> 4) * 16;
    const int b_row = (lane & 7) + ((lane >> 4) << 3);
    const int b_c16 = ((lane >> 3) & 1) * 16;

    float acc[4][4][4];
#pragma unroll
    for (int mf = 0; mf < 4; mf++)
#pragma unroll
        for (int nf = 0; nf < 4; nf++)
#pragma unroll
            for (int r = 0; r < 4; r++) acc[mf][nf][r] = 0.f;

    for (int c = 0; c < NCHUNKS; c++) {
        const int coff = c * KCHUNK;
#pragma unroll
        for (int gix = 0; gix < 4; gix++) {
            uint4 vah = *(const uint4*)(Arow_h + coff + gix * 8);
            uint4 val = *(const uint4*)(Arow_l + coff + gix * 8);
            uint4 vbh = *(const uint4*)(Brow_h + coff + gix * 8);
            uint4 vbl = *(const uint4*)(Brow_l + coff + gix * 8);
            *(uint4*)(smem + 0 * TILE_BYTES + sw[gix]) = vah;
            *(uint4*)(smem + 1 * TILE_BYTES + sw[gix]) = val;
            *(uint4*)(smem + 2 * TILE_BYTES + sw[gix]) = vbh;
            *(uint4*)(smem + 3 * TILE_BYTES + sw[gix]) = vbl;
        }
        __syncthreads();

#pragma unroll
        for (int ks = 0; ks < 4; ks++) {
            uint32_t ah[4][4], al[4][4];
#pragma unroll
            for (int mf = 0; mf < 4; mf++) {
                const uint32_t off = (uint32_t)((wm * 64 + mf * 16 + a_row) * 128
                                                + ks * 32 + a_c16);
                const uint32_t swo = SMEM_SWIZZLE_128B(off);
                ldsm4(ah[mf], tAh + swo);
                ldsm4(al[mf], tAl + swo);
            }
            uint32_t bh[8];
#pragma unroll
            for (int np = 0; np < 2; np++) {
                const uint32_t off = (uint32_t)((wn * 32 + np * 16 + b_row) * 128
                                                + ks * 32 + b_c16);
                ldsm4(&bh[np * 4], tBh + SMEM_SWIZZLE_128B(off));
            }
#pragma unroll
            for (int mf = 0; mf < 4; mf++)
#pragma unroll
                for (int nf = 0; nf < 4; nf++)
                    mma16816(acc[mf][nf], ah[mf], &bh[nf * 2]);
#pragma unroll
            for (int mf = 0; mf < 4; mf++)
#pragma unroll
                for (int nf = 0; nf < 4; nf++)
                    mma16816(acc[mf][nf], al[mf], &bh[nf * 2]);
            uint32_t bl[8];
#pragma unroll
            for (int np = 0; np < 2; np++) {
                const uint32_t off = (uint32_t)((wn * 32 + np * 16 + b_row) * 128
                                                + ks * 32 + b_c16);
                ldsm4(&bl[np * 4], tBl + SMEM_SWIZZLE_128B(off));
            }
#pragma unroll
            for (int mf = 0; mf < 4; mf++)
#pragma unroll
                for (int nf = 0; nf < 4; nf++)
                    mma16816(acc[mf][nf], ah[mf], &bl[nf * 2]);
        }
        __syncthreads();
    }

    float* stg = (float*)smem;  /* [128][SS] */
    const int gr = lane >> 2, c2 = (lane & 3) * 2;
#pragma unroll
    for (int mf = 0; mf < 4; mf++) {
        const int row0 = wm * 64 + mf * 16 + gr;
#pragma unroll
        for (int nf = 0; nf < 4; nf++) {
            const int col = wn * 32 + nf * 8 + c2;
            *(float2*)&stg[row0 * SS + col]       = make_float2(acc[mf][nf][0], acc[mf][nf][1]);
            *(float2*)&stg[(row0 + 8) * SS + col] = make_float2(acc[mf][nf][2], acc[mf][nf][3]);
        }
    }
    __syncthreads();

    if (MODE == 0) {
        const int n = m0 >> 10, s0 = m0 & (SEQ - 1);
        const int h0 = n0 >> 6;
        if (p >= 1) {
            __nv_bfloat16* oh = (p == 1) ? g_Kh : g_Qh;
            __nv_bfloat16* ol = (p == 1) ? g_Kl : g_Ql;
#pragma unroll
            for (int it = 0; it < 16; it++) {
                const int flat = tid + it * 256;
                const int srow = flat >> 5;
                const int rem = flat & 31;
                const int hh = rem >> 4, dq = (rem & 15) * 4;
                const int ocol = hh * 64 + dq;
                float hi[4], lo[4];
#pragma unroll
                for (int j = 0; j < 4; j++) {
                    const float v = stg[srow * SS + ocol + j]
                                    + bias[b * EBS + n0 + ocol + j];
                    splitf(v, hi[j], lo[j]);
                }
                uint2 hv, lv;
                hv.x = packbf2(hi[0], hi[1]); hv.y = packbf2(hi[2], hi[3]);
                lv.x = packbf2(lo[0], lo[1]); lv.y = packbf2(lo[2], lo[3]);
                const size_t gidx = (size_t)((n * NB + b) * HEADS + h0 + hh);
                const size_t off = (gidx * SEQ + s0 + srow) * HD + dq;
                *(uint2*)(oh + off) = hv;
                *(uint2*)(ol + off) = lv;
            }
        } else {
            const int dcol = tid >> 1;
            const int shalf = (tid & 1) * 64;
            const int hh = dcol >> 6, dl = dcol & 63;
            const size_t gidx = (size_t)((n * NB + b) * HEADS + h0 + hh);
            const float bb = bias[b * EBS + n0 + dcol];
            __nv_bfloat16* oh = g_Vth + (gidx * HD + dl) * SEQ + s0 + shalf;
            __nv_bfloat16* ol = g_Vtl + (gidx * HD + dl) * SEQ + s0 + shalf;
#pragma unroll
            for (int blk = 0; blk < 16; blk++) {
                float hi[4], lo[4];
#pragma unroll
                for (int j = 0; j < 4; j++) {
                    const float v = stg[(shalf + blk * 4 + j) * SS + dcol] + bb;
                    splitf(v, hi[j], lo[j]);
                }
                uint2 hv, lv;
                hv.x = packbf2(hi[0], hi[1]); hv.y = packbf2(hi[2], hi[3]);
                lv.x = packbf2(lo[0], lo[1]); lv.y = packbf2(lo[2], lo[3]);
                *(uint2*)(oh + blk * 4) = hv;
                *(uint2*)(ol + blk * 4) = lv;
            }
        }
    } else {
#pragma unroll
        for (int it = 0; it < 16; it++) {
            const int flat = tid + it * 256;
            const int srow = flat >> 5;
            const int oq = (flat & 31) * 4;
            float4 v;
            v.x = stg[srow * SS + oq + 0] + bias[b * EBS + n0 + oq + 0];
            v.y = stg[srow * SS + oq + 1] + bias[b * EBS + n0 + oq + 1];
            v.z = stg[srow * SS + oq + 2] + bias[b * EBS + n0 + oq + 2];
            v.w = stg[srow * SS + oq + 3] + bias[b * EBS + n0 + oq + 3];
            *(float4*)(oout + (size_t)(m0 + srow) * EMBED + b * EBS + n0 + oq) = v;
        }
    }
}

/* ================================================================== */
/* Energy v2: one CTA per (g, q-tile); Q resident, K streamed with     */
/* cp.async double-buffer over 8 l-tiles. E out as bf16 hi/lo; column  */
/* partial sums per l-tile. smem = 32K(Q) + 2*32K(K) = 96K.            */
/* ================================================================== */
#define SMEM_ENERGY 98304

__global__ __launch_bounds__(256, 2) void energy_mma_kernel()
{
    extern __shared__ char smem[];
    const uint32_t smem_base = smem_to_u32(smem);
    const int tid = threadIdx.x;
    const int wid = tid >> 5, lane = tid & 31;
    const int wm = wid & 1, wn = wid >> 1;

    const int g  = blockIdx.y;
    const int qt = blockIdx.x;
    const int q0 = qt * 128;
    const int n = g >> 5;

    const uint32_t tQh = smem_base;
    const uint32_t tQl = smem_base + TILE_BYTES;

    const int lrow = tid >> 1;
    const int lhalf = (tid & 1) * 32;
    uint32_t sw[4];
#pragma unroll
    for (int gix = 0; gix < 4; gix++)
        sw[gix] = SMEM_SWIZZLE_128B((uint32_t)(lrow * 128 + (lhalf + gix * 8) * 2));

    const __nv_bfloat16* qh = g_Qh + ((size_t)g * SEQ + q0 + lrow) * HD + lhalf;
    const __nv_bfloat16* ql = g_Ql + ((size_t)g * SEQ + q0 + lrow) * HD + lhalf;
    const __nv_bfloat16* khb = g_Kh + ((size_t)g * SEQ + lrow) * HD + lhalf;
    const __nv_bfloat16* klb = g_Kl + ((size_t)g * SEQ + lrow) * HD + lhalf;

    /* group 0: Q + K tile 0 */
#pragma unroll
    for (int gix = 0; gix < 4; gix++) {
        cpa16(tQh + sw[gix], qh + gix * 8);
        cpa16(tQl + sw[gix], ql + gix * 8);
    }
    {
        const uint32_t kb = smem_base + 2 * TILE_BYTES;
#pragma unroll
        for (int gix = 0; gix < 4; gix++) {
            cpa16(kb + sw[gix], khb + gix * 8);
            cpa16(kb + TILE_BYTES + sw[gix], klb + gix * 8);
        }
    }
    CP_COMMIT();
    /* group 1: K tile 1 */
    {
        const uint32_t kb = smem_base + 4 * TILE_BYTES;
        const size_t so = (size_t)128 * HD;
#pragma unroll
        for (int gix = 0; gix < 4; gix++) {
            cpa16(kb + sw[gix], khb + so + gix * 8);
            cpa16(kb + TILE_BYTES + sw[gix], klb + so + gix * 8);
        }
    }
    CP_COMMIT();

    const int a_row = (lane & 15);
    const int a_c16 = (lane >> 4) * 16;
    const int b_row = (lane & 7) + ((lane >> 4) << 3);
    const int b_c16 = ((lane >> 3) & 1) * 16;
    const int gr = lane >> 2, c2 = (lane & 3) * 2;

    const uint32_t* Mbn = g_Mb + (size_t)n * SEQ * 32;
    __nv_bfloat16* Egh = g_Eh + (size_t)g * SEQ * SEQ;
    __nv_bfloat16* Egl = g_El + (size_t)g * SEQ * SEQ;

    for (int c = 0; c < 8; c++) {
        CP_WAIT1();
        __syncthreads();
        const uint32_t tKh = smem_base + (2 + 2 * (c & 1)) * TILE_BYTES;
        const uint32_t tKl = tKh + TILE_BYTES;

        float acc[4][4][4];
#pragma unroll
        for (int mf = 0; mf < 4; mf++)
#pragma unroll
            for (int nf = 0; nf < 4; nf++)
#pragma unroll
                for (int r = 0; r < 4; r++) acc[mf][nf][r] = 0.f;

#pragma unroll
        for (int ks = 0; ks < 4; ks++) {
            uint32_t ah[4][4], al[4][4];
#pragma unroll
            for (int mf = 0; mf < 4; mf++) {
                const uint32_t off = (uint32_t)((wm * 64 + mf * 16 + a_row) * 128
                                                + ks * 32 + a_c16);
                const uint32_t swo = SMEM_SWIZZLE_128B(off);
                ldsm4(ah[mf], tQh + swo);
                ldsm4(al[mf], tQl + swo);
            }
            uint32_t bh[8];
#pragma unroll
            for (int np = 0; np < 2; np++) {
                const uint32_t off = (uint32_t)((wn * 32 + np * 16 + b_row) * 128
                                                + ks * 32 + b_c16);
                ldsm4(&bh[np * 4], tKh + SMEM_SWIZZLE_128B(off));
            }
#pragma unroll
            for (int mf = 0; mf < 4; mf++)
#pragma unroll
                for (int nf = 0; nf < 4; nf++)
                    mma16816(acc[mf][nf], ah[mf], &bh[nf * 2]);
#pragma unroll
            for (int mf = 0; mf < 4; mf++)
#pragma unroll
                for (int nf = 0; nf < 4; nf++)
                    mma16816(acc[mf][nf], al[mf], &bh[nf * 2]);
            uint32_t bl[8];
#pragma unroll
            for (int np = 0; np < 2; np++) {
                const uint32_t off = (uint32_t)((wn * 32 + np * 16 + b_row) * 128
                                                + ks * 32 + b_c16);
                ldsm4(&bl[np * 4], tKl + SMEM_SWIZZLE_128B(off));
            }
#pragma unroll
            for (int mf = 0; mf < 4; mf++)
#pragma unroll
                for (int nf = 0; nf < 4; nf++)
                    mma16816(acc[mf][nf], ah[mf], &bl[nf * 2]);
        }
        __syncthreads();

        /* prefetch K tile c+2 into the buffer just freed */
        if (c + 2 < 8) {
            const uint32_t kb = smem_base + (2 + 2 * (c & 1)) * TILE_BYTES;
            const size_t so = (size_t)(c + 2) * 128 * HD;
#pragma unroll
            for (int gix = 0; gix < 4; gix++) {
                cpa16(kb + sw[gix], khb + so + gix * 8);
                cpa16(kb + TILE_BYTES + sw[gix], klb + so + gix * 8);
            }
        }
        CP_COMMIT();

        /* epilogue: E = exp(masked * 0.125) as bf16 hi/lo + col sums */
        const int l0 = c * 128;
        const int cw = c * 4 + wn;
        float csum[4][2];
#pragma unroll
        for (int nf = 0; nf < 4; nf++) { csum[nf][0] = 0.f; csum[nf][1] = 0.f; }

#pragma unroll
        for (int mf = 0; mf < 4; mf++) {
#pragma unroll
            for (int half = 0; half < 2; half++) {
                const int q = q0 + wm * 64 + mf * 16 + gr + half * 8;
                const uint32_t w = Mbn[q * 32 + cw];
#pragma unroll
                for (int nf = 0; nf < 4; nf++) {
                    const int col = l0 + wn * 32 + nf * 8 + c2;
                    const uint32_t bits = (w >> (nf * 8 + c2)) & 3u;
                    float2 e;
                    e.x = (bits & 1u) ? __expf(acc[mf][nf][half * 2 + 0] * 0.125f) : 0.f;
                    e.y = (bits & 2u) ? __expf(acc[mf][nf][half * 2 + 1] * 0.125f) : 0.f;
                    float h0, lo0, h1, lo1;
                    splitf(e.x, h0, lo0);
                    splitf(e.y, h1, lo1);
                    *(uint32_t*)(Egh + (size_t)q * SEQ + col) = packbf2(h0, h1);
                    *(uint32_t*)(Egl + (size_t)q * SEQ + col) = packbf2(lo0, lo1);
                    csum[nf][0] += e.x;
                    csum[nf][1] += e.y;
                }
            }
        }
        float* Zp = g_Zp[qt * 2 + wm] + g * SEQ;
#pragma unroll
        for (int nf = 0; nf < 4; nf++) {
#pragma unroll
            for (int cc = 0; cc < 2; cc++) {
                float v = csum[nf][cc];
                v += __shfl_xor_sync(0xffffffffu, v, 4);
                v += __shfl_xor_sync(0xffffffffu, v, 8);
                v += __shfl_xor_sync(0xffffffffu, v, 16);
                if (gr == 0)
                    Zp[l0 + wn * 32 + nf * 8 + c2 + cc] = v;
            }
        }
    }
}

/* ================================================================== */
/* Reduce 16 column-sum partials -> Zi = 1/Z                           */
/* ================================================================== */
__global__ __launch_bounds__(256) void zred_kernel()
{
    const int i = blockIdx.x * 256 + threadIdx.x;
    float z = 0.f;
#pragma unroll
    for (int s = 0; s < 16; s++)
        z += g_Zp[s][i];
    g_Zi[i] = (z > 0.f) ? (1.f / z) : 0.f;
}

/* ================================================================== */
/* Fold Zi into V rows: V'[g][d][s] = (Vh+Vl)[g][d][s] * Zi[g][s]      */
/* ================================================================== */
__global__ __launch_bounds__(256) void vscale_kernel()
{
    const size_t e = ((size_t)blockIdx.x * 256 + threadIdx.x) * 8;
    const int g = (int)(e / ((size_t)HD * SEQ));
    const int s = (int)(e % SEQ);
    float4 z0 = *(const float4*)(g_Zi + g * SEQ + s);
    float4 z1 = *(const float4*)(g_Zi + g * SEQ + s + 4);
    const float zz[8] = {z0.x, z0.y, z0.z, z0.w, z1.x, z1.y, z1.z, z1.w};
    uint4 vh = *(const uint4*)(g_Vth + e);
    uint4 vl = *(const uint4*)(g_Vtl + e);
    const uint32_t hw[4] = {vh.x, vh.y, vh.z, vh.w};
    const uint32_t lw[4] = {vl.x, vl.y, vl.z, vl.w};
    uint32_t oh[4], ol[4];
#pragma unroll
    for (int j = 0; j < 4; j++) {
        float2 fh = upk(hw[j]);
        float2 fl = upk(lw[j]);
        const float a = (fh.x + fl.x) * zz[2 * j];
        const float b = (fh.y + fl.y) * zz[2 * j + 1];
        float ah, alo, bh, blo;
        splitf(a, ah, alo);
        splitf(b, bh, blo);
        oh[j] = packbf2(ah, bh);
        ol[j] = packbf2(alo, blo);
    }
    *(uint4*)(g_Vth + e) = make_uint4(oh[0], oh[1], oh[2], oh[3]);
    *(uint4*)(g_Vtl + e) = make_uint4(ol[0], ol[1], ol[2], ol[3]);
}

/* ================================================================== */
/* AV v2: pure GEMM O = E·V' with cp.async double-buffered E/V tiles.  */
/* 128q x 64d per CTA, 16 l-chunks of 64. buf = Eh16K+El16K+Vh8K+Vl8K. */
/* ================================================================== */
#define AVBUF 49152
#define SMEM_AV (2 * AVBUF)

__global__ __launch_bounds__(256, 2) void av_mma_kernel()
{
    extern __shared__ char smem[];
    const uint32_t smem_base = smem_to_u32(smem);
    const int tid = threadIdx.x;
    const int wid = tid >> 5, lane = tid & 31;
    const int wm = wid >> 1, wn = wid & 1;

    const int g  = blockIdx.y;
    const int q0 = blockIdx.x * 128;

    /* E loader: row=tid>>1 (128), 64B half=(tid&1)*64, 4x16B */
    const int erow = tid >> 1;
    const int ebyte = (tid & 1) * 64;
    const __nv_bfloat16* ehb = g_Eh + ((size_t)g * SEQ + q0 + erow) * SEQ + ebyte / 2;
    const __nv_bfloat16* elb = g_El + ((size_t)g * SEQ + q0 + erow) * SEQ + ebyte / 2;
    uint32_t esw[4];
#pragma unroll
    for (int gix = 0; gix < 4; gix++)
        esw[gix] = SMEM_SWIZZLE_128B((uint32_t)(erow * 128 + ebyte + gix * 16));

    /* V loader: row=tid>>2 (64), 32B seg=(tid&3)*32, 2x16B */
    const int vrow = tid >> 2;
    const int vbyte = (tid & 3) * 32;
    const __nv_bfloat16* vhb = g_Vth + ((size_t)g * HD + vrow) * SEQ + vbyte / 2;
    const __nv_bfloat16* vlb = g_Vtl + ((size_t)g * HD + vrow) * SEQ + vbyte / 2;
    uint32_t vsw[2];
#pragma unroll
    for (int j = 0; j < 2; j++)
        vsw[j] = SMEM_SWIZZLE_128B((uint32_t)(vrow * 128 + vbyte + j * 16));

#define AV_ISSUE(cc, buf)                                                      \
    do {                                                                       \
        const int _l0 = (cc) * 64;                                             \
        const uint32_t _bb = smem_base + (buf) * AVBUF;                        \
        _Pragma("unroll")                                                      \
        for (int gix = 0; gix < 4; gix++) {                                    \
            cpa16(_bb + esw[gix], ehb + _l0 + gix * 8);                        \
            cpa16(_bb + 16384 + esw[gix], elb + _l0 + gix * 8);                \
        }                                                                      \
        _Pragma("unroll")                                                      \
        for (int j = 0; j < 2; j++) {                                          \
            cpa16(_bb + 32768 + vsw[j], vhb + _l0 + j * 8);                    \
            cpa16(_bb + 40960 + vsw[j], vlb + _l0 + j * 8);                    \
        }                                                                      \
    } while (0)

    AV_ISSUE(0, 0);
    CP_COMMIT();
    AV_ISSUE(1, 1);
    CP_COMMIT();

    const int a_row = (lane & 15);
    const int a_c16 = (lane >> 4) * 16;
    const int b_row = (lane & 7) + ((lane >> 4) << 3);
    const int b_c16 = ((lane >> 3) & 1) * 16;

    float acc[2][4][4];
#pragma unroll
    for (int mf = 0; mf < 2; mf++)
#pragma unroll
        for (int nf = 0; nf < 4; nf++)
#pragma unroll
            for (int r = 0; r < 4; r++) acc[mf][nf][r] = 0.f;

    for (int c = 0; c < 16; c++) {
        CP_WAIT1();
        __syncthreads();
        const uint32_t bb = smem_base + (c & 1) * AVBUF;
        const uint32_t tEh = bb, tEl = bb + 16384;
        const uint32_t tVh = bb + 32768, tVl = bb + 40960;

#pragma unroll
        for (int ks = 0; ks < 4; ks++) {
            uint32_t ah[2][4], al[2][4];
#pragma unroll
            for (int mf = 0; mf < 2; mf++) {
                const uint32_t off = (uint32_t)((wm * 32 + mf * 16 + a_row) * 128
                                                + ks * 32 + a_c16);
                const uint32_t swo = SMEM_SWIZZLE_128B(off);
                ldsm4(ah[mf], tEh + swo);
                ldsm4(al[mf], tEl + swo);
            }
            uint32_t bh[8];
#pragma unroll
            for (int np = 0; np < 2; np++) {
                const uint32_t off = (uint32_t)((wn * 32 + np * 16 + b_row) * 128
                                                + ks * 32 + b_c16);
                ldsm4(&bh[np * 4], tVh + SMEM_SWIZZLE_128B(off));
            }
#pragma unroll
            for (int mf = 0; mf < 2; mf++)
#pragma unroll
                for (int nf = 0; nf < 4; nf++)
                    mma16816(acc[mf][nf], ah[mf], &bh[nf * 2]);
#pragma unroll
            for (int mf = 0; mf < 2; mf++)
#pragma unroll
                for (int nf = 0; nf < 4; nf++)
                    mma16816(acc[mf][nf], al[mf], &bh[nf * 2]);
            uint32_t bl[8];
#pragma unroll
            for (int np = 0; np < 2; np++) {
                const uint32_t off = (uint32_t)((wn * 32 + np * 16 + b_row) * 128
                                                + ks * 32 + b_c16);
                ldsm4(&bl[np * 4], tVl + SMEM_SWIZZLE_128B(off));
            }
#pragma unroll
            for (int mf = 0; mf < 2; mf++)
#pragma unroll
                for (int nf = 0; nf < 4; nf++)
                    mma16816(acc[mf][nf], ah[mf], &bl[nf * 2]);
        }
        __syncthreads();
        if (c + 2 < 16)
            AV_ISSUE(c + 2, c & 1);
        CP_COMMIT();
    }

    /* epilogue: split O to bf16 hi/lo -> g_AOh/g_AOl */
    const int n = g >> 5, b = (g >> 3) & 3, hd = g & 7;
    const int gr = lane >> 2, c2 = (lane & 3) * 2;
#pragma unroll
    for (int mf = 0; mf < 2; mf++) {
#pragma unroll
        for (int nf = 0; nf < 4; nf++) {
            const int d = wn * 32 + nf * 8 + c2;
#pragma unroll
            for (int half = 0; half < 2; half++) {
                const int q = q0 + wm * 32 + mf * 16 + gr + half * 8;
                const size_t t = (size_t)(n * SEQ + q);
                const size_t off = t * EMBED + b * EBS + hd * HD + d;
                float h0, l0f, h1, l1;
                splitf(acc[mf][nf][half * 2 + 0], h0, l0f);
                splitf(acc[mf][nf][half * 2 + 1], h1, l1);
                *(uint32_t*)(g_AOh + off) = packbf2(h0, h1);
                *(uint32_t*)(g_AOl + off) = packbf2(l0f, l1);
            }
        }
    }
}

/* ------------------------------------------------------------------ */
extern "C" void kernel_launch(void* const* d_in, const int* in_sizes, int n_in,
                              void* d_out, int out_size)
{
    const float* values = (const float*)d_in[0];
    const float* keys   = (const float*)d_in[1];
    const float* query  = (const float*)d_in[2];
    const int*   mask   = (const int*)d_in[3];
    const float* Wv = (const float*)d_in[4];
    const float* bv = (const float*)d_in[5];
    const float* Wk = (const float*)d_in[6];
    const float* bk = (const float*)d_in[7];
    const float* Wq = (const float*)d_in[8];
    const float* bq = (const float*)d_in[9];
    const float* Wo = (const float*)d_in[10];
    const float* bo = (const float*)d_in[11];
    float* out = (float*)d_out;

    cudaFuncSetAttribute(mm_kernel<0>, cudaFuncAttributeMaxDynamicSharedMemorySize,
                         SMEM_GEMM_TOTAL);
    cudaFuncSetAttribute(mm_kernel<1>, cudaFuncAttributeMaxDynamicSharedMemorySize,
                         SMEM_GEMM_TOTAL);
    cudaFuncSetAttribute(energy_mma_kernel, cudaFuncAttributeMaxDynamicSharedMemorySize,
                         SMEM_ENERGY);
    cudaFuncSetAttribute(av_mma_kernel, cudaFuncAttributeMaxDynamicSharedMemorySize,
                         SMEM_AV);

    /* converts */
    dim3 gx((TTOK * EMBED) / (256 * 4), 3);
    convx_kernel<<<gx, 256>>>(values, keys, query);
    dim3 gw(EBS / 32, EBS / 32, 16);
    convw_kernel<<<gw, dim3(32, 8)>>>(Wv, Wk, Wq, Wo);
    convm_kernel<<<(NBATCH * SEQ) / 8, 256>>>(mask);

    /* fused qkv projections (tensor) */
    dim3 gqkv(EBS / 128, TTOK / 128, 12);
    mm_kernel<0><<<gqkv, 256, SMEM_GEMM_TOTAL>>>(bv, bk, bq, nullptr);

    /* energy + exp + column partial sums (tensor, pipelined) */
    dim3 ge(SEQ / 128, NG);
    energy_mma_kernel<<<ge, 256, SMEM_ENERGY>>>();

    /* reduce partials -> 1/Z, fold into V */
    zred_kernel<<<(NG * SEQ) / 256, 256>>>();
    vscale_kernel<<<(NG * HD * SEQ) / (256 * 8), 256>>>();

    /* AV (tensor, pipelined) */
    dim3 ga(SEQ / 128, NG);
    av_mma_kernel<<<ga, 256, SMEM_AV>>>();

    /* output projection (tensor) */
    dim3 go(EBS / 128, TTOK / 128, NB);
    mm_kernel<1><<<go, 256, SMEM_GEMM_TOTAL>>>(bo, nullptr, nullptr, out);
}

// round 12
// speedup vs baseline: 2.9339x; 1.0563x over previous
#include <cuda_runtime.h>
#include <cuda_bf16.h>
#include <math.h>
#include <stdint.h>

#define NBATCH 4
#define SEQ    1024
#define EMBED  2048
#define EBS    512
#define NB     4
#define HEADS  8
#define HD     64
#define TTOK   (NBATCH * SEQ)        /* 4096 tokens */
#define NG     (NBATCH * NB * HEADS) /* 128 (n,b,h) heads */

typedef unsigned long long u64;

#define SMEM_SWIZZLE_128B(off) ((off) ^ (((off) >> 3) & 0x70))

/* ================================================================== */
/* Tensor / async helpers (sm_80 path: legal on base sm_103 target)    */
/* ================================================================== */
__device__ __forceinline__ uint32_t smem_to_u32(const void* p) {
    uint32_t a;
    asm("{ .reg .u64 t; cvta.to.shared.u64 t, %1; cvt.u32.u64 %0, t; }"
        : "=r"(a) : "l"(p));
    return a;
}
__device__ __forceinline__ void ldsm4(uint32_t* r, uint32_t addr) {
    asm volatile("ldmatrix.sync.aligned.m8n8.x4.shared.b16 {%0,%1,%2,%3}, [%4];"
                 : "=r"(r[0]), "=r"(r[1]), "=r"(r[2]), "=r"(r[3]) : "r"(addr));
}
__device__ __forceinline__ void mma16816(float* d, const uint32_t* a,
                                         const uint32_t* b) {
    asm volatile(
        "mma.sync.aligned.m16n8k16.row.col.f32.bf16.bf16.f32 "
        "{%0,%1,%2,%3}, {%4,%5,%6,%7}, {%8,%9}, {%0,%1,%2,%3};"
        : "+f"(d[0]), "+f"(d[1]), "+f"(d[2]), "+f"(d[3])
        : "r"(a[0]), "r"(a[1]), "r"(a[2]), "r"(a[3]), "r"(b[0]), "r"(b[1]));
}
__device__ __forceinline__ void cpa16(uint32_t dst, const void* src) {
    asm volatile("cp.async.cg.shared.global [%0], [%1], 16;"
                 :: "r"(dst), "l"(src) : "memory");
}
#define CP_COMMIT() asm volatile("cp.async.commit_group;" ::: "memory")
#define CP_WAIT1()  asm volatile("cp.async.wait_group 1;" ::: "memory")
#define CP_WAIT0()  asm volatile("cp.async.wait_group 0;" ::: "memory")
__device__ __forceinline__ uint32_t packbf2(float a, float b) {
    __nv_bfloat162 p = __floats2bfloat162_rn(a, b);
    return *(uint32_t*)&p;
}
__device__ __forceinline__ void splitf(float v, float& hi, float& lo) {
    __nv_bfloat16 hb = __float2bfloat16_rn(v);
    hi = __bfloat162float(hb);
    lo = v - hi;
}
__device__ __forceinline__ float2 upk(uint32_t u) {
    __nv_bfloat162 b = *(__nv_bfloat162*)&u;
    return __bfloat1622float2(b);
}

/* ================================================================== */
/* Device scratch                                                      */
/* ================================================================== */
__device__ __align__(256) __nv_bfloat16 g_Eh[(size_t)NG * SEQ * SEQ]; /* 256 MB */
__device__ __align__(256) __nv_bfloat16 g_El[(size_t)NG * SEQ * SEQ]; /* 256 MB */
__device__ __align__(256) float g_Zp[16][NG * SEQ];
__device__ float g_Zi[NG * SEQ];
__device__ __align__(256) uint32_t g_Mb[NBATCH * SEQ * 32];           /* bit mask */
__device__ __align__(256) __nv_bfloat16 g_Xh[(size_t)3 * TTOK * EMBED];
__device__ __align__(256) __nv_bfloat16 g_Xl[(size_t)3 * TTOK * EMBED];
__device__ __align__(256) __nv_bfloat16 g_AOh[(size_t)TTOK * EMBED];
__device__ __align__(256) __nv_bfloat16 g_AOl[(size_t)TTOK * EMBED];
__device__ __align__(256) __nv_bfloat16 g_Wh[(size_t)4 * NB * EBS * EBS];
__device__ __align__(256) __nv_bfloat16 g_Wl[(size_t)4 * NB * EBS * EBS];
__device__ __align__(256) __nv_bfloat16 g_Qh[(size_t)NG * SEQ * HD];
__device__ __align__(256) __nv_bfloat16 g_Ql[(size_t)NG * SEQ * HD];
__device__ __align__(256) __nv_bfloat16 g_Kh[(size_t)NG * SEQ * HD];
__device__ __align__(256) __nv_bfloat16 g_Kl[(size_t)NG * SEQ * HD];
__device__ __align__(256) __nv_bfloat16 g_Vth[(size_t)NG * HD * SEQ]; /* [g][d][s] */
__device__ __align__(256) __nv_bfloat16 g_Vtl[(size_t)NG * HD * SEQ];

/* ================================================================== */
/* Converters                                                          */
/* ================================================================== */
__global__ __launch_bounds__(256) void convx_kernel(
    const float* __restrict__ V, const float* __restrict__ K,
    const float* __restrict__ Q)
{
    const int p = blockIdx.y;
    const float* src = (p == 0) ? V : (p == 1) ? K : Q;
    __nv_bfloat16* dh = g_Xh + (size_t)p * TTOK * EMBED;
    __nv_bfloat16* dl = g_Xl + (size_t)p * TTOK * EMBED;
    const size_t i = ((size_t)blockIdx.x * 256 + threadIdx.x) * 4;
    float4 v = *(const float4*)(src + i);
    float f[4] = {v.x, v.y, v.z, v.w};
    float hi[4], lo[4];
#pragma unroll
    for (int j = 0; j < 4; j++) splitf(f[j], hi[j], lo[j]);
    uint2 hv, lv;
    hv.x = packbf2(hi[0], hi[1]); hv.y = packbf2(hi[2], hi[3]);
    lv.x = packbf2(lo[0], lo[1]); lv.y = packbf2(lo[2], lo[3]);
    *(uint2*)(dh + i) = hv;
    *(uint2*)(dl + i) = lv;
}

__global__ __launch_bounds__(256) void convw_kernel(
    const float* __restrict__ Wv, const float* __restrict__ Wk,
    const float* __restrict__ Wq, const float* __restrict__ Wo)
{
    __shared__ float st[32][33];
    const int z = blockIdx.z;
    const int wi = z >> 2, b = z & 3;
    const float* W = ((wi == 0) ? Wv : (wi == 1) ? Wk : (wi == 2) ? Wq : Wo)
                     + (size_t)b * EBS * EBS;
    const int i0 = blockIdx.y * 32, o0 = blockIdx.x * 32;
    const int tx = threadIdx.x, ty = threadIdx.y;
#pragma unroll
    for (int kk = 0; kk < 4; kk++)
        st[ty + 8 * kk][tx] = W[(size_t)(i0 + ty + 8 * kk) * EBS + o0 + tx];
    __syncthreads();
    __nv_bfloat16* oh = g_Wh + (size_t)(wi * NB + b) * EBS * EBS;
    __nv_bfloat16* ol = g_Wl + (size_t)(wi * NB + b) * EBS * EBS;
#pragma unroll
    for (int kk = 0; kk < 4; kk++) {
        const float v = st[tx][ty + 8 * kk];
        float h, l;
        splitf(v, h, l);
        const size_t off = (size_t)(o0 + ty + 8 * kk) * EBS + i0 + tx;
        oh[off] = __float2bfloat16_rn(h);
        ol[off] = __float2bfloat16_rn(l);
    }
}

/* pack mask int32 -> bits */
__global__ __launch_bounds__(256) void convm_kernel(const int* __restrict__ mask)
{
    const int wid = threadIdx.x >> 5, lane = threadIdx.x & 31;
    const int r = blockIdx.x * 8 + wid;
    const int* row = mask + (size_t)r * SEQ;
    uint32_t* orow = g_Mb + (size_t)r * 32;
    for (int w = 0; w < 32; w++) {
        const int m = row[w * 32 + lane];
        const uint32_t bits = __ballot_sync(0xffffffffu, m != 0);
        if (lane == 0) orow[w] = bits;
    }
}

/* ================================================================== */
/* mma.sync bf16 3-split projection GEMM, cp.async double-buffered.    */
/* 128x128 CTA tile, K=512 in 8 chunks of 64. Warps 2(m)x4(n).         */
/* smem: 2 buffers x (Ah,Al,Bh,Bl) x 16KB = 128 KB.                    */
/* ================================================================== */
#define KCHUNK 64
#define NCHUNKS 8
#define TILE_BYTES 16384
#define MMBUF (4 * TILE_BYTES)            /* 64 KB per chunk buffer */
#define SS 132
#define SMEM_GEMM_TOTAL (2 * MMBUF)       /* 128 KB */

template <int MODE>
__global__ __launch_bounds__(256) void mm_kernel(
    const float* __restrict__ bias0, const float* __restrict__ bias1,
    const float* __restrict__ bias2, float* __restrict__ oout)
{
    extern __shared__ char smem[];
    const uint32_t smem_base = smem_to_u32(smem);
    const int tid = threadIdx.x;
    const int wid = tid >> 5, lane = tid & 31;
    const int wm = wid & 1, wn = wid >> 1;

    int p, b;
    const __nv_bfloat16 *Ah, *Al;
    const float* bias;
    if (MODE == 0) {
        p = blockIdx.z >> 2; b = blockIdx.z & 3;
        Ah = g_Xh + (size_t)p * TTOK * EMBED;
        Al = g_Xl + (size_t)p * TTOK * EMBED;
        bias = (p == 0) ? bias0 : (p == 1) ? bias1 : bias2;
    } else {
        p = 3; b = blockIdx.z;
        Ah = g_AOh; Al = g_AOl;
        bias = bias0;
    }
    const __nv_bfloat16* Bh = g_Wh + (size_t)(p * NB + b) * EBS * EBS;
    const __nv_bfloat16* Bl = g_Wl + (size_t)(p * NB + b) * EBS * EBS;
    const int m0 = blockIdx.y * 128, n0 = blockIdx.x * 128;

    const int lrow = tid >> 1;
    const int lhalf = (tid & 1) * 32;
    const __nv_bfloat16* Arow_h = Ah + (size_t)(m0 + lrow) * EMBED + b * EBS + lhalf;
    const __nv_bfloat16* Arow_l = Al + (size_t)(m0 + lrow) * EMBED + b * EBS + lhalf;
    const __nv_bfloat16* Brow_h = Bh + (size_t)(n0 + lrow) * EBS + lhalf;
    const __nv_bfloat16* Brow_l = Bl + (size_t)(n0 + lrow) * EBS + lhalf;
    uint32_t sw[4];
#pragma unroll
    for (int gix = 0; gix < 4; gix++)
        sw[gix] = SMEM_SWIZZLE_128B((uint32_t)(lrow * 128 + (lhalf + gix * 8) * 2));

#define MM_ISSUE(cc, buf)                                                      \
    do {                                                                       \
        const int _co = (cc) * KCHUNK;                                         \
        const uint32_t _bb = smem_base + (buf) * MMBUF;                        \
        _Pragma("unroll")                                                      \
        for (int gix = 0; gix < 4; gix++) {                                    \
            cpa16(_bb + 0 * TILE_BYTES + sw[gix], Arow_h + _co + gix * 8);     \
            cpa16(_bb + 1 * TILE_BYTES + sw[gix], Arow_l + _co + gix * 8);     \
            cpa16(_bb + 2 * TILE_BYTES + sw[gix], Brow_h + _co + gix * 8);     \
            cpa16(_bb + 3 * TILE_BYTES + sw[gix], Brow_l + _co + gix * 8);     \
        }                                                                      \
    } while (0)

    MM_ISSUE(0, 0);
    CP_COMMIT();
    MM_ISSUE(1, 1);
    CP_COMMIT();

    const int a_row = (lane & 15);
    const int a_c16 = (lane >> 4) * 16;
    const int b_row = (lane & 7) + ((lane >> 4) << 3);
    const int b_c16 = ((lane >> 3) & 1) * 16;

    float acc[4][4][4];
#pragma unroll
    for (int mf = 0; mf < 4; mf++)
#pragma unroll
        for (int nf = 0; nf < 4; nf++)
#pragma unroll
            for (int r = 0; r < 4; r++) acc[mf][nf][r] = 0.f;

    for (int c = 0; c < NCHUNKS; c++) {
        CP_WAIT1();
        __syncthreads();
        const uint32_t bb = smem_base + (c & 1) * MMBUF;
        const uint32_t tAh = bb, tAl = bb + TILE_BYTES;
        const uint32_t tBh = bb + 2 * TILE_BYTES, tBl = bb + 3 * TILE_BYTES;

#pragma unroll
        for (int ks = 0; ks < 4; ks++) {
            uint32_t ah[4][4], al[4][4];
#pragma unroll
            for (int mf = 0; mf < 4; mf++) {
                const uint32_t off = (uint32_t)((wm * 64 + mf * 16 + a_row) * 128
                                                + ks * 32 + a_c16);
                const uint32_t swo = SMEM_SWIZZLE_128B(off);
                ldsm4(ah[mf], tAh + swo);
                ldsm4(al[mf], tAl + swo);
            }
            uint32_t bh[8];
#pragma unroll
            for (int np = 0; np < 2; np++) {
                const uint32_t off = (uint32_t)((wn * 32 + np * 16 + b_row) * 128
                                                + ks * 32 + b_c16);
                ldsm4(&bh[np * 4], tBh + SMEM_SWIZZLE_128B(off));
            }
#pragma unroll
            for (int mf = 0; mf < 4; mf++)
#pragma unroll
                for (int nf = 0; nf < 4; nf++)
                    mma16816(acc[mf][nf], ah[mf], &bh[nf * 2]);
#pragma unroll
            for (int mf = 0; mf < 4; mf++)
#pragma unroll
                for (int nf = 0; nf < 4; nf++)
                    mma16816(acc[mf][nf], al[mf], &bh[nf * 2]);
            uint32_t bl[8];
#pragma unroll
            for (int np = 0; np < 2; np++) {
                const uint32_t off = (uint32_t)((wn * 32 + np * 16 + b_row) * 128
                                                + ks * 32 + b_c16);
                ldsm4(&bl[np * 4], tBl + SMEM_SWIZZLE_128B(off));
            }
#pragma unroll
            for (int mf = 0; mf < 4; mf++)
#pragma unroll
                for (int nf = 0; nf < 4; nf++)
                    mma16816(acc[mf][nf], ah[mf], &bl[nf * 2]);
        }
        __syncthreads();
        if (c + 2 < NCHUNKS)
            MM_ISSUE(c + 2, c & 1);
        CP_COMMIT();
    }
    CP_WAIT0();
    __syncthreads();

    float* stg = (float*)smem;  /* [128][SS] */
    const int gr = lane >> 2, c2 = (lane & 3) * 2;
#pragma unroll
    for (int mf = 0; mf < 4; mf++) {
        const int row0 = wm * 64 + mf * 16 + gr;
#pragma unroll
        for (int nf = 0; nf < 4; nf++) {
            const int col = wn * 32 + nf * 8 + c2;
            *(float2*)&stg[row0 * SS + col]       = make_float2(acc[mf][nf][0], acc[mf][nf][1]);
            *(float2*)&stg[(row0 + 8) * SS + col] = make_float2(acc[mf][nf][2], acc[mf][nf][3]);
        }
    }
    __syncthreads();

    if (MODE == 0) {
        const int n = m0 >> 10, s0 = m0 & (SEQ - 1);
        const int h0 = n0 >> 6;
        if (p >= 1) {
            __nv_bfloat16* oh = (p == 1) ? g_Kh : g_Qh;
            __nv_bfloat16* ol = (p == 1) ? g_Kl : g_Ql;
#pragma unroll
            for (int it = 0; it < 16; it++) {
                const int flat = tid + it * 256;
                const int srow = flat >> 5;
                const int rem = flat & 31;
                const int hh = rem >> 4, dq = (rem & 15) * 4;
                const int ocol = hh * 64 + dq;
                float hi[4], lo[4];
#pragma unroll
                for (int j = 0; j < 4; j++) {
                    const float v = stg[srow * SS + ocol + j]
                                    + bias[b * EBS + n0 + ocol + j];
                    splitf(v, hi[j], lo[j]);
                }
                uint2 hv, lv;
                hv.x = packbf2(hi[0], hi[1]); hv.y = packbf2(hi[2], hi[3]);
                lv.x = packbf2(lo[0], lo[1]); lv.y = packbf2(lo[2], lo[3]);
                const size_t gidx = (size_t)((n * NB + b) * HEADS + h0 + hh);
                const size_t off = (gidx * SEQ + s0 + srow) * HD + dq;
                *(uint2*)(oh + off) = hv;
                *(uint2*)(ol + off) = lv;
            }
        } else {
            const int dcol = tid >> 1;
            const int shalf = (tid & 1) * 64;
            const int hh = dcol >> 6, dl = dcol & 63;
            const size_t gidx = (size_t)((n * NB + b) * HEADS + h0 + hh);
            const float bb = bias[b * EBS + n0 + dcol];
            __nv_bfloat16* oh = g_Vth + (gidx * HD + dl) * SEQ + s0 + shalf;
            __nv_bfloat16* ol = g_Vtl + (gidx * HD + dl) * SEQ + s0 + shalf;
#pragma unroll
            for (int blk = 0; blk < 16; blk++) {
                float hi[4], lo[4];
#pragma unroll
                for (int j = 0; j < 4; j++) {
                    const float v = stg[(shalf + blk * 4 + j) * SS + dcol] + bb;
                    splitf(v, hi[j], lo[j]);
                }
                uint2 hv, lv;
                hv.x = packbf2(hi[0], hi[1]); hv.y = packbf2(hi[2], hi[3]);
                lv.x = packbf2(lo[0], lo[1]); lv.y = packbf2(lo[2], lo[3]);
                *(uint2*)(oh + blk * 4) = hv;
                *(uint2*)(ol + blk * 4) = lv;
            }
        }
    } else {
#pragma unroll
        for (int it = 0; it < 16; it++) {
            const int flat = tid + it * 256;
            const int srow = flat >> 5;
            const int oq = (flat & 31) * 4;
            float4 v;
            v.x = stg[srow * SS + oq + 0] + bias[b * EBS + n0 + oq + 0];
            v.y = stg[srow * SS + oq + 1] + bias[b * EBS + n0 + oq + 1];
            v.z = stg[srow * SS + oq + 2] + bias[b * EBS + n0 + oq + 2];
            v.w = stg[srow * SS + oq + 3] + bias[b * EBS + n0 + oq + 3];
            *(float4*)(oout + (size_t)(m0 + srow) * EMBED + b * EBS + n0 + oq) = v;
        }
    }
}

/* ================================================================== */
/* Energy v2 (unchanged from R11): Q resident, K cp.async streamed.    */
/* ================================================================== */
#define SMEM_ENERGY 98304

__global__ __launch_bounds__(256, 2) void energy_mma_kernel()
{
    extern __shared__ char smem[];
    const uint32_t smem_base = smem_to_u32(smem);
    const int tid = threadIdx.x;
    const int wid = tid >> 5, lane = tid & 31;
    const int wm = wid & 1, wn = wid >> 1;

    const int g  = blockIdx.y;
    const int qt = blockIdx.x;
    const int q0 = qt * 128;
    const int n = g >> 5;

    const uint32_t tQh = smem_base;
    const uint32_t tQl = smem_base + TILE_BYTES;

    const int lrow = tid >> 1;
    const int lhalf = (tid & 1) * 32;
    uint32_t sw[4];
#pragma unroll
    for (int gix = 0; gix < 4; gix++)
        sw[gix] = SMEM_SWIZZLE_128B((uint32_t)(lrow * 128 + (lhalf + gix * 8) * 2));

    const __nv_bfloat16* qh = g_Qh + ((size_t)g * SEQ + q0 + lrow) * HD + lhalf;
    const __nv_bfloat16* ql = g_Ql + ((size_t)g * SEQ + q0 + lrow) * HD + lhalf;
    const __nv_bfloat16* khb = g_Kh + ((size_t)g * SEQ + lrow) * HD + lhalf;
    const __nv_bfloat16* klb = g_Kl + ((size_t)g * SEQ + lrow) * HD + lhalf;

#pragma unroll
    for (int gix = 0; gix < 4; gix++) {
        cpa16(tQh + sw[gix], qh + gix * 8);
        cpa16(tQl + sw[gix], ql + gix * 8);
    }
    {
        const uint32_t kb = smem_base + 2 * TILE_BYTES;
#pragma unroll
        for (int gix = 0; gix < 4; gix++) {
            cpa16(kb + sw[gix], khb + gix * 8);
            cpa16(kb + TILE_BYTES + sw[gix], klb + gix * 8);
        }
    }
    CP_COMMIT();
    {
        const uint32_t kb = smem_base + 4 * TILE_BYTES;
        const size_t so = (size_t)128 * HD;
#pragma unroll
        for (int gix = 0; gix < 4; gix++) {
            cpa16(kb + sw[gix], khb + so + gix * 8);
            cpa16(kb + TILE_BYTES + sw[gix], klb + so + gix * 8);
        }
    }
    CP_COMMIT();

    const int a_row = (lane & 15);
    const int a_c16 = (lane >> 4) * 16;
    const int b_row = (lane & 7) + ((lane >> 4) << 3);
    const int b_c16 = ((lane >> 3) & 1) * 16;
    const int gr = lane >> 2, c2 = (lane & 3) * 2;

    const uint32_t* Mbn = g_Mb + (size_t)n * SEQ * 32;
    __nv_bfloat16* Egh = g_Eh + (size_t)g * SEQ * SEQ;
    __nv_bfloat16* Egl = g_El + (size_t)g * SEQ * SEQ;

    for (int c = 0; c < 8; c++) {
        CP_WAIT1();
        __syncthreads();
        const uint32_t tKh = smem_base + (2 + 2 * (c & 1)) * TILE_BYTES;
        const uint32_t tKl = tKh + TILE_BYTES;

        float acc[4][4][4];
#pragma unroll
        for (int mf = 0; mf < 4; mf++)
#pragma unroll
            for (int nf = 0; nf < 4; nf++)
#pragma unroll
                for (int r = 0; r < 4; r++) acc[mf][nf][r] = 0.f;

#pragma unroll
        for (int ks = 0; ks < 4; ks++) {
            uint32_t ah[4][4], al[4][4];
#pragma unroll
            for (int mf = 0; mf < 4; mf++) {
                const uint32_t off = (uint32_t)((wm * 64 + mf * 16 + a_row) * 128
                                                + ks * 32 + a_c16);
                const uint32_t swo = SMEM_SWIZZLE_128B(off);
                ldsm4(ah[mf], tQh + swo);
                ldsm4(al[mf], tQl + swo);
            }
            uint32_t bh[8];
#pragma unroll
            for (int np = 0; np < 2; np++) {
                const uint32_t off = (uint32_t)((wn * 32 + np * 16 + b_row) * 128
                                                + ks * 32 + b_c16);
                ldsm4(&bh[np * 4], tKh + SMEM_SWIZZLE_128B(off));
            }
#pragma unroll
            for (int mf = 0; mf < 4; mf++)
#pragma unroll
                for (int nf = 0; nf < 4; nf++)
                    mma16816(acc[mf][nf], ah[mf], &bh[nf * 2]);
#pragma unroll
            for (int mf = 0; mf < 4; mf++)
#pragma unroll
                for (int nf = 0; nf < 4; nf++)
                    mma16816(acc[mf][nf], al[mf], &bh[nf * 2]);
            uint32_t bl[8];
#pragma unroll
            for (int np = 0; np < 2; np++) {
                const uint32_t off = (uint32_t)((wn * 32 + np * 16 + b_row) * 128
                                                + ks * 32 + b_c16);
                ldsm4(&bl[np * 4], tKl + SMEM_SWIZZLE_128B(off));
            }
#pragma unroll
            for (int mf = 0; mf < 4; mf++)
#pragma unroll
                for (int nf = 0; nf < 4; nf++)
                    mma16816(acc[mf][nf], ah[mf], &bl[nf * 2]);
        }
        __syncthreads();

        if (c + 2 < 8) {
            const uint32_t kb = smem_base + (2 + 2 * (c & 1)) * TILE_BYTES;
            const size_t so = (size_t)(c + 2) * 128 * HD;
#pragma unroll
            for (int gix = 0; gix < 4; gix++) {
                cpa16(kb + sw[gix], khb + so + gix * 8);
                cpa16(kb + TILE_BYTES + sw[gix], klb + so + gix * 8);
            }
        }
        CP_COMMIT();

        const int l0 = c * 128;
        const int cw = c * 4 + wn;
        float csum[4][2];
#pragma unroll
        for (int nf = 0; nf < 4; nf++) { csum[nf][0] = 0.f; csum[nf][1] = 0.f; }

#pragma unroll
        for (int mf = 0; mf < 4; mf++) {
#pragma unroll
            for (int half = 0; half < 2; half++) {
                const int q = q0 + wm * 64 + mf * 16 + gr + half * 8;
                const uint32_t w = Mbn[q * 32 + cw];
#pragma unroll
                for (int nf = 0; nf < 4; nf++) {
                    const int col = l0 + wn * 32 + nf * 8 + c2;
                    const uint32_t bits = (w >> (nf * 8 + c2)) & 3u;
                    float2 e;
                    e.x = (bits & 1u) ? __expf(acc[mf][nf][half * 2 + 0] * 0.125f) : 0.f;
                    e.y = (bits & 2u) ? __expf(acc[mf][nf][half * 2 + 1] * 0.125f) : 0.f;
                    float h0, lo0, h1, lo1;
                    splitf(e.x, h0, lo0);
                    splitf(e.y, h1, lo1);
                    *(uint32_t*)(Egh + (size_t)q * SEQ + col) = packbf2(h0, h1);
                    *(uint32_t*)(Egl + (size_t)q * SEQ + col) = packbf2(lo0, lo1);
                    csum[nf][0] += e.x;
                    csum[nf][1] += e.y;
                }
            }
        }
        float* Zp = g_Zp[qt * 2 + wm] + g * SEQ;
#pragma unroll
        for (int nf = 0; nf < 4; nf++) {
#pragma unroll
            for (int cc = 0; cc < 2; cc++) {
                float v = csum[nf][cc];
                v += __shfl_xor_sync(0xffffffffu, v, 4);
                v += __shfl_xor_sync(0xffffffffu, v, 8);
                v += __shfl_xor_sync(0xffffffffu, v, 16);
                if (gr == 0)
                    Zp[l0 + wn * 32 + nf * 8 + c2 + cc] = v;
            }
        }
    }
}

/* ================================================================== */
__global__ __launch_bounds__(256) void zred_kernel()
{
    const int i = blockIdx.x * 256 + threadIdx.x;
    float z = 0.f;
#pragma unroll
    for (int s = 0; s < 16; s++)
        z += g_Zp[s][i];
    g_Zi[i] = (z > 0.f) ? (1.f / z) : 0.f;
}

/* ================================================================== */
__global__ __launch_bounds__(256) void vscale_kernel()
{
    const size_t e = ((size_t)blockIdx.x * 256 + threadIdx.x) * 8;
    const int g = (int)(e / ((size_t)HD * SEQ));
    const int s = (int)(e % SEQ);
    float4 z0 = *(const float4*)(g_Zi + g * SEQ + s);
    float4 z1 = *(const float4*)(g_Zi + g * SEQ + s + 4);
    const float zz[8] = {z0.x, z0.y, z0.z, z0.w, z1.x, z1.y, z1.z, z1.w};
    uint4 vh = *(const uint4*)(g_Vth + e);
    uint4 vl = *(const uint4*)(g_Vtl + e);
    const uint32_t hw[4] = {vh.x, vh.y, vh.z, vh.w};
    const uint32_t lw[4] = {vl.x, vl.y, vl.z, vl.w};
    uint32_t oh[4], ol[4];
#pragma unroll
    for (int j = 0; j < 4; j++) {
        float2 fh = upk(hw[j]);
        float2 fl = upk(lw[j]);
        const float a = (fh.x + fl.x) * zz[2 * j];
        const float b = (fh.y + fl.y) * zz[2 * j + 1];
        float ah, alo, bh, blo;
        splitf(a, ah, alo);
        splitf(b, bh, blo);
        oh[j] = packbf2(ah, bh);
        ol[j] = packbf2(alo, blo);
    }
    *(uint4*)(g_Vth + e) = make_uint4(oh[0], oh[1], oh[2], oh[3]);
    *(uint4*)(g_Vtl + e) = make_uint4(ol[0], ol[1], ol[2], ol[3]);
}

/* ================================================================== */
/* AV v2 (unchanged from R11): pure GEMM, cp.async double-buffered.    */
/* ================================================================== */
#define AVBUF 49152
#define SMEM_AV (2 * AVBUF)

__global__ __launch_bounds__(256, 2) void av_mma_kernel()
{
    extern __shared__ char smem[];
    const uint32_t smem_base = smem_to_u32(smem);
    const int tid = threadIdx.x;
    const int wid = tid >> 5, lane = tid & 31;
    const int wm = wid >> 1, wn = wid & 1;

    const int g  = blockIdx.y;
    const int q0 = blockIdx.x * 128;

    const int erow = tid >> 1;
    const int ebyte = (tid & 1) * 64;
    const __nv_bfloat16* ehb = g_Eh + ((size_t)g * SEQ + q0 + erow) * SEQ + ebyte / 2;
    const __nv_bfloat16* elb = g_El + ((size_t)g * SEQ + q0 + erow) * SEQ + ebyte / 2;
    uint32_t esw[4];
#pragma unroll
    for (int gix = 0; gix < 4; gix++)
        esw[gix] = SMEM_SWIZZLE_128B((uint32_t)(erow * 128 + ebyte + gix * 16));

    const int vrow = tid >> 2;
    const int vbyte = (tid & 3) * 32;
    const __nv_bfloat16* vhb = g_Vth + ((size_t)g * HD + vrow) * SEQ + vbyte / 2;
    const __nv_bfloat16* vlb = g_Vtl + ((size_t)g * HD + vrow) * SEQ + vbyte / 2;
    uint32_t vsw[2];
#pragma unroll
    for (int j = 0; j < 2; j++)
        vsw[j] = SMEM_SWIZZLE_128B((uint32_t)(vrow * 128 + vbyte + j * 16));

#define AV_ISSUE(cc, buf)                                                      \
    do {                                                                       \
        const int _l0 = (cc) * 64;                                             \
        const uint32_t _bb = smem_base + (buf) * AVBUF;                        \
        _Pragma("unroll")                                                      \
        for (int gix = 0; gix < 4; gix++) {                                    \
            cpa16(_bb + esw[gix], ehb + _l0 + gix * 8);                        \
            cpa16(_bb + 16384 + esw[gix], elb + _l0 + gix * 8);                \
        }                                                                      \
        _Pragma("unroll")                                                      \
        for (int j = 0; j < 2; j++) {                                          \
            cpa16(_bb + 32768 + vsw[j], vhb + _l0 + j * 8);                    \
            cpa16(_bb + 40960 + vsw[j], vlb + _l0 + j * 8);                    \
        }                                                                      \
    } while (0)

    AV_ISSUE(0, 0);
    CP_COMMIT();
    AV_ISSUE(1, 1);
    CP_COMMIT();

    const int a_row = (lane & 15);
    const int a_c16 = (lane >> 4) * 16;
    const int b_row = (lane & 7) + ((lane >> 4) << 3);
    const int b_c16 = ((lane >> 3) & 1) * 16;

    float acc[2][4][4];
#pragma unroll
    for (int mf = 0; mf < 2; mf++)
#pragma unroll
        for (int nf = 0; nf < 4; nf++)
#pragma unroll
            for (int r = 0; r < 4; r++) acc[mf][nf][r] = 0.f;

    for (int c = 0; c < 16; c++) {
        CP_WAIT1();
        __syncthreads();
        const uint32_t bb = smem_base + (c & 1) * AVBUF;
        const uint32_t tEh = bb, tEl = bb + 16384;
        const uint32_t tVh = bb + 32768, tVl = bb + 40960;

#pragma unroll
        for (int ks = 0; ks < 4; ks++) {
            uint32_t ah[2][4], al[2][4];
#pragma unroll
            for (int mf = 0; mf < 2; mf++) {
                const uint32_t off = (uint32_t)((wm * 32 + mf * 16 + a_row) * 128
                                                + ks * 32 + a_c16);
                const uint32_t swo = SMEM_SWIZZLE_128B(off);
                ldsm4(ah[mf], tEh + swo);
                ldsm4(al[mf], tEl + swo);
            }
            uint32_t bh[8];
#pragma unroll
            for (int np = 0; np < 2; np++) {
                const uint32_t off = (uint32_t)((wn * 32 + np * 16 + b_row) * 128
                                                + ks * 32 + b_c16);
                ldsm4(&bh[np * 4], tVh + SMEM_SWIZZLE_128B(off));
            }
#pragma unroll
            for (int mf = 0; mf < 2; mf++)
#pragma unroll
                for (int nf = 0; nf < 4; nf++)
                    mma16816(acc[mf][nf], ah[mf], &bh[nf * 2]);
#pragma unroll
            for (int mf = 0; mf < 2; mf++)
#pragma unroll
                for (int nf = 0; nf < 4; nf++)
                    mma16816(acc[mf][nf], al[mf], &bh[nf * 2]);
            uint32_t bl[8];
#pragma unroll
            for (int np = 0; np < 2; np++) {
                const uint32_t off = (uint32_t)((wn * 32 + np * 16 + b_row) * 128
                                                + ks * 32 + b_c16);
                ldsm4(&bl[np * 4], tVl + SMEM_SWIZZLE_128B(off));
            }
#pragma unroll
            for (int mf = 0; mf < 2; mf++)
#pragma unroll
                for (int nf = 0; nf < 4; nf++)
                    mma16816(acc[mf][nf], ah[mf], &bl[nf * 2]);
        }
        __syncthreads();
        if (c + 2 < 16)
            AV_ISSUE(c + 2, c & 1);
        CP_COMMIT();
    }

    const int n = g >> 5, b = (g >> 3) & 3, hd = g & 7;
    const int gr = lane >> 2, c2 = (lane & 3) * 2;
#pragma unroll
    for (int mf = 0; mf < 2; mf++) {
#pragma unroll
        for (int nf = 0; nf < 4; nf++) {
            const int d = wn * 32 + nf * 8 + c2;
#pragma unroll
            for (int half = 0; half < 2; half++) {
                const int q = q0 + wm * 32 + mf * 16 + gr + half * 8;
                const size_t t = (size_t)(n * SEQ + q);
                const size_t off = t * EMBED + b * EBS + hd * HD + d;
                float h0, l0f, h1, l1;
                splitf(acc[mf][nf][half * 2 + 0], h0, l0f);
                splitf(acc[mf][nf][half * 2 + 1], h1, l1);
                *(uint32_t*)(g_AOh + off) = packbf2(h0, h1);
                *(uint32_t*)(g_AOl + off) = packbf2(l0f, l1);
            }
        }
    }
}

/* ------------------------------------------------------------------ */
extern "C" void kernel_launch(void* const* d_in, const int* in_sizes, int n_in,
                              void* d_out, int out_size)
{
    const float* values = (const float*)d_in[0];
    const float* keys   = (const float*)d_in[1];
    const float* query  = (const float*)d_in[2];
    const int*   mask   = (const int*)d_in[3];
    const float* Wv = (const float*)d_in[4];
    const float* bv = (const float*)d_in[5];
    const float* Wk = (const float*)d_in[6];
    const float* bk = (const float*)d_in[7];
    const float* Wq = (const float*)d_in[8];
    const float* bq = (const float*)d_in[9];
    const float* Wo = (const float*)d_in[10];
    const float* bo = (const float*)d_in[11];
    float* out = (float*)d_out;

    cudaFuncSetAttribute(mm_kernel<0>, cudaFuncAttributeMaxDynamicSharedMemorySize,
                         SMEM_GEMM_TOTAL);
    cudaFuncSetAttribute(mm_kernel<1>, cudaFuncAttributeMaxDynamicSharedMemorySize,
                         SMEM_GEMM_TOTAL);
    cudaFuncSetAttribute(energy_mma_kernel, cudaFuncAttributeMaxDynamicSharedMemorySize,
                         SMEM_ENERGY);
    cudaFuncSetAttribute(av_mma_kernel, cudaFuncAttributeMaxDynamicSharedMemorySize,
                         SMEM_AV);

    /* converts */
    dim3 gx((TTOK * EMBED) / (256 * 4), 3);
    convx_kernel<<<gx, 256>>>(values, keys, query);
    dim3 gw(EBS / 32, EBS / 32, 16);
    convw_kernel<<<gw, dim3(32, 8)>>>(Wv, Wk, Wq, Wo);
    convm_kernel<<<(NBATCH * SEQ) / 8, 256>>>(mask);

    /* fused qkv projections (tensor, pipelined) */
    dim3 gqkv(EBS / 128, TTOK / 128, 12);
    mm_kernel<0><<<gqkv, 256, SMEM_GEMM_TOTAL>>>(bv, bk, bq, nullptr);

    /* energy + exp + column partial sums (tensor, pipelined) */
    dim3 ge(SEQ / 128, NG);
    energy_mma_kernel<<<ge, 256, SMEM_ENERGY>>>();

    /* reduce partials -> 1/Z, fold into V */
    zred_kernel<<<(NG * SEQ) / 256, 256>>>();
    vscale_kernel<<<(NG * HD * SEQ) / (256 * 8), 256>>>();

    /* AV (tensor, pipelined) */
    dim3 ga(SEQ / 128, NG);
    av_mma_kernel<<<ga, 256, SMEM_AV>>>();

    /* output projection (tensor, pipelined) */
    dim3 go(EBS / 128, TTOK / 128, NB);
    mm_kernel<1><<<go, 256, SMEM_GEMM_TOTAL>>>(bo, nullptr, nullptr, out);
}

// round 13
// speedup vs baseline: 3.1245x; 1.0650x over previous
#include <cuda_runtime.h>
#include <cuda_bf16.h>
#include <math.h>
#include <stdint.h>

#define NBATCH 4
#define SEQ    1024
#define EMBED  2048
#define EBS    512
#define NB     4
#define HEADS  8
#define HD     64
#define TTOK   (NBATCH * SEQ)        /* 4096 tokens */
#define NG     (NBATCH * NB * HEADS) /* 128 (n,b,h) heads */

typedef unsigned long long u64;

#define SMEM_SWIZZLE_128B(off) ((off) ^ (((off) >> 3) & 0x70))

/* ================================================================== */
/* Tensor / async helpers (sm_80 path: legal on base sm_103 target)    */
/* ================================================================== */
__device__ __forceinline__ uint32_t smem_to_u32(const void* p) {
    uint32_t a;
    asm("{ .reg .u64 t; cvta.to.shared.u64 t, %1; cvt.u32.u64 %0, t; }"
        : "=r"(a) : "l"(p));
    return a;
}
__device__ __forceinline__ void ldsm4(uint32_t* r, uint32_t addr) {
    asm volatile("ldmatrix.sync.aligned.m8n8.x4.shared.b16 {%0,%1,%2,%3}, [%4];"
                 : "=r"(r[0]), "=r"(r[1]), "=r"(r[2]), "=r"(r[3]) : "r"(addr));
}
__device__ __forceinline__ void mma16816(float* d, const uint32_t* a,
                                         const uint32_t* b) {
    asm volatile(
        "mma.sync.aligned.m16n8k16.row.col.f32.bf16.bf16.f32 "
        "{%0,%1,%2,%3}, {%4,%5,%6,%7}, {%8,%9}, {%0,%1,%2,%3};"
        : "+f"(d[0]), "+f"(d[1]), "+f"(d[2]), "+f"(d[3])
        : "r"(a[0]), "r"(a[1]), "r"(a[2]), "r"(a[3]), "r"(b[0]), "r"(b[1]));
}
__device__ __forceinline__ void cpa16(uint32_t dst, const void* src) {
    asm volatile("cp.async.cg.shared.global [%0], [%1], 16;"
                 :: "r"(dst), "l"(src) : "memory");
}
#define CP_COMMIT() asm volatile("cp.async.commit_group;" ::: "memory")
#define CP_WAIT1()  asm volatile("cp.async.wait_group 1;" ::: "memory")
#define CP_WAIT0()  asm volatile("cp.async.wait_group 0;" ::: "memory")
__device__ __forceinline__ uint32_t packbf2(float a, float b) {
    __nv_bfloat162 p = __floats2bfloat162_rn(a, b);
    return *(uint32_t*)&p;
}
__device__ __forceinline__ void splitf(float v, float& hi, float& lo) {
    __nv_bfloat16 hb = __float2bfloat16_rn(v);
    hi = __bfloat162float(hb);
    lo = v - hi;
}
__device__ __forceinline__ float2 upk(uint32_t u) {
    __nv_bfloat162 b = *(__nv_bfloat162*)&u;
    return __bfloat1622float2(b);
}

/* ================================================================== */
/* Device scratch                                                      */
/* ================================================================== */
__device__ __align__(256) __nv_bfloat16 g_Eh[(size_t)NG * SEQ * SEQ]; /* 256 MB */
__device__ __align__(256) __nv_bfloat16 g_El[(size_t)NG * SEQ * SEQ]; /* 256 MB */
__device__ __align__(256) float g_Zp[16][NG * SEQ];
__device__ float g_Zi[NG * SEQ];
__device__ __align__(256) uint32_t g_Mb[NBATCH * SEQ * 32];           /* bit mask */
__device__ __align__(256) __nv_bfloat16 g_Xh[(size_t)3 * TTOK * EMBED];
__device__ __align__(256) __nv_bfloat16 g_Xl[(size_t)3 * TTOK * EMBED];
__device__ __align__(256) __nv_bfloat16 g_AOh[(size_t)TTOK * EMBED];
__device__ __align__(256) __nv_bfloat16 g_AOl[(size_t)TTOK * EMBED];
__device__ __align__(256) __nv_bfloat16 g_Wh[(size_t)4 * NB * EBS * EBS];
__device__ __align__(256) __nv_bfloat16 g_Wl[(size_t)4 * NB * EBS * EBS];
__device__ __align__(256) __nv_bfloat16 g_Qh[(size_t)NG * SEQ * HD];
__device__ __align__(256) __nv_bfloat16 g_Ql[(size_t)NG * SEQ * HD];
__device__ __align__(256) __nv_bfloat16 g_Kh[(size_t)NG * SEQ * HD];
__device__ __align__(256) __nv_bfloat16 g_Kl[(size_t)NG * SEQ * HD];
__device__ __align__(256) __nv_bfloat16 g_Vth[(size_t)NG * HD * SEQ]; /* [g][d][s] */
__device__ __align__(256) __nv_bfloat16 g_Vtl[(size_t)NG * HD * SEQ];

/* ================================================================== */
/* Converters                                                          */
/* ================================================================== */
__global__ __launch_bounds__(256) void convx_kernel(
    const float* __restrict__ V, const float* __restrict__ K,
    const float* __restrict__ Q)
{
    const int p = blockIdx.y;
    const float* src = (p == 0) ? V : (p == 1) ? K : Q;
    __nv_bfloat16* dh = g_Xh + (size_t)p * TTOK * EMBED;
    __nv_bfloat16* dl = g_Xl + (size_t)p * TTOK * EMBED;
    const size_t i = ((size_t)blockIdx.x * 256 + threadIdx.x) * 4;
    float4 v = *(const float4*)(src + i);
    float f[4] = {v.x, v.y, v.z, v.w};
    float hi[4], lo[4];
#pragma unroll
    for (int j = 0; j < 4; j++) splitf(f[j], hi[j], lo[j]);
    uint2 hv, lv;
    hv.x = packbf2(hi[0], hi[1]); hv.y = packbf2(hi[2], hi[3]);
    lv.x = packbf2(lo[0], lo[1]); lv.y = packbf2(lo[2], lo[3]);
    *(uint2*)(dh + i) = hv;
    *(uint2*)(dl + i) = lv;
}

__global__ __launch_bounds__(256) void convw_kernel(
    const float* __restrict__ Wv, const float* __restrict__ Wk,
    const float* __restrict__ Wq, const float* __restrict__ Wo)
{
    __shared__ float st[32][33];
    const int z = blockIdx.z;
    const int wi = z >> 2, b = z & 3;
    const float* W = ((wi == 0) ? Wv : (wi == 1) ? Wk : (wi == 2) ? Wq : Wo)
                     + (size_t)b * EBS * EBS;
    const int i0 = blockIdx.y * 32, o0 = blockIdx.x * 32;
    const int tx = threadIdx.x, ty = threadIdx.y;
#pragma unroll
    for (int kk = 0; kk < 4; kk++)
        st[ty + 8 * kk][tx] = W[(size_t)(i0 + ty + 8 * kk) * EBS + o0 + tx];
    __syncthreads();
    __nv_bfloat16* oh = g_Wh + (size_t)(wi * NB + b) * EBS * EBS;
    __nv_bfloat16* ol = g_Wl + (size_t)(wi * NB + b) * EBS * EBS;
#pragma unroll
    for (int kk = 0; kk < 4; kk++) {
        const float v = st[tx][ty + 8 * kk];
        float h, l;
        splitf(v, h, l);
        const size_t off = (size_t)(o0 + ty + 8 * kk) * EBS + i0 + tx;
        oh[off] = __float2bfloat16_rn(h);
        ol[off] = __float2bfloat16_rn(l);
    }
}

/* pack mask int32 -> bits */
__global__ __launch_bounds__(256) void convm_kernel(const int* __restrict__ mask)
{
    const int wid = threadIdx.x >> 5, lane = threadIdx.x & 31;
    const int r = blockIdx.x * 8 + wid;
    const int* row = mask + (size_t)r * SEQ;
    uint32_t* orow = g_Mb + (size_t)r * 32;
    for (int w = 0; w < 32; w++) {
        const int m = row[w * 32 + lane];
        const uint32_t bits = __ballot_sync(0xffffffffu, m != 0);
        if (lane == 0) orow[w] = bits;
    }
}

/* ================================================================== */
/* mma.sync bf16 3-split projection GEMM.                              */
/* 512 threads (16 warps as 4m x 4n, warp tile 32x32), 128x128 CTA     */
/* tile, K=512 in 8 chunks of 64, 3-stage cp.async ring, single        */
/* __syncthreads per chunk.                                            */
/* ================================================================== */
#define KCHUNK 64
#define NCHUNKS 8
#define TILE_BYTES 16384
#define MMBUF (4 * TILE_BYTES)            /* 64 KB per chunk buffer */
#define SS 132
#define SMEM_GEMM_TOTAL (3 * MMBUF)       /* 192 KB */

template <int MODE>
__global__ __launch_bounds__(512) void mm_kernel(
    const float* __restrict__ bias0, const float* __restrict__ bias1,
    const float* __restrict__ bias2, float* __restrict__ oout)
{
    extern __shared__ char smem[];
    const uint32_t smem_base = smem_to_u32(smem);
    const int tid = threadIdx.x;
    const int wid = tid >> 5, lane = tid & 31;
    const int wm = wid & 3, wn = wid >> 2;   /* 4x4 warp grid, 32x32 tiles */

    int p, b;
    const __nv_bfloat16 *Ah, *Al;
    const float* bias;
    if (MODE == 0) {
        p = blockIdx.z >> 2; b = blockIdx.z & 3;
        Ah = g_Xh + (size_t)p * TTOK * EMBED;
        Al = g_Xl + (size_t)p * TTOK * EMBED;
        bias = (p == 0) ? bias0 : (p == 1) ? bias1 : bias2;
    } else {
        p = 3; b = blockIdx.z;
        Ah = g_AOh; Al = g_AOl;
        bias = bias0;
    }
    const __nv_bfloat16* Bh = g_Wh + (size_t)(p * NB + b) * EBS * EBS;
    const __nv_bfloat16* Bl = g_Wl + (size_t)(p * NB + b) * EBS * EBS;
    const int m0 = blockIdx.y * 128, n0 = blockIdx.x * 128;

    /* loaders: 512 threads, each 32B per 16KB tile (2 x cpa16) */
    const int lrow = tid >> 2;
    const int lseg = (tid & 3) * 16;          /* bf16 elems */
    const __nv_bfloat16* Arow_h = Ah + (size_t)(m0 + lrow) * EMBED + b * EBS + lseg;
    const __nv_bfloat16* Arow_l = Al + (size_t)(m0 + lrow) * EMBED + b * EBS + lseg;
    const __nv_bfloat16* Brow_h = Bh + (size_t)(n0 + lrow) * EBS + lseg;
    const __nv_bfloat16* Brow_l = Bl + (size_t)(n0 + lrow) * EBS + lseg;
    uint32_t sw[2];
#pragma unroll
    for (int j = 0; j < 2; j++)
        sw[j] = SMEM_SWIZZLE_128B((uint32_t)(lrow * 128 + (lseg + j * 8) * 2));

#define MM_ISSUE(cc, buf)                                                      \
    do {                                                                       \
        const int _co = (cc) * KCHUNK;                                         \
        const uint32_t _bb = smem_base + (buf) * MMBUF;                        \
        _Pragma("unroll")                                                      \
        for (int j = 0; j < 2; j++) {                                          \
            cpa16(_bb + 0 * TILE_BYTES + sw[j], Arow_h + _co + j * 8);         \
            cpa16(_bb + 1 * TILE_BYTES + sw[j], Arow_l + _co + j * 8);         \
            cpa16(_bb + 2 * TILE_BYTES + sw[j], Brow_h + _co + j * 8);         \
            cpa16(_bb + 3 * TILE_BYTES + sw[j], Brow_l + _co + j * 8);         \
        }                                                                      \
    } while (0)

    MM_ISSUE(0, 0);
    CP_COMMIT();
    MM_ISSUE(1, 1);
    CP_COMMIT();

    const int a_row = (lane & 15);
    const int a_c16 = (lane >> 4) * 16;
    const int b_row = (lane & 7) + ((lane >> 4) << 3);
    const int b_c16 = ((lane >> 3) & 1) * 16;

    float acc[2][4][4];
#pragma unroll
    for (int mf = 0; mf < 2; mf++)
#pragma unroll
        for (int nf = 0; nf < 4; nf++)
#pragma unroll
            for (int r = 0; r < 4; r++) acc[mf][nf][r] = 0.f;

    int rbuf = 0;
    for (int c = 0; c < NCHUNKS; c++) {
        CP_WAIT1();
        __syncthreads();
        /* issue chunk c+2 first (overlaps with mma below); its buffer was
           consumed in iteration c-1, safe after the barrier above. */
        if (c + 2 < NCHUNKS) {
            const int ibuf = (rbuf + 2 >= 3) ? rbuf + 2 - 3 : rbuf + 2;
            MM_ISSUE(c + 2, ibuf);
        }
        CP_COMMIT();

        const uint32_t bb = smem_base + rbuf * MMBUF;
        const uint32_t tAh = bb, tAl = bb + TILE_BYTES;
        const uint32_t tBh = bb + 2 * TILE_BYTES, tBl = bb + 3 * TILE_BYTES;

#pragma unroll
        for (int ks = 0; ks < 4; ks++) {
            uint32_t ah[2][4], al[2][4];
#pragma unroll
            for (int mf = 0; mf < 2; mf++) {
                const uint32_t off = (uint32_t)((wm * 32 + mf * 16 + a_row) * 128
                                                + ks * 32 + a_c16);
                const uint32_t swo = SMEM_SWIZZLE_128B(off);
                ldsm4(ah[mf], tAh + swo);
                ldsm4(al[mf], tAl + swo);
            }
            uint32_t bh[8];
#pragma unroll
            for (int np = 0; np < 2; np++) {
                const uint32_t off = (uint32_t)((wn * 32 + np * 16 + b_row) * 128
                                                + ks * 32 + b_c16);
                ldsm4(&bh[np * 4], tBh + SMEM_SWIZZLE_128B(off));
            }
#pragma unroll
            for (int mf = 0; mf < 2; mf++)
#pragma unroll
                for (int nf = 0; nf < 4; nf++)
                    mma16816(acc[mf][nf], ah[mf], &bh[nf * 2]);
#pragma unroll
            for (int mf = 0; mf < 2; mf++)
#pragma unroll
                for (int nf = 0; nf < 4; nf++)
                    mma16816(acc[mf][nf], al[mf], &bh[nf * 2]);
            uint32_t bl[8];
#pragma unroll
            for (int np = 0; np < 2; np++) {
                const uint32_t off = (uint32_t)((wn * 32 + np * 16 + b_row) * 128
                                                + ks * 32 + b_c16);
                ldsm4(&bl[np * 4], tBl + SMEM_SWIZZLE_128B(off));
            }
#pragma unroll
            for (int mf = 0; mf < 2; mf++)
#pragma unroll
                for (int nf = 0; nf < 4; nf++)
                    mma16816(acc[mf][nf], ah[mf], &bl[nf * 2]);
        }
        rbuf = (rbuf + 1 >= 3) ? 0 : rbuf + 1;
    }
    CP_WAIT0();
    __syncthreads();

    float* stg = (float*)smem;  /* [128][SS] */
    const int gr = lane >> 2, c2 = (lane & 3) * 2;
#pragma unroll
    for (int mf = 0; mf < 2; mf++) {
        const int row0 = wm * 32 + mf * 16 + gr;
#pragma unroll
        for (int nf = 0; nf < 4; nf++) {
            const int col = wn * 32 + nf * 8 + c2;
            *(float2*)&stg[row0 * SS + col]       = make_float2(acc[mf][nf][0], acc[mf][nf][1]);
            *(float2*)&stg[(row0 + 8) * SS + col] = make_float2(acc[mf][nf][2], acc[mf][nf][3]);
        }
    }
    __syncthreads();

    if (MODE == 0) {
        const int n = m0 >> 10, s0 = m0 & (SEQ - 1);
        const int h0 = n0 >> 6;
        if (p >= 1) {
            __nv_bfloat16* oh = (p == 1) ? g_Kh : g_Qh;
            __nv_bfloat16* ol = (p == 1) ? g_Kl : g_Ql;
#pragma unroll
            for (int it = 0; it < 8; it++) {
                const int flat = tid + it * 512;
                const int srow = flat >> 5;
                const int rem = flat & 31;
                const int hh = rem >> 4, dq = (rem & 15) * 4;
                const int ocol = hh * 64 + dq;
                float hi[4], lo[4];
#pragma unroll
                for (int j = 0; j < 4; j++) {
                    const float v = stg[srow * SS + ocol + j]
                                    + bias[b * EBS + n0 + ocol + j];
                    splitf(v, hi[j], lo[j]);
                }
                uint2 hv, lv;
                hv.x = packbf2(hi[0], hi[1]); hv.y = packbf2(hi[2], hi[3]);
                lv.x = packbf2(lo[0], lo[1]); lv.y = packbf2(lo[2], lo[3]);
                const size_t gidx = (size_t)((n * NB + b) * HEADS + h0 + hh);
                const size_t off = (gidx * SEQ + s0 + srow) * HD + dq;
                *(uint2*)(oh + off) = hv;
                *(uint2*)(ol + off) = lv;
            }
        } else {
            /* V: bf16 hi/lo transposed [g][d][s] */
            const int dcol = tid >> 2;
            const int squarter = (tid & 3) * 32;
            const int hh = dcol >> 6, dl = dcol & 63;
            const size_t gidx = (size_t)((n * NB + b) * HEADS + h0 + hh);
            const float bb = bias[b * EBS + n0 + dcol];
            __nv_bfloat16* oh = g_Vth + (gidx * HD + dl) * SEQ + s0 + squarter;
            __nv_bfloat16* ol = g_Vtl + (gidx * HD + dl) * SEQ + s0 + squarter;
#pragma unroll
            for (int blk = 0; blk < 8; blk++) {
                float hi[4], lo[4];
#pragma unroll
                for (int j = 0; j < 4; j++) {
                    const float v = stg[(squarter + blk * 4 + j) * SS + dcol] + bb;
                    splitf(v, hi[j], lo[j]);
                }
                uint2 hv, lv;
                hv.x = packbf2(hi[0], hi[1]); hv.y = packbf2(hi[2], hi[3]);
                lv.x = packbf2(lo[0], lo[1]); lv.y = packbf2(lo[2], lo[3]);
                *(uint2*)(oh + blk * 4) = hv;
                *(uint2*)(ol + blk * 4) = lv;
            }
        }
    } else {
#pragma unroll
        for (int it = 0; it < 8; it++) {
            const int flat = tid + it * 512;
            const int srow = flat >> 5;
            const int oq = (flat & 31) * 4;
            float4 v;
            v.x = stg[srow * SS + oq + 0] + bias[b * EBS + n0 + oq + 0];
            v.y = stg[srow * SS + oq + 1] + bias[b * EBS + n0 + oq + 1];
            v.z = stg[srow * SS + oq + 2] + bias[b * EBS + n0 + oq + 2];
            v.w = stg[srow * SS + oq + 3] + bias[b * EBS + n0 + oq + 3];
            *(float4*)(oout + (size_t)(m0 + srow) * EMBED + b * EBS + n0 + oq) = v;
        }
    }
}

/* ================================================================== */
/* Energy v2 (unchanged): Q resident, K cp.async streamed.             */
/* ================================================================== */
#define SMEM_ENERGY 98304

__global__ __launch_bounds__(256, 2) void energy_mma_kernel()
{
    extern __shared__ char smem[];
    const uint32_t smem_base = smem_to_u32(smem);
    const int tid = threadIdx.x;
    const int wid = tid >> 5, lane = tid & 31;
    const int wm = wid & 1, wn = wid >> 1;

    const int g  = blockIdx.y;
    const int qt = blockIdx.x;
    const int q0 = qt * 128;
    const int n = g >> 5;

    const uint32_t tQh = smem_base;
    const uint32_t tQl = smem_base + TILE_BYTES;

    const int lrow = tid >> 1;
    const int lhalf = (tid & 1) * 32;
    uint32_t sw[4];
#pragma unroll
    for (int gix = 0; gix < 4; gix++)
        sw[gix] = SMEM_SWIZZLE_128B((uint32_t)(lrow * 128 + (lhalf + gix * 8) * 2));

    const __nv_bfloat16* qh = g_Qh + ((size_t)g * SEQ + q0 + lrow) * HD + lhalf;
    const __nv_bfloat16* ql = g_Ql + ((size_t)g * SEQ + q0 + lrow) * HD + lhalf;
    const __nv_bfloat16* khb = g_Kh + ((size_t)g * SEQ + lrow) * HD + lhalf;
    const __nv_bfloat16* klb = g_Kl + ((size_t)g * SEQ + lrow) * HD + lhalf;

#pragma unroll
    for (int gix = 0; gix < 4; gix++) {
        cpa16(tQh + sw[gix], qh + gix * 8);
        cpa16(tQl + sw[gix], ql + gix * 8);
    }
    {
        const uint32_t kb = smem_base + 2 * TILE_BYTES;
#pragma unroll
        for (int gix = 0; gix < 4; gix++) {
            cpa16(kb + sw[gix], khb + gix * 8);
            cpa16(kb + TILE_BYTES + sw[gix], klb + gix * 8);
        }
    }
    CP_COMMIT();
    {
        const uint32_t kb = smem_base + 4 * TILE_BYTES;
        const size_t so = (size_t)128 * HD;
#pragma unroll
        for (int gix = 0; gix < 4; gix++) {
            cpa16(kb + sw[gix], khb + so + gix * 8);
            cpa16(kb + TILE_BYTES + sw[gix], klb + so + gix * 8);
        }
    }
    CP_COMMIT();

    const int a_row = (lane & 15);
    const int a_c16 = (lane >> 4) * 16;
    const int b_row = (lane & 7) + ((lane >> 4) << 3);
    const int b_c16 = ((lane >> 3) & 1) * 16;
    const int gr = lane >> 2, c2 = (lane & 3) * 2;

    const uint32_t* Mbn = g_Mb + (size_t)n * SEQ * 32;
    __nv_bfloat16* Egh = g_Eh + (size_t)g * SEQ * SEQ;
    __nv_bfloat16* Egl = g_El + (size_t)g * SEQ * SEQ;

    for (int c = 0; c < 8; c++) {
        CP_WAIT1();
        __syncthreads();
        const uint32_t tKh = smem_base + (2 + 2 * (c & 1)) * TILE_BYTES;
        const uint32_t tKl = tKh + TILE_BYTES;

        float acc[4][4][4];
#pragma unroll
        for (int mf = 0; mf < 4; mf++)
#pragma unroll
            for (int nf = 0; nf < 4; nf++)
#pragma unroll
                for (int r = 0; r < 4; r++) acc[mf][nf][r] = 0.f;

#pragma unroll
        for (int ks = 0; ks < 4; ks++) {
            uint32_t ah[4][4], al[4][4];
#pragma unroll
            for (int mf = 0; mf < 4; mf++) {
                const uint32_t off = (uint32_t)((wm * 64 + mf * 16 + a_row) * 128
                                                + ks * 32 + a_c16);
                const uint32_t swo = SMEM_SWIZZLE_128B(off);
                ldsm4(ah[mf], tQh + swo);
                ldsm4(al[mf], tQl + swo);
            }
            uint32_t bh[8];
#pragma unroll
            for (int np = 0; np < 2; np++) {
                const uint32_t off = (uint32_t)((wn * 32 + np * 16 + b_row) * 128
                                                + ks * 32 + b_c16);
                ldsm4(&bh[np * 4], tKh + SMEM_SWIZZLE_128B(off));
            }
#pragma unroll
            for (int mf = 0; mf < 4; mf++)
#pragma unroll
                for (int nf = 0; nf < 4; nf++)
                    mma16816(acc[mf][nf], ah[mf], &bh[nf * 2]);
#pragma unroll
            for (int mf = 0; mf < 4; mf++)
#pragma unroll
                for (int nf = 0; nf < 4; nf++)
                    mma16816(acc[mf][nf], al[mf], &bh[nf * 2]);
            uint32_t bl[8];
#pragma unroll
            for (int np = 0; np < 2; np++) {
                const uint32_t off = (uint32_t)((wn * 32 + np * 16 + b_row) * 128
                                                + ks * 32 + b_c16);
                ldsm4(&bl[np * 4], tKl + SMEM_SWIZZLE_128B(off));
            }
#pragma unroll
            for (int mf = 0; mf < 4; mf++)
#pragma unroll
                for (int nf = 0; nf < 4; nf++)
                    mma16816(acc[mf][nf], ah[mf], &bl[nf * 2]);
        }
        __syncthreads();

        if (c + 2 < 8) {
            const uint32_t kb = smem_base + (2 + 2 * (c & 1)) * TILE_BYTES;
            const size_t so = (size_t)(c + 2) * 128 * HD;
#pragma unroll
            for (int gix = 0; gix < 4; gix++) {
                cpa16(kb + sw[gix], khb + so + gix * 8);
                cpa16(kb + TILE_BYTES + sw[gix], klb + so + gix * 8);
            }
        }
        CP_COMMIT();

        const int l0 = c * 128;
        const int cw = c * 4 + wn;
        float csum[4][2];
#pragma unroll
        for (int nf = 0; nf < 4; nf++) { csum[nf][0] = 0.f; csum[nf][1] = 0.f; }

#pragma unroll
        for (int mf = 0; mf < 4; mf++) {
#pragma unroll
            for (int half = 0; half < 2; half++) {
                const int q = q0 + wm * 64 + mf * 16 + gr + half * 8;
                const uint32_t w = Mbn[q * 32 + cw];
#pragma unroll
                for (int nf = 0; nf < 4; nf++) {
                    const int col = l0 + wn * 32 + nf * 8 + c2;
                    const uint32_t bits = (w >> (nf * 8 + c2)) & 3u;
                    float2 e;
                    e.x = (bits & 1u) ? __expf(acc[mf][nf][half * 2 + 0] * 0.125f) : 0.f;
                    e.y = (bits & 2u) ? __expf(acc[mf][nf][half * 2 + 1] * 0.125f) : 0.f;
                    float h0, lo0, h1, lo1;
                    splitf(e.x, h0, lo0);
                    splitf(e.y, h1, lo1);
                    *(uint32_t*)(Egh + (size_t)q * SEQ + col) = packbf2(h0, h1);
                    *(uint32_t*)(Egl + (size_t)q * SEQ + col) = packbf2(lo0, lo1);
                    csum[nf][0] += e.x;
                    csum[nf][1] += e.y;
                }
            }
        }
        float* Zp = g_Zp[qt * 2 + wm] + g * SEQ;
#pragma unroll
        for (int nf = 0; nf < 4; nf++) {
#pragma unroll
            for (int cc = 0; cc < 2; cc++) {
                float v = csum[nf][cc];
                v += __shfl_xor_sync(0xffffffffu, v, 4);
                v += __shfl_xor_sync(0xffffffffu, v, 8);
                v += __shfl_xor_sync(0xffffffffu, v, 16);
                if (gr == 0)
                    Zp[l0 + wn * 32 + nf * 8 + c2 + cc] = v;
            }
        }
    }
}

/* ================================================================== */
__global__ __launch_bounds__(256) void zred_kernel()
{
    const int i = blockIdx.x * 256 + threadIdx.x;
    float z = 0.f;
#pragma unroll
    for (int s = 0; s < 16; s++)
        z += g_Zp[s][i];
    g_Zi[i] = (z > 0.f) ? (1.f / z) : 0.f;
}

/* ================================================================== */
__global__ __launch_bounds__(256) void vscale_kernel()
{
    const size_t e = ((size_t)blockIdx.x * 256 + threadIdx.x) * 8;
    const int g = (int)(e / ((size_t)HD * SEQ));
    const int s = (int)(e % SEQ);
    float4 z0 = *(const float4*)(g_Zi + g * SEQ + s);
    float4 z1 = *(const float4*)(g_Zi + g * SEQ + s + 4);
    const float zz[8] = {z0.x, z0.y, z0.z, z0.w, z1.x, z1.y, z1.z, z1.w};
    uint4 vh = *(const uint4*)(g_Vth + e);
    uint4 vl = *(const uint4*)(g_Vtl + e);
    const uint32_t hw[4] = {vh.x, vh.y, vh.z, vh.w};
    const uint32_t lw[4] = {vl.x, vl.y, vl.z, vl.w};
    uint32_t oh[4], ol[4];
#pragma unroll
    for (int j = 0; j < 4; j++) {
        float2 fh = upk(hw[j]);
        float2 fl = upk(lw[j]);
        const float a = (fh.x + fl.x) * zz[2 * j];
        const float b = (fh.y + fl.y) * zz[2 * j + 1];
        float ah, alo, bh, blo;
        splitf(a, ah, alo);
        splitf(b, bh, blo);
        oh[j] = packbf2(ah, bh);
        ol[j] = packbf2(alo, blo);
    }
    *(uint4*)(g_Vth + e) = make_uint4(oh[0], oh[1], oh[2], oh[3]);
    *(uint4*)(g_Vtl + e) = make_uint4(ol[0], ol[1], ol[2], ol[3]);
}

/* ================================================================== */
/* AV v2 (unchanged): pure GEMM, cp.async double-buffered.             */
/* ================================================================== */
#define AVBUF 49152
#define SMEM_AV (2 * AVBUF)

__global__ __launch_bounds__(256, 2) void av_mma_kernel()
{
    extern __shared__ char smem[];
    const uint32_t smem_base = smem_to_u32(smem);
    const int tid = threadIdx.x;
    const int wid = tid >> 5, lane = tid & 31;
    const int wm = wid >> 1, wn = wid & 1;

    const int g  = blockIdx.y;
    const int q0 = blockIdx.x * 128;

    const int erow = tid >> 1;
    const int ebyte = (tid & 1) * 64;
    const __nv_bfloat16* ehb = g_Eh + ((size_t)g * SEQ + q0 + erow) * SEQ + ebyte / 2;
    const __nv_bfloat16* elb = g_El + ((size_t)g * SEQ + q0 + erow) * SEQ + ebyte / 2;
    uint32_t esw[4];
#pragma unroll
    for (int gix = 0; gix < 4; gix++)
        esw[gix] = SMEM_SWIZZLE_128B((uint32_t)(erow * 128 + ebyte + gix * 16));

    const int vrow = tid >> 2;
    const int vbyte = (tid & 3) * 32;
    const __nv_bfloat16* vhb = g_Vth + ((size_t)g * HD + vrow) * SEQ + vbyte / 2;
    const __nv_bfloat16* vlb = g_Vtl + ((size_t)g * HD + vrow) * SEQ + vbyte / 2;
    uint32_t vsw[2];
#pragma unroll
    for (int j = 0; j < 2; j++)
        vsw[j] = SMEM_SWIZZLE_128B((uint32_t)(vrow * 128 + vbyte + j * 16));

#define AV_ISSUE(cc, buf)                                                      \
    do {                                                                       \
        const int _l0 = (cc) * 64;                                             \
        const uint32_t _bb = smem_base + (buf) * AVBUF;                        \
        _Pragma("unroll")                                                      \
        for (int gix = 0; gix < 4; gix++) {                                    \
            cpa16(_bb + esw[gix], ehb + _l0 + gix * 8);                        \
            cpa16(_bb + 16384 + esw[gix], elb + _l0 + gix * 8);                \
        }                                                                      \
        _Pragma("unroll")                                                      \
        for (int j = 0; j < 2; j++) {                                          \
            cpa16(_bb + 32768 + vsw[j], vhb + _l0 + j * 8);                    \
            cpa16(_bb + 40960 + vsw[j], vlb + _l0 + j * 8);                    \
        }                                                                      \
    } while (0)

    AV_ISSUE(0, 0);
    CP_COMMIT();
    AV_ISSUE(1, 1);
    CP_COMMIT();

    const int a_row = (lane & 15);
    const int a_c16 = (lane >> 4) * 16;
    const int b_row = (lane & 7) + ((lane >> 4) << 3);
    const int b_c16 = ((lane >> 3) & 1) * 16;

    float acc[2][4][4];
#pragma unroll
    for (int mf = 0; mf < 2; mf++)
#pragma unroll
        for (int nf = 0; nf < 4; nf++)
#pragma unroll
            for (int r = 0; r < 4; r++) acc[mf][nf][r] = 0.f;

    for (int c = 0; c < 16; c++) {
        CP_WAIT1();
        __syncthreads();
        const uint32_t bb = smem_base + (c & 1) * AVBUF;
        const uint32_t tEh = bb, tEl = bb + 16384;
        const uint32_t tVh = bb + 32768, tVl = bb + 40960;

#pragma unroll
        for (int ks = 0; ks < 4; ks++) {
            uint32_t ah[2][4], al[2][4];
#pragma unroll
            for (int mf = 0; mf < 2; mf++) {
                const uint32_t off = (uint32_t)((wm * 32 + mf * 16 + a_row) * 128
                                                + ks * 32 + a_c16);
                const uint32_t swo = SMEM_SWIZZLE_128B(off);
                ldsm4(ah[mf], tEh + swo);
                ldsm4(al[mf], tEl + swo);
            }
            uint32_t bh[8];
#pragma unroll
            for (int np = 0; np < 2; np++) {
                const uint32_t off = (uint32_t)((wn * 32 + np * 16 + b_row) * 128
                                                + ks * 32 + b_c16);
                ldsm4(&bh[np * 4], tVh + SMEM_SWIZZLE_128B(off));
            }
#pragma unroll
            for (int mf = 0; mf < 2; mf++)
#pragma unroll
                for (int nf = 0; nf < 4; nf++)
                    mma16816(acc[mf][nf], ah[mf], &bh[nf * 2]);
#pragma unroll
            for (int mf = 0; mf < 2; mf++)
#pragma unroll
                for (int nf = 0; nf < 4; nf++)
                    mma16816(acc[mf][nf], al[mf], &bh[nf * 2]);
            uint32_t bl[8];
#pragma unroll
            for (int np = 0; np < 2; np++) {
                const uint32_t off = (uint32_t)((wn * 32 + np * 16 + b_row) * 128
                                                + ks * 32 + b_c16);
                ldsm4(&bl[np * 4], tVl + SMEM_SWIZZLE_128B(off));
            }
#pragma unroll
            for (int mf = 0; mf < 2; mf++)
#pragma unroll
                for (int nf = 0; nf < 4; nf++)
                    mma16816(acc[mf][nf], ah[mf], &bl[nf * 2]);
        }
        __syncthreads();
        if (c + 2 < 16)
            AV_ISSUE(c + 2, c & 1);
        CP_COMMIT();
    }

    const int n = g >> 5, b = (g >> 3) & 3, hd = g & 7;
    const int gr = lane >> 2, c2 = (lane & 3) * 2;
#pragma unroll
    for (int mf = 0; mf < 2; mf++) {
#pragma unroll
        for (int nf = 0; nf < 4; nf++) {
            const int d = wn * 32 + nf * 8 + c2;
#pragma unroll
            for (int half = 0; half < 2; half++) {
                const int q = q0 + wm * 32 + mf * 16 + gr + half * 8;
                const size_t t = (size_t)(n * SEQ + q);
                const size_t off = t * EMBED + b * EBS + hd * HD + d;
                float h0, l0f, h1, l1;
                splitf(acc[mf][nf][half * 2 + 0], h0, l0f);
                splitf(acc[mf][nf][half * 2 + 1], h1, l1);
                *(uint32_t*)(g_AOh + off) = packbf2(h0, h1);
                *(uint32_t*)(g_AOl + off) = packbf2(l0f, l1);
            }
        }
    }
}

/* ------------------------------------------------------------------ */
extern "C" void kernel_launch(void* const* d_in, const int* in_sizes, int n_in,
                              void* d_out, int out_size)
{
    const float* values = (const float*)d_in[0];
    const float* keys   = (const float*)d_in[1];
    const float* query  = (const float*)d_in[2];
    const int*   mask   = (const int*)d_in[3];
    const float* Wv = (const float*)d_in[4];
    const float* bv = (const float*)d_in[5];
    const float* Wk = (const float*)d_in[6];
    const float* bk = (const float*)d_in[7];
    const float* Wq = (const float*)d_in[8];
    const float* bq = (const float*)d_in[9];
    const float* Wo = (const float*)d_in[10];
    const float* bo = (const float*)d_in[11];
    float* out = (float*)d_out;

    cudaFuncSetAttribute(mm_kernel<0>, cudaFuncAttributeMaxDynamicSharedMemorySize,
                         SMEM_GEMM_TOTAL);
    cudaFuncSetAttribute(mm_kernel<1>, cudaFuncAttributeMaxDynamicSharedMemorySize,
                         SMEM_GEMM_TOTAL);
    cudaFuncSetAttribute(energy_mma_kernel, cudaFuncAttributeMaxDynamicSharedMemorySize,
                         SMEM_ENERGY);
    cudaFuncSetAttribute(av_mma_kernel, cudaFuncAttributeMaxDynamicSharedMemorySize,
                         SMEM_AV);

    /* converts */
    dim3 gx((TTOK * EMBED) / (256 * 4), 3);
    convx_kernel<<<gx, 256>>>(values, keys, query);
    dim3 gw(EBS / 32, EBS / 32, 16);
    convw_kernel<<<gw, dim3(32, 8)>>>(Wv, Wk, Wq, Wo);
    convm_kernel<<<(NBATCH * SEQ) / 8, 256>>>(mask);

    /* fused qkv projections (tensor, 512 threads, 3-stage) */
    dim3 gqkv(EBS / 128, TTOK / 128, 12);
    mm_kernel<0><<<gqkv, 512, SMEM_GEMM_TOTAL>>>(bv, bk, bq, nullptr);

    /* energy + exp + column partial sums (tensor, pipelined) */
    dim3 ge(SEQ / 128, NG);
    energy_mma_kernel<<<ge, 256, SMEM_ENERGY>>>();

    /* reduce partials -> 1/Z, fold into V */
    zred_kernel<<<(NG * SEQ) / 256, 256>>>();
    vscale_kernel<<<(NG * HD * SEQ) / (256 * 8), 256>>>();

    /* AV (tensor, pipelined) */
    dim3 ga(SEQ / 128, NG);
    av_mma_kernel<<<ga, 256, SMEM_AV>>>();

    /* output projection (tensor, 512 threads, 3-stage) */
    dim3 go(EBS / 128, TTOK / 128, NB);
    mm_kernel<1><<<go, 512, SMEM_GEMM_TOTAL>>>(bo, nullptr, nullptr, out);
}